// round 2
// baseline (speedup 1.0000x reference)
#include <cuda_runtime.h>
#include <math.h>

#define NLAT  256
#define NLON  256
#define LMAX  128
#define MMAX  129
#define NF    258           // 2*MMAX
#define NX    33024         // 2*LMAX*MMAX
#define BCH   256           // BATCH*CIN = BATCH*COUT
#define NROW  65536         // BCH*NLAT

// ---------------------------------------------------------------------------
// Static device scratch (no allocations allowed)
// ---------------------------------------------------------------------------
__device__ float d_wq[NLAT];
__device__ float d_F[NF * NLON];                       // [n][j] fwd DFT
__device__ float d_G[NF * NLON];                       // [n][j] inv DFT
__device__ float d_PCT [(size_t)MMAX * LMAX * NLAT];   // [m][l][k]
__device__ float d_PCTW[(size_t)MMAX * LMAX * NLAT];   // [m][l][k] * wq
__device__ float d_PCTT[(size_t)MMAX * NLAT * LMAX];   // [m][k][l]
__device__ float d_xh  [(size_t)NF * NROW];            // [n][k*256+bc]
__device__ float d_spec[(size_t)NX * BCH];             // [x][b*32+i]
__device__ float d_out2[(size_t)NX * BCH];             // [x][b*32+o]
__device__ float d_rr  [(size_t)NF * NROW];            // [n][k*256+bo]

// ---------------------------------------------------------------------------
// Clenshaw-Curtis quadrature weights (NLAT=256, N=255, 2k never == N)
// ---------------------------------------------------------------------------
__global__ __launch_bounds__(128) void k_quad() {
    int j = blockIdx.x;
    int k = threadIdx.x;                 // 0..127
    double tj = M_PI * (double)j / 255.0;
    double v = 0.0;
    if (k >= 1) v = cos(2.0 * tj * (double)k) * (2.0 / (4.0 * (double)k * k - 1.0));
    __shared__ double red[128];
    red[k] = v;
    __syncthreads();
    for (int s = 64; s > 0; s >>= 1) {
        if (k < s) red[k] += red[k + s];
        __syncthreads();
    }
    if (k == 0) {
        double c = (j == 0 || j == 255) ? 1.0 : 2.0;
        d_wq[j] = (float)(c / 255.0 * (1.0 - red[0]));
    }
}

// ---------------------------------------------------------------------------
// Fourier matrices (exact mod-256 phase reduction)
// ---------------------------------------------------------------------------
__global__ __launch_bounds__(256) void k_fourier() {
    int m = blockIdx.x;                  // 0..128
    int j = threadIdx.x;                 // 0..255
    int r = (m * j) & 255;
    float s, c;
    sincosf((float)(2.0 * M_PI / 256.0 * (double)r), &s, &c);
    const float sc = (float)(2.0 * M_PI / 256.0);
    d_F[(2 * m)     * NLON + j] =  sc * c;
    d_F[(2 * m + 1) * NLON + j] = -sc * s;
    float wm = (m == 0 || m == 128) ? 1.0f : 2.0f;
    d_G[(2 * m)     * NLON + j] =  wm * c;
    d_G[(2 * m + 1) * NLON + j] = -wm * s;
}

// ---------------------------------------------------------------------------
// Associated Legendre tables (double precision recurrences)
// ---------------------------------------------------------------------------
__global__ __launch_bounds__(256) void k_legendre() {
    int m  = blockIdx.x;                 // 0..128
    int kk = threadIdx.x;                // 0..255
    size_t basePCT = (size_t)m * LMAX * NLAT;
    size_t baseT   = (size_t)m * NLAT * LMAX + (size_t)kk * LMAX;
    if (m >= LMAX) {                     // m == 128: entire plane zero (l < m)
        for (int l = 0; l < LMAX; l++) {
            d_PCT [basePCT + l * NLAT + kk] = 0.f;
            d_PCTW[basePCT + l * NLAT + kk] = 0.f;
            d_PCTT[baseT + l] = 0.f;
        }
        return;
    }
    __shared__ double s_a[LMAX], s_b[LMAX];
    __shared__ double s_sect;
    if (kk < LMAX) {
        int l = kk;
        if (l >= m + 2) {
            double fl = (double)l, fm = (double)m, g = fl - 1.0;
            s_a[l] = sqrt((4.0 * fl * fl - 1.0) / (fl * fl - fm * fm));
            s_b[l] = sqrt((g * g - fm * fm) / (4.0 * g * g - 1.0));
        }
    }
    if (kk == 0) {
        double pr = 1.0;
        for (int i = 1; i <= m; i++) pr *= (2.0 * i + 1.0) / (2.0 * i);
        s_sect = sqrt(pr);
    }
    __syncthreads();
    double tt = M_PI * (double)kk / 255.0;
    double ct = cos(tt), st = sin(tt);
    double w  = (double)d_wq[kk];
    for (int l = 0; l < m; l++) {
        d_PCT [basePCT + l * NLAT + kk] = 0.f;
        d_PCTW[basePCT + l * NLAT + kk] = 0.f;
        d_PCTT[baseT + l] = 0.f;
    }
    double powv = 1.0;
    for (int i = 0; i < m; i++) powv *= -st;
    double p2 = 0.28209479177387814347 * s_sect * powv;   // p[m][m]
    d_PCT [basePCT + m * NLAT + kk] = (float)p2;
    d_PCTW[basePCT + m * NLAT + kk] = (float)(p2 * w);
    d_PCTT[baseT + m] = (float)p2;
    if (m + 1 < LMAX) {
        double p1 = sqrt(2.0 * m + 3.0) * ct * p2;
        d_PCT [basePCT + (m + 1) * NLAT + kk] = (float)p1;
        d_PCTW[basePCT + (m + 1) * NLAT + kk] = (float)(p1 * w);
        d_PCTT[baseT + m + 1] = (float)p1;
        for (int l = m + 2; l < LMAX; l++) {
            double p = s_a[l] * (ct * p1 - s_b[l] * p2);
            d_PCT [basePCT + l * NLAT + kk] = (float)p;
            d_PCTW[basePCT + l * NLAT + kk] = (float)(p * w);
            d_PCTT[baseT + l] = (float)p;
            p2 = p1; p1 = p;
        }
    }
}

// ---------------------------------------------------------------------------
// G1: xh[n][k*256+bc] = sum_j F[n][j] * x[bc][k][j]
// tile 64n x 64col, K=256
// ---------------------------------------------------------------------------
__global__ __launch_bounds__(256) void k_g1(const float* __restrict__ x) {
    __shared__ float Ast[16 * 68];       // [j][n_local]
    __shared__ float Bs [16 * 68];       // [j][col_local]
    int t = threadIdx.x;
    int col0 = blockIdx.x * 64;
    int n0   = blockIdx.y * 64;
    int klat = col0 >> 8;
    int bc0  = col0 & 255;
    const float* xb = x + (size_t)bc0 * 65536 + (size_t)klat * 256;
    int a_nl = t >> 2, a_j4 = t & 3;
    int b_cl = t & 63, b_j4 = t >> 6;
    int tc = t & 15, tn = t >> 4;
    float acc[4][4] = {};
    for (int kt = 0; kt < 16; kt++) {
        int j0 = kt * 16;
        float4 av = make_float4(0.f, 0.f, 0.f, 0.f);
        int n = n0 + a_nl;
        if (n < NF) av = *reinterpret_cast<const float4*>(&d_F[n * 256 + j0 + a_j4 * 4]);
        Ast[(a_j4 * 4 + 0) * 68 + a_nl] = av.x;
        Ast[(a_j4 * 4 + 1) * 68 + a_nl] = av.y;
        Ast[(a_j4 * 4 + 2) * 68 + a_nl] = av.z;
        Ast[(a_j4 * 4 + 3) * 68 + a_nl] = av.w;
        float4 bv = *reinterpret_cast<const float4*>(&xb[(size_t)b_cl * 65536 + j0 + b_j4 * 4]);
        Bs[(b_j4 * 4 + 0) * 68 + b_cl] = bv.x;
        Bs[(b_j4 * 4 + 1) * 68 + b_cl] = bv.y;
        Bs[(b_j4 * 4 + 2) * 68 + b_cl] = bv.z;
        Bs[(b_j4 * 4 + 3) * 68 + b_cl] = bv.w;
        __syncthreads();
        #pragma unroll
        for (int j = 0; j < 16; j++) {
            float4 a = *reinterpret_cast<const float4*>(&Ast[j * 68 + tn * 4]);
            float4 b = *reinterpret_cast<const float4*>(&Bs [j * 68 + tc * 4]);
            float ar[4] = {a.x, a.y, a.z, a.w};
            float br[4] = {b.x, b.y, b.z, b.w};
            #pragma unroll
            for (int p = 0; p < 4; p++)
                #pragma unroll
                for (int q = 0; q < 4; q++) acc[p][q] += ar[p] * br[q];
        }
        __syncthreads();
    }
    #pragma unroll
    for (int en = 0; en < 4; en++) {
        int n = n0 + tn * 4 + en;
        if (n < NF)
            *reinterpret_cast<float4*>(&d_xh[(size_t)n * NROW + col0 + tc * 4]) =
                make_float4(acc[en][0], acc[en][1], acc[en][2], acc[en][3]);
    }
}

// ---------------------------------------------------------------------------
// G2: spec[(l*129+m)*2+ri][bc] = sum_k PCTW[m][l][k] * xh[2m+ri][k*256+bc]
// one block: 128l x 64bc, K=256; grid (4, 258)
// ---------------------------------------------------------------------------
__global__ __launch_bounds__(256) void k_g2() {
    __shared__ float Ast[16 * 132];      // [k_local][l]
    __shared__ float Bs [16 * 68];       // [k_local][bc_local]
    int t = threadIdx.x;
    int bc0 = blockIdx.x * 64;
    int mri = blockIdx.y;
    int m = mri >> 1, ri = mri & 1;
    const float* A = d_PCTW + (size_t)m * LMAX * NLAT;     // [l][k]
    const float* B = d_xh + (size_t)mri * NROW;            // [k][bc]
    int b_bc4 = t & 15, b_kl = t >> 4;
    int tc = t & 15, tn = t >> 4;
    float acc[8][4] = {};
    for (int kt = 0; kt < 16; kt++) {
        int j0 = kt * 16;
        #pragma unroll
        for (int rep = 0; rep < 2; rep++) {
            int idx = rep * 256 + t;
            int j4 = idx & 3, l_l = idx >> 2;              // l_l 0..127
            float4 av = *reinterpret_cast<const float4*>(&A[l_l * 256 + j0 + j4 * 4]);
            Ast[(j4 * 4 + 0) * 132 + l_l] = av.x;
            Ast[(j4 * 4 + 1) * 132 + l_l] = av.y;
            Ast[(j4 * 4 + 2) * 132 + l_l] = av.z;
            Ast[(j4 * 4 + 3) * 132 + l_l] = av.w;
        }
        float4 bv = *reinterpret_cast<const float4*>(&B[(size_t)(j0 + b_kl) * 256 + bc0 + b_bc4 * 4]);
        *reinterpret_cast<float4*>(&Bs[b_kl * 68 + b_bc4 * 4]) = bv;
        __syncthreads();
        #pragma unroll
        for (int j = 0; j < 16; j++) {
            float4 a0 = *reinterpret_cast<const float4*>(&Ast[j * 132 + tn * 8]);
            float4 a1 = *reinterpret_cast<const float4*>(&Ast[j * 132 + tn * 8 + 4]);
            float4 b  = *reinterpret_cast<const float4*>(&Bs [j * 68  + tc * 4]);
            float ar[8] = {a0.x, a0.y, a0.z, a0.w, a1.x, a1.y, a1.z, a1.w};
            float br[4] = {b.x, b.y, b.z, b.w};
            #pragma unroll
            for (int p = 0; p < 8; p++)
                #pragma unroll
                for (int q = 0; q < 4; q++) acc[p][q] += ar[p] * br[q];
        }
        __syncthreads();
    }
    #pragma unroll
    for (int e = 0; e < 8; e++) {
        int l = tn * 8 + e;
        size_t xrow = ((size_t)l * 129 + m) * 2 + ri;
        *reinterpret_cast<float4*>(&d_spec[xrow * 256 + bc0 + tc * 4]) =
            make_float4(acc[e][0], acc[e][1], acc[e][2], acc[e][3]);
    }
}

// ---------------------------------------------------------------------------
// G3: out2[x][b*32+o] = sum_i spec[x][b*32+i] * W[(i*32+o)*NX + x]
// 8 x per block
// ---------------------------------------------------------------------------
__global__ __launch_bounds__(256) void k_mix(const float* __restrict__ W) {
    __shared__ float Ws[8 * 1028];       // [xl][io], padded
    __shared__ float Ss[8 * 256];        // [xl][bc]
    int t = threadIdx.x;
    int x0 = blockIdx.x * 8;
    #pragma unroll
    for (int rep = 0; rep < 32; rep++) {
        int idx = rep * 256 + t;
        int xl = idx & 7, io = idx >> 3;
        Ws[xl * 1028 + io] = W[(size_t)io * NX + x0 + xl];
    }
    #pragma unroll
    for (int rep = 0; rep < 8; rep++) {
        int idx = rep * 256 + t;
        int xl = idx >> 8, bc = idx & 255;
        Ss[xl * 256 + bc] = d_spec[(size_t)(x0 + xl) * 256 + bc];
    }
    __syncthreads();
    int b = t >> 5, o = t & 31;
    float acc[8] = {};
    #pragma unroll
    for (int xl = 0; xl < 8; xl++)
        #pragma unroll
        for (int i = 0; i < 32; i++)
            acc[xl] += Ss[xl * 256 + b * 32 + i] * Ws[xl * 1028 + i * 32 + o];
    #pragma unroll
    for (int xl = 0; xl < 8; xl++)
        d_out2[(size_t)(x0 + xl) * 256 + t] = acc[xl];
}

// ---------------------------------------------------------------------------
// G4: rr[2m+ri][k*256+bo] = sum_l PCTT[m][k][l] * out2[(l*129+m)*2+ri][bo]
// tile 64k x 64bo, K=128; grid (16, 258)
// ---------------------------------------------------------------------------
__global__ __launch_bounds__(256) void k_g4() {
    __shared__ float Ast[16 * 68];       // [l_local][k_local]
    __shared__ float Bs [16 * 68];       // [l_local][bo_local]
    int t = threadIdx.x;
    int k0  = (blockIdx.x >> 2) * 64;
    int bo0 = (blockIdx.x & 3) * 64;
    int mri = blockIdx.y;
    int m = mri >> 1, ri = mri & 1;
    const float* A = d_PCTT + (size_t)m * NLAT * LMAX;     // [k][l]
    int a_kl = t >> 2, a_l4 = t & 3;
    int b_bo4 = t & 15, b_ll = t >> 4;
    int tc = t & 15, tn = t >> 4;
    float acc[4][4] = {};
    for (int lt = 0; lt < 8; lt++) {
        int l0 = lt * 16;
        float4 av = *reinterpret_cast<const float4*>(&A[(size_t)(k0 + a_kl) * 128 + l0 + a_l4 * 4]);
        Ast[(a_l4 * 4 + 0) * 68 + a_kl] = av.x;
        Ast[(a_l4 * 4 + 1) * 68 + a_kl] = av.y;
        Ast[(a_l4 * 4 + 2) * 68 + a_kl] = av.z;
        Ast[(a_l4 * 4 + 3) * 68 + a_kl] = av.w;
        {
            int l = l0 + b_ll;
            size_t xrow = ((size_t)l * 129 + m) * 2 + ri;
            float4 bv = *reinterpret_cast<const float4*>(&d_out2[xrow * 256 + bo0 + b_bo4 * 4]);
            *reinterpret_cast<float4*>(&Bs[b_ll * 68 + b_bo4 * 4]) = bv;
        }
        __syncthreads();
        #pragma unroll
        for (int j = 0; j < 16; j++) {
            float4 a = *reinterpret_cast<const float4*>(&Ast[j * 68 + tn * 4]);
            float4 b = *reinterpret_cast<const float4*>(&Bs [j * 68 + tc * 4]);
            float ar[4] = {a.x, a.y, a.z, a.w};
            float br[4] = {b.x, b.y, b.z, b.w};
            #pragma unroll
            for (int p = 0; p < 4; p++)
                #pragma unroll
                for (int q = 0; q < 4; q++) acc[p][q] += ar[p] * br[q];
        }
        __syncthreads();
    }
    #pragma unroll
    for (int en = 0; en < 4; en++) {
        int k = k0 + tn * 4 + en;
        *reinterpret_cast<float4*>(&d_rr[(size_t)mri * NROW + (size_t)k * 256 + bo0 + tc * 4]) =
            make_float4(acc[en][0], acc[en][1], acc[en][2], acc[en][3]);
    }
}

// ---------------------------------------------------------------------------
// G5: y[bo][k][j] = sum_n rr[n][r] * G[n][j],  r = k*256+bo
// tile 64r x 64j, K=258 (17 tiles, guarded)
// ---------------------------------------------------------------------------
__global__ __launch_bounds__(256) void k_g5(float* __restrict__ out) {
    __shared__ float Ast[16 * 68];       // [n_local][r_local]
    __shared__ float Bs [16 * 68];       // [n_local][j_local]
    int t = threadIdx.x;
    int r0  = blockIdx.x * 64;
    int jc0 = blockIdx.y * 64;
    int a_r4 = t & 15, a_nl = t >> 4;
    int b_j4 = t & 15, b_nl = t >> 4;
    int tc = t & 15, tn = t >> 4;
    float acc[4][4] = {};
    for (int kt = 0; kt < 17; kt++) {
        int n0 = kt * 16;
        float4 av = make_float4(0.f, 0.f, 0.f, 0.f);
        int na = n0 + a_nl;
        if (na < NF) av = *reinterpret_cast<const float4*>(&d_rr[(size_t)na * NROW + r0 + a_r4 * 4]);
        *reinterpret_cast<float4*>(&Ast[a_nl * 68 + a_r4 * 4]) = av;
        float4 bv = make_float4(0.f, 0.f, 0.f, 0.f);
        int nb = n0 + b_nl;
        if (nb < NF) bv = *reinterpret_cast<const float4*>(&d_G[nb * 256 + jc0 + b_j4 * 4]);
        *reinterpret_cast<float4*>(&Bs[b_nl * 68 + b_j4 * 4]) = bv;
        __syncthreads();
        #pragma unroll
        for (int j = 0; j < 16; j++) {
            float4 a = *reinterpret_cast<const float4*>(&Ast[j * 68 + tn * 4]);
            float4 b = *reinterpret_cast<const float4*>(&Bs [j * 68 + tc * 4]);
            float ar[4] = {a.x, a.y, a.z, a.w};
            float br[4] = {b.x, b.y, b.z, b.w};
            #pragma unroll
            for (int p = 0; p < 4; p++)
                #pragma unroll
                for (int q = 0; q < 4; q++) acc[p][q] += ar[p] * br[q];
        }
        __syncthreads();
    }
    #pragma unroll
    for (int en = 0; en < 4; en++) {
        int r = r0 + tn * 4 + en;
        int k = r >> 8, bo = r & 255;
        *reinterpret_cast<float4*>(&out[(size_t)bo * 65536 + (size_t)k * 256 + jc0 + tc * 4]) =
            make_float4(acc[en][0], acc[en][1], acc[en][2], acc[en][3]);
    }
}

// ---------------------------------------------------------------------------
extern "C" void kernel_launch(void* const* d_in, const int* in_sizes, int n_in,
                              void* d_out, int out_size) {
    const float* x = (const float*)d_in[0];
    const float* w = (const float*)d_in[1];
    float* out = (float*)d_out;

    k_quad<<<256, 128>>>();
    k_fourier<<<129, 256>>>();
    k_legendre<<<129, 256>>>();

    dim3 g1(1024, 5);  k_g1<<<g1, 256>>>(x);
    dim3 g2(4, 258);   k_g2<<<g2, 256>>>();
    k_mix<<<NX / 8, 256>>>(w);
    dim3 g4(16, 258);  k_g4<<<g4, 256>>>();
    dim3 g5(1024, 4);  k_g5<<<g5, 256>>>(out);
}

// round 5
// speedup vs baseline: 1.2164x; 1.2164x over previous
#include <cuda_runtime.h>
#include <math.h>

#define NLAT  256
#define NLON  256
#define LMAX  128
#define MMAX  129
#define NF    258           // full 2*MMAX (tables); compute uses 256 (m=128 dead)
#define NM    256           // effective 2*128
#define NX    33024         // 2*LMAX*MMAX
#define BCH   256           // BATCH*CIN = BATCH*COUT
#define NROW  65536         // BCH*NLAT

// ---------------------------------------------------------------------------
// Static device scratch (no allocations allowed; zero-initialized at load)
// ---------------------------------------------------------------------------
__device__ float d_wq[NLAT];
__device__ float d_F[NF * NLON];                       // [n][j] fwd DFT
__device__ float d_G[NF * NLON];                       // [n][j] inv DFT
__device__ float d_PCT [(size_t)MMAX * LMAX * NLAT];   // [m][l][k]
__device__ float d_PCTW[(size_t)MMAX * LMAX * NLAT];   // [m][l][k] * wq
__device__ float d_PCTT[(size_t)MMAX * NLAT * LMAX];   // [m][k][l]
__device__ float d_xh  [(size_t)NM * NROW];            // [n][k*256+bc]
__device__ float d_spec[(size_t)NX * BCH];             // [x][b*32+i]  (m=128 rows stay 0)
__device__ float d_out2[(size_t)NX * BCH];             // [x][b*32+o]
__device__ float d_rr  [(size_t)NM * NROW];            // [n][k*256+bo]

// ---------------------------------------------------------------------------
// Clenshaw-Curtis quadrature weights (NLAT=256, N=255)
// ---------------------------------------------------------------------------
__global__ __launch_bounds__(128) void k_quad() {
    int j = blockIdx.x;
    int k = threadIdx.x;
    double tj = M_PI * (double)j / 255.0;
    double v = 0.0;
    if (k >= 1) v = cos(2.0 * tj * (double)k) * (2.0 / (4.0 * (double)k * k - 1.0));
    __shared__ double red[128];
    red[k] = v;
    __syncthreads();
    for (int s = 64; s > 0; s >>= 1) {
        if (k < s) red[k] += red[k + s];
        __syncthreads();
    }
    if (k == 0) {
        double c = (j == 0 || j == 255) ? 1.0 : 2.0;
        d_wq[j] = (float)(c / 255.0 * (1.0 - red[0]));
    }
}

// ---------------------------------------------------------------------------
// Fourier matrices (exact mod-256 phase reduction)
// ---------------------------------------------------------------------------
__global__ __launch_bounds__(256) void k_fourier() {
    int m = blockIdx.x;                  // 0..128
    int j = threadIdx.x;                 // 0..255
    int r = (m * j) & 255;
    float s, c;
    sincosf((float)(2.0 * M_PI / 256.0 * (double)r), &s, &c);
    const float sc = (float)(2.0 * M_PI / 256.0);
    d_F[(2 * m)     * NLON + j] =  sc * c;
    d_F[(2 * m + 1) * NLON + j] = -sc * s;
    float wm = (m == 0 || m == 128) ? 1.0f : 2.0f;
    d_G[(2 * m)     * NLON + j] =  wm * c;
    d_G[(2 * m + 1) * NLON + j] = -wm * s;
}

// ---------------------------------------------------------------------------
// Associated Legendre tables (double precision recurrences)
// ---------------------------------------------------------------------------
__global__ __launch_bounds__(256) void k_legendre() {
    int m  = blockIdx.x;                 // 0..128
    int kk = threadIdx.x;                // 0..255
    size_t basePCT = (size_t)m * LMAX * NLAT;
    size_t baseT   = (size_t)m * NLAT * LMAX + (size_t)kk * LMAX;
    if (m >= LMAX) {                     // m == 128: plane zero
        for (int l = 0; l < LMAX; l++) {
            d_PCT [basePCT + l * NLAT + kk] = 0.f;
            d_PCTW[basePCT + l * NLAT + kk] = 0.f;
            d_PCTT[baseT + l] = 0.f;
        }
        return;
    }
    __shared__ double s_a[LMAX], s_b[LMAX];
    __shared__ double s_sect;
    if (kk < LMAX) {
        int l = kk;
        if (l >= m + 2) {
            double fl = (double)l, fm = (double)m, g = fl - 1.0;
            s_a[l] = sqrt((4.0 * fl * fl - 1.0) / (fl * fl - fm * fm));
            s_b[l] = sqrt((g * g - fm * fm) / (4.0 * g * g - 1.0));
        }
    }
    if (kk == 0) {
        double pr = 1.0;
        for (int i = 1; i <= m; i++) pr *= (2.0 * i + 1.0) / (2.0 * i);
        s_sect = sqrt(pr);
    }
    __syncthreads();
    double tt = M_PI * (double)kk / 255.0;
    double ct = cos(tt), st = sin(tt);
    double w  = (double)d_wq[kk];
    for (int l = 0; l < m; l++) {
        d_PCT [basePCT + l * NLAT + kk] = 0.f;
        d_PCTW[basePCT + l * NLAT + kk] = 0.f;
        d_PCTT[baseT + l] = 0.f;
    }
    double powv = 1.0;
    for (int i = 0; i < m; i++) powv *= -st;
    double p2 = 0.28209479177387814347 * s_sect * powv;   // p[m][m]
    d_PCT [basePCT + m * NLAT + kk] = (float)p2;
    d_PCTW[basePCT + m * NLAT + kk] = (float)(p2 * w);
    d_PCTT[baseT + m] = (float)p2;
    if (m + 1 < LMAX) {
        double p1 = sqrt(2.0 * m + 3.0) * ct * p2;
        d_PCT [basePCT + (m + 1) * NLAT + kk] = (float)p1;
        d_PCTW[basePCT + (m + 1) * NLAT + kk] = (float)(p1 * w);
        d_PCTT[baseT + m + 1] = (float)p1;
        for (int l = m + 2; l < LMAX; l++) {
            double p = s_a[l] * (ct * p1 - s_b[l] * p2);
            d_PCT [basePCT + l * NLAT + kk] = (float)p;
            d_PCTW[basePCT + l * NLAT + kk] = (float)(p * w);
            d_PCTT[baseT + l] = (float)p;
            p2 = p1; p1 = p;
        }
    }
}

// ===========================================================================
// Shared 128x128 tile / 8x8 fragment GEMM machinery
//   Ast[8][132]  layout [k][m]      Bs[8][132] layout [k][n]
//   thread (tc = t&15, tn = t>>4): rows tn*4 (+64), cols tc*4 (+64)
// ===========================================================================
#define GEMM_COMPUTE()                                                        \
    _Pragma("unroll")                                                         \
    for (int j = 0; j < 8; j++) {                                             \
        float4 a0 = *reinterpret_cast<const float4*>(&Ast[j*132 + tn*4]);     \
        float4 a1 = *reinterpret_cast<const float4*>(&Ast[j*132 + tn*4 + 64]);\
        float4 b0 = *reinterpret_cast<const float4*>(&Bs [j*132 + tc*4]);     \
        float4 b1 = *reinterpret_cast<const float4*>(&Bs [j*132 + tc*4 + 64]);\
        float ar[8] = {a0.x,a0.y,a0.z,a0.w,a1.x,a1.y,a1.z,a1.w};              \
        float br[8] = {b0.x,b0.y,b0.z,b0.w,b1.x,b1.y,b1.z,b1.w};              \
        _Pragma("unroll")                                                     \
        for (int p = 0; p < 8; p++)                                           \
            _Pragma("unroll")                                                 \
            for (int q = 0; q < 8; q++) acc[p][q] += ar[p] * br[q];           \
    }

// ---------------------------------------------------------------------------
// G1: xh[n][col] = sum_j F[n][j] * x[bc][klat][j],  col = klat*256+bc
// M=n (256, 2 tiles) N=col (65536, 512 tiles) K=j (256)
// ---------------------------------------------------------------------------
__global__ __launch_bounds__(256, 2) void k_g1(const float* __restrict__ x) {
    __shared__ float Ast[8 * 132];
    __shared__ float Bs [8 * 132];
    int t = threadIdx.x;
    int col0 = blockIdx.x * 128;
    int n0   = blockIdx.y * 128;
    int klat = col0 >> 8;
    int bc0  = col0 & 255;
    const float* xb = x + (size_t)bc0 * 65536 + (size_t)klat * 256;
    int am = t >> 1, ak4 = (t & 1) * 4;        // A: transpose store
    int bm = t >> 1, bk4 = (t & 1) * 4;        // B: x rows (j-fast) transpose store
    int tc = t & 15, tn = t >> 4;
    float acc[8][8] = {};
    for (int kt = 0; kt < 32; kt++) {
        int k0 = kt * 8;
        float4 av = *reinterpret_cast<const float4*>(&d_F[(n0 + am) * 256 + k0 + ak4]);
        float4 bv = *reinterpret_cast<const float4*>(&xb[(size_t)bm * 65536 + k0 + bk4]);
        Ast[(ak4 + 0) * 132 + am] = av.x;
        Ast[(ak4 + 1) * 132 + am] = av.y;
        Ast[(ak4 + 2) * 132 + am] = av.z;
        Ast[(ak4 + 3) * 132 + am] = av.w;
        Bs [(bk4 + 0) * 132 + bm] = bv.x;
        Bs [(bk4 + 1) * 132 + bm] = bv.y;
        Bs [(bk4 + 2) * 132 + bm] = bv.z;
        Bs [(bk4 + 3) * 132 + bm] = bv.w;
        __syncthreads();
        GEMM_COMPUTE();
        __syncthreads();
    }
    #pragma unroll
    for (int ph = 0; ph < 2; ph++)
        #pragma unroll
        for (int e = 0; e < 4; e++) {
            int n = n0 + ph * 64 + tn * 4 + e;
            float* dst = &d_xh[(size_t)n * NROW + col0];
            *reinterpret_cast<float4*>(dst + tc * 4) =
                make_float4(acc[ph*4+e][0], acc[ph*4+e][1], acc[ph*4+e][2], acc[ph*4+e][3]);
            *reinterpret_cast<float4*>(dst + tc * 4 + 64) =
                make_float4(acc[ph*4+e][4], acc[ph*4+e][5], acc[ph*4+e][6], acc[ph*4+e][7]);
        }
}

// ---------------------------------------------------------------------------
// G2: spec[(l*129+m)*2+ri][bc] = sum_k PCTW[m][l][k] * xh[2m+ri][k*256+bc]
// per mri: M=l (128, 1 tile) N=bc (256, 2 tiles) K=k (256). grid (2, 256)
// ---------------------------------------------------------------------------
__global__ __launch_bounds__(256, 2) void k_g2() {
    __shared__ float Ast[8 * 132];
    __shared__ float Bs [8 * 132];
    int t = threadIdx.x;
    int bc0 = blockIdx.x * 128;
    int mri = blockIdx.y;
    int m = mri >> 1, ri = mri & 1;
    const float* A = d_PCTW + (size_t)m * LMAX * NLAT;     // [l][k]
    const float* B = d_xh + (size_t)mri * NROW;            // [k][bc]
    int am = t >> 1, ak4 = (t & 1) * 4;
    int bk = t >> 5, bn4 = (t & 31) * 4;
    int tc = t & 15, tn = t >> 4;
    float acc[8][8] = {};
    for (int kt = 0; kt < 32; kt++) {
        int k0 = kt * 8;
        float4 av = *reinterpret_cast<const float4*>(&A[am * 256 + k0 + ak4]);
        float4 bv = *reinterpret_cast<const float4*>(&B[(size_t)(k0 + bk) * 256 + bc0 + bn4]);
        Ast[(ak4 + 0) * 132 + am] = av.x;
        Ast[(ak4 + 1) * 132 + am] = av.y;
        Ast[(ak4 + 2) * 132 + am] = av.z;
        Ast[(ak4 + 3) * 132 + am] = av.w;
        *reinterpret_cast<float4*>(&Bs[bk * 132 + bn4]) = bv;
        __syncthreads();
        GEMM_COMPUTE();
        __syncthreads();
    }
    #pragma unroll
    for (int ph = 0; ph < 2; ph++)
        #pragma unroll
        for (int e = 0; e < 4; e++) {
            int l = ph * 64 + tn * 4 + e;
            size_t xrow = ((size_t)l * 129 + m) * 2 + ri;
            float* dst = &d_spec[xrow * 256 + bc0];
            *reinterpret_cast<float4*>(dst + tc * 4) =
                make_float4(acc[ph*4+e][0], acc[ph*4+e][1], acc[ph*4+e][2], acc[ph*4+e][3]);
            *reinterpret_cast<float4*>(dst + tc * 4 + 64) =
                make_float4(acc[ph*4+e][4], acc[ph*4+e][5], acc[ph*4+e][6], acc[ph*4+e][7]);
        }
}

// ---------------------------------------------------------------------------
// G3: out2[x][b*32+o] = sum_i spec[x][b*32+i] * W[(i*32+o)*NX + x]
// ---------------------------------------------------------------------------
__global__ __launch_bounds__(256) void k_mix(const float* __restrict__ W) {
    __shared__ float Ws[8 * 1028];
    __shared__ float Ss[8 * 256];
    int t = threadIdx.x;
    int x0 = blockIdx.x * 8;
    #pragma unroll
    for (int rep = 0; rep < 32; rep++) {
        int idx = rep * 256 + t;
        int xl = idx & 7, io = idx >> 3;
        Ws[xl * 1028 + io] = W[(size_t)io * NX + x0 + xl];
    }
    #pragma unroll
    for (int rep = 0; rep < 8; rep++) {
        int idx = rep * 256 + t;
        int xl = idx >> 8, bc = idx & 255;
        Ss[xl * 256 + bc] = d_spec[(size_t)(x0 + xl) * 256 + bc];
    }
    __syncthreads();
    int b = t >> 5, o = t & 31;
    float acc[8] = {};
    #pragma unroll
    for (int xl = 0; xl < 8; xl++)
        #pragma unroll
        for (int i = 0; i < 32; i++)
            acc[xl] += Ss[xl * 256 + b * 32 + i] * Ws[xl * 1028 + i * 32 + o];
    #pragma unroll
    for (int xl = 0; xl < 8; xl++)
        d_out2[(size_t)(x0 + xl) * 256 + t] = acc[xl];
}

// ---------------------------------------------------------------------------
// G4: rr[2m+ri][k*256+bo] = sum_l PCTT[m][k][l] * out2[(l*129+m)*2+ri][bo]
// per mri: M=k (256, 2 tiles) N=bo (256, 2 tiles) K=l (128). grid (4, 256)
// ---------------------------------------------------------------------------
__global__ __launch_bounds__(256, 2) void k_g4() {
    __shared__ float Ast[8 * 132];
    __shared__ float Bs [8 * 132];
    int t = threadIdx.x;
    int k0g = (blockIdx.x >> 1) * 128;
    int bo0 = (blockIdx.x & 1) * 128;
    int mri = blockIdx.y;
    int m = mri >> 1, ri = mri & 1;
    const float* A = d_PCTT + (size_t)m * NLAT * LMAX;     // [k][l]
    int am = t >> 1, ak4 = (t & 1) * 4;
    int bk = t >> 5, bn4 = (t & 31) * 4;
    int tc = t & 15, tn = t >> 4;
    float acc[8][8] = {};
    for (int lt = 0; lt < 16; lt++) {
        int l0 = lt * 8;
        float4 av = *reinterpret_cast<const float4*>(&A[(size_t)(k0g + am) * 128 + l0 + ak4]);
        int l = l0 + bk;
        size_t xrow = ((size_t)l * 129 + m) * 2 + ri;
        float4 bv = *reinterpret_cast<const float4*>(&d_out2[xrow * 256 + bo0 + bn4]);
        Ast[(ak4 + 0) * 132 + am] = av.x;
        Ast[(ak4 + 1) * 132 + am] = av.y;
        Ast[(ak4 + 2) * 132 + am] = av.z;
        Ast[(ak4 + 3) * 132 + am] = av.w;
        *reinterpret_cast<float4*>(&Bs[bk * 132 + bn4]) = bv;
        __syncthreads();
        GEMM_COMPUTE();
        __syncthreads();
    }
    #pragma unroll
    for (int ph = 0; ph < 2; ph++)
        #pragma unroll
        for (int e = 0; e < 4; e++) {
            int k = k0g + ph * 64 + tn * 4 + e;
            float* dst = &d_rr[(size_t)mri * NROW + (size_t)k * 256 + bo0];
            *reinterpret_cast<float4*>(dst + tc * 4) =
                make_float4(acc[ph*4+e][0], acc[ph*4+e][1], acc[ph*4+e][2], acc[ph*4+e][3]);
            *reinterpret_cast<float4*>(dst + tc * 4 + 64) =
                make_float4(acc[ph*4+e][4], acc[ph*4+e][5], acc[ph*4+e][6], acc[ph*4+e][7]);
        }
}

// ---------------------------------------------------------------------------
// G5: y[bo][k][j] = sum_n rr[n][r] * G[n][j],  r = k*256+bo
// M=r (65536, 512 tiles) N=j (256, 2 tiles) K=n (256)
// ---------------------------------------------------------------------------
__global__ __launch_bounds__(256, 2) void k_g5(float* __restrict__ out) {
    __shared__ float Ast[8 * 132];
    __shared__ float Bs [8 * 132];
    int t = threadIdx.x;
    int r0  = blockIdx.x * 128;
    int jc0 = blockIdx.y * 128;
    int ak = t >> 5, am4 = (t & 31) * 4;       // A: rr is [n][r] -> direct [k][m] store
    int bk = t >> 5, bn4 = (t & 31) * 4;
    int tc = t & 15, tn = t >> 4;
    float acc[8][8] = {};
    for (int kt = 0; kt < 32; kt++) {
        int n0 = kt * 8;
        float4 av = *reinterpret_cast<const float4*>(&d_rr[(size_t)(n0 + ak) * NROW + r0 + am4]);
        float4 bv = *reinterpret_cast<const float4*>(&d_G[(n0 + bk) * 256 + jc0 + bn4]);
        *reinterpret_cast<float4*>(&Ast[ak * 132 + am4]) = av;
        *reinterpret_cast<float4*>(&Bs [bk * 132 + bn4]) = bv;
        __syncthreads();
        GEMM_COMPUTE();
        __syncthreads();
    }
    #pragma unroll
    for (int ph = 0; ph < 2; ph++)
        #pragma unroll
        for (int e = 0; e < 4; e++) {
            int r = r0 + ph * 64 + tn * 4 + e;
            int k = r >> 8, bo = r & 255;
            float* dst = &out[(size_t)bo * 65536 + (size_t)k * 256 + jc0];
            *reinterpret_cast<float4*>(dst + tc * 4) =
                make_float4(acc[ph*4+e][0], acc[ph*4+e][1], acc[ph*4+e][2], acc[ph*4+e][3]);
            *reinterpret_cast<float4*>(dst + tc * 4 + 64) =
                make_float4(acc[ph*4+e][4], acc[ph*4+e][5], acc[ph*4+e][6], acc[ph*4+e][7]);
        }
}

// ---------------------------------------------------------------------------
extern "C" void kernel_launch(void* const* d_in, const int* in_sizes, int n_in,
                              void* d_out, int out_size) {
    const float* x = (const float*)d_in[0];
    const float* w = (const float*)d_in[1];
    float* out = (float*)d_out;

    k_quad<<<256, 128>>>();
    k_fourier<<<129, 256>>>();
    k_legendre<<<129, 256>>>();

    dim3 g1(512, 2);   k_g1<<<g1, 256>>>(x);
    dim3 g2(2, 256);   k_g2<<<g2, 256>>>();
    k_mix<<<NX / 8, 256>>>(w);
    dim3 g4(4, 256);   k_g4<<<g4, 256>>>();
    dim3 g5(512, 2);   k_g5<<<g5, 256>>>(out);
}

// round 8
// speedup vs baseline: 1.4958x; 1.2298x over previous
#include <cuda_runtime.h>
#include <math.h>

#define NLAT  256
#define NLON  256
#define LMAX  128
#define MMAX  129
#define NM    256           // effective 2*128 (m=128 plane identically zero)
#define NX    33024         // 2*LMAX*MMAX
#define BCH   256           // BATCH*CIN = BATCH*COUT
#define NROW  65536         // BCH*NLAT
#define KEPAD 136           // padded K for cos GEMM (valid j = 0..128)

// ---------------------------------------------------------------------------
// Static device scratch (no allocations; zero-initialized at load)
// ---------------------------------------------------------------------------
__device__ float d_wq[NLAT];
__device__ float d_Fc[LMAX * KEPAD];                   // [m][j] sc*cos, j<=128, else 0
__device__ float d_Fs[LMAX * 128];                     // [m][j] -sc*sin
__device__ float d_Gc[LMAX * 128];                     // [m][j] wm*cos
__device__ float d_Gs[LMAX * 128];                     // [m][j] wm*sin
__device__ float d_PCTW[(size_t)MMAX * LMAX * NLAT];   // [m][l][k] * wq
__device__ float d_PCTT[(size_t)MMAX * NLAT * LMAX];   // [m][k][l]
__device__ float d_xe  [(size_t)KEPAD * NROW];         // folded even, rows 129..135 stay 0
__device__ float d_xo  [(size_t)128 * NROW];           // folded odd
__device__ float d_xh  [(size_t)NM * NROW];            // [n=2m+ri][k*256+bc]
__device__ float d_spec[(size_t)NX * BCH];             // (m=128 rows stay 0)
__device__ float d_out2[(size_t)NX * BCH];
__device__ float d_rr  [(size_t)NM * NROW];            // [n][k*256+bo]

// ---------------------------------------------------------------------------
// Clenshaw-Curtis quadrature weights
// ---------------------------------------------------------------------------
__global__ __launch_bounds__(128) void k_quad() {
    int j = blockIdx.x;
    int k = threadIdx.x;
    double tj = M_PI * (double)j / 255.0;
    double v = 0.0;
    if (k >= 1) v = cos(2.0 * tj * (double)k) * (2.0 / (4.0 * (double)k * k - 1.0));
    __shared__ double red[128];
    red[k] = v;
    __syncthreads();
    for (int s = 64; s > 0; s >>= 1) {
        if (k < s) red[k] += red[k + s];
        __syncthreads();
    }
    if (k == 0) {
        double c = (j == 0 || j == 255) ? 1.0 : 2.0;
        d_wq[j] = (float)(c / 255.0 * (1.0 - red[0]));
    }
}

// ---------------------------------------------------------------------------
// Fourier tables (exact mod-256 phase reduction)
// ---------------------------------------------------------------------------
__global__ __launch_bounds__(256) void k_four2() {
    int m = blockIdx.x;                  // 0..127
    int j = threadIdx.x;                 // 0..255
    int r = (m * j) & 255;
    float s, c;
    sincosf((float)(2.0 * M_PI / 256.0 * (double)r), &s, &c);
    const float sc = (float)(2.0 * M_PI / 256.0);
    if (j < KEPAD) d_Fc[m * KEPAD + j] = (j <= 128) ? sc * c : 0.f;
    if (j < 128) {
        d_Fs[m * 128 + j] = -sc * s;
        float wm = (m == 0) ? 1.f : 2.f;
        d_Gc[m * 128 + j] = wm * c;
        d_Gs[m * 128 + j] = wm * s;
    }
}

// ---------------------------------------------------------------------------
// Associated Legendre tables (double precision recurrences)
// ---------------------------------------------------------------------------
__global__ __launch_bounds__(256) void k_legendre() {
    int m  = blockIdx.x;                 // 0..128
    int kk = threadIdx.x;                // 0..255
    size_t baseW = (size_t)m * LMAX * NLAT;
    size_t baseT = (size_t)m * NLAT * LMAX + (size_t)kk * LMAX;
    if (m >= LMAX) {
        for (int l = 0; l < LMAX; l++) {
            d_PCTW[baseW + l * NLAT + kk] = 0.f;
            d_PCTT[baseT + l] = 0.f;
        }
        return;
    }
    __shared__ double s_a[LMAX], s_b[LMAX];
    __shared__ double s_sect;
    if (kk < LMAX) {
        int l = kk;
        if (l >= m + 2) {
            double fl = (double)l, fm = (double)m, g = fl - 1.0;
            s_a[l] = sqrt((4.0 * fl * fl - 1.0) / (fl * fl - fm * fm));
            s_b[l] = sqrt((g * g - fm * fm) / (4.0 * g * g - 1.0));
        }
    }
    if (kk == 0) {
        double pr = 1.0;
        for (int i = 1; i <= m; i++) pr *= (2.0 * i + 1.0) / (2.0 * i);
        s_sect = sqrt(pr);
    }
    __syncthreads();
    double tt = M_PI * (double)kk / 255.0;
    double ct = cos(tt), st = sin(tt);
    double w  = (double)d_wq[kk];
    for (int l = 0; l < m; l++) {
        d_PCTW[baseW + l * NLAT + kk] = 0.f;
        d_PCTT[baseT + l] = 0.f;
    }
    double powv = 1.0;
    for (int i = 0; i < m; i++) powv *= -st;
    double p2 = 0.28209479177387814347 * s_sect * powv;   // p[m][m]
    d_PCTW[baseW + m * NLAT + kk] = (float)(p2 * w);
    d_PCTT[baseT + m] = (float)p2;
    if (m + 1 < LMAX) {
        double p1 = sqrt(2.0 * m + 3.0) * ct * p2;
        d_PCTW[baseW + (m + 1) * NLAT + kk] = (float)(p1 * w);
        d_PCTT[baseT + m + 1] = (float)p1;
        for (int l = m + 2; l < LMAX; l++) {
            double p = s_a[l] * (ct * p1 - s_b[l] * p2);
            d_PCTW[baseW + l * NLAT + kk] = (float)(p * w);
            d_PCTT[baseT + l] = (float)p;
            p2 = p1; p1 = p;
        }
    }
}

// ---------------------------------------------------------------------------
// Fold: xe[j][col] = x[j]+x[256-j] (j=1..127), xe[0]=x[0], xe[128]=x[128]
//       xo[j][col] = x[j]-x[256-j] (j=1..127), xo[0]=0
// col = klat*256+bc; x addressed [bc][klat][j]. 32 cols per block, smem transpose.
// ---------------------------------------------------------------------------
__global__ __launch_bounds__(256) void k_fold(const float* __restrict__ x) {
    __shared__ float s[32][257];
    int t = threadIdx.x;
    int col0 = blockIdx.x * 32;
    int klat = col0 >> 8;
    int bc0  = col0 & 255;
    #pragma unroll 4
    for (int r = 0; r < 32; r++)
        s[r][t] = x[(size_t)(bc0 + r) * 65536 + klat * 256 + t];
    __syncthreads();
    #pragma unroll 4
    for (int it = 0; it < 16; it++) {
        int idx = it * 256 + t;
        int j = idx >> 5, c = idx & 31;
        float a = s[c][j];
        float b = s[c][(256 - j) & 255];
        float xe = (j == 0) ? a : a + b;
        float xo = (j == 0) ? 0.f : a - b;
        d_xe[(size_t)j * NROW + col0 + c] = xe;
        d_xo[(size_t)j * NROW + col0 + c] = xo;
    }
    if (t < 32) d_xe[(size_t)128 * NROW + col0 + t] = s[t][128];
}

// ===========================================================================
// 128x128 tile / 8x8 fragment, double-buffered GEMM core
// ===========================================================================
#define GEMM_COMPUTE(Ap, Bp)                                                  \
    _Pragma("unroll")                                                         \
    for (int j = 0; j < 8; j++) {                                             \
        float4 a0 = *reinterpret_cast<const float4*>(&(Ap)[j*132 + tn*4]);    \
        float4 a1 = *reinterpret_cast<const float4*>(&(Ap)[j*132 + tn*4 + 64]);\
        float4 b0 = *reinterpret_cast<const float4*>(&(Bp)[j*132 + tc*4]);    \
        float4 b1 = *reinterpret_cast<const float4*>(&(Bp)[j*132 + tc*4 + 64]);\
        float ar[8] = {a0.x,a0.y,a0.z,a0.w,a1.x,a1.y,a1.z,a1.w};              \
        float br[8] = {b0.x,b0.y,b0.z,b0.w,b1.x,b1.y,b1.z,b1.w};              \
        _Pragma("unroll")                                                     \
        for (int p = 0; p < 8; p++)                                           \
            _Pragma("unroll")                                                 \
            for (int q = 0; q < 8; q++) acc[p][q] += ar[p] * br[q];           \
    }

#define A_TSTORE(buf, v)                                                      \
    do { (buf)[(ak4+0)*132+am] = (v).x; (buf)[(ak4+1)*132+am] = (v).y;        \
         (buf)[(ak4+2)*132+am] = (v).z; (buf)[(ak4+3)*132+am] = (v).w; } while(0)

// ---------------------------------------------------------------------------
// G1 folded: xh[2*mm+PAR][col] = sum_j Atab[mm][j] * Bmat[j][col]
// PAR=0: Atab=d_Fc (stride 136, KT=17), Bmat=d_xe.  PAR=1: d_Fs/128/16, d_xo.
// Device-side symbol selection (host cannot pass __device__ symbol addresses).
// ---------------------------------------------------------------------------
template<int PAR>
__global__ __launch_bounds__(256, 2) void k_g1f() {
    const float* Atab = PAR ? d_Fs : d_Fc;
    const float* Bmat = PAR ? d_xo : d_xe;
    const int astr = PAR ? 128 : KEPAD;
    const int KT   = PAR ? 16 : 17;
    __shared__ float Ast[2][8 * 132];
    __shared__ float Bs [2][8 * 132];
    int t = threadIdx.x;
    int col0 = blockIdx.x * 128;
    int am = t >> 1, ak4 = (t & 1) * 4;
    int bk = t >> 5, bn4 = (t & 31) * 4;
    int tc = t & 15, tn = t >> 4;
    float4 av = *reinterpret_cast<const float4*>(&Atab[am * astr + ak4]);
    float4 bv = *reinterpret_cast<const float4*>(&Bmat[(size_t)bk * NROW + col0 + bn4]);
    A_TSTORE(Ast[0], av);
    *reinterpret_cast<float4*>(&Bs[0][bk * 132 + bn4]) = bv;
    __syncthreads();
    float acc[8][8] = {};
    for (int kt = 0; kt < KT; kt++) {
        int cur = kt & 1;
        bool more = (kt + 1 < KT);
        float4 an, bn_;
        if (more) {
            int k0 = (kt + 1) * 8;
            an  = *reinterpret_cast<const float4*>(&Atab[am * astr + k0 + ak4]);
            bn_ = *reinterpret_cast<const float4*>(&Bmat[(size_t)(k0 + bk) * NROW + col0 + bn4]);
        }
        GEMM_COMPUTE(Ast[cur], Bs[cur]);
        if (more) {
            A_TSTORE(Ast[cur ^ 1], an);
            *reinterpret_cast<float4*>(&Bs[cur ^ 1][bk * 132 + bn4]) = bn_;
            __syncthreads();
        }
    }
    #pragma unroll
    for (int ph = 0; ph < 2; ph++)
        #pragma unroll
        for (int e = 0; e < 4; e++) {
            int mm = ph * 64 + tn * 4 + e;
            float* dst = &d_xh[(size_t)(2 * mm + PAR) * NROW + col0];
            *reinterpret_cast<float4*>(dst + tc * 4) =
                make_float4(acc[ph*4+e][0], acc[ph*4+e][1], acc[ph*4+e][2], acc[ph*4+e][3]);
            *reinterpret_cast<float4*>(dst + tc * 4 + 64) =
                make_float4(acc[ph*4+e][4], acc[ph*4+e][5], acc[ph*4+e][6], acc[ph*4+e][7]);
        }
}

// ---------------------------------------------------------------------------
// G2: spec[(l*129+m)*2+ri][bc] = sum_k PCTW[m][l][k] * xh[2m+ri][k*256+bc]
// grid (2, 256)
// ---------------------------------------------------------------------------
__global__ __launch_bounds__(256, 2) void k_g2() {
    __shared__ float Ast[2][8 * 132];
    __shared__ float Bs [2][8 * 132];
    int t = threadIdx.x;
    int bc0 = blockIdx.x * 128;
    int mri = blockIdx.y;
    int m = mri >> 1, ri = mri & 1;
    const float* A = d_PCTW + (size_t)m * LMAX * NLAT;     // [l][k]
    const float* B = d_xh + (size_t)mri * NROW;            // [k][bc]
    int am = t >> 1, ak4 = (t & 1) * 4;
    int bk = t >> 5, bn4 = (t & 31) * 4;
    int tc = t & 15, tn = t >> 4;
    float4 av = *reinterpret_cast<const float4*>(&A[am * 256 + ak4]);
    float4 bv = *reinterpret_cast<const float4*>(&B[(size_t)bk * 256 + bc0 + bn4]);
    A_TSTORE(Ast[0], av);
    *reinterpret_cast<float4*>(&Bs[0][bk * 132 + bn4]) = bv;
    __syncthreads();
    float acc[8][8] = {};
    for (int kt = 0; kt < 32; kt++) {
        int cur = kt & 1;
        bool more = (kt + 1 < 32);
        float4 an, bn_;
        if (more) {
            int k0 = (kt + 1) * 8;
            an  = *reinterpret_cast<const float4*>(&A[am * 256 + k0 + ak4]);
            bn_ = *reinterpret_cast<const float4*>(&B[(size_t)(k0 + bk) * 256 + bc0 + bn4]);
        }
        GEMM_COMPUTE(Ast[cur], Bs[cur]);
        if (more) {
            A_TSTORE(Ast[cur ^ 1], an);
            *reinterpret_cast<float4*>(&Bs[cur ^ 1][bk * 132 + bn4]) = bn_;
            __syncthreads();
        }
    }
    #pragma unroll
    for (int ph = 0; ph < 2; ph++)
        #pragma unroll
        for (int e = 0; e < 4; e++) {
            int l = ph * 64 + tn * 4 + e;
            size_t xrow = ((size_t)l * 129 + m) * 2 + ri;
            float* dst = &d_spec[xrow * 256 + bc0];
            *reinterpret_cast<float4*>(dst + tc * 4) =
                make_float4(acc[ph*4+e][0], acc[ph*4+e][1], acc[ph*4+e][2], acc[ph*4+e][3]);
            *reinterpret_cast<float4*>(dst + tc * 4 + 64) =
                make_float4(acc[ph*4+e][4], acc[ph*4+e][5], acc[ph*4+e][6], acc[ph*4+e][7]);
        }
}

// ---------------------------------------------------------------------------
// G3: out2[x][b*32+o] = sum_i spec[x][b*32+i] * W[(i*32+o)*NX + x]
// ---------------------------------------------------------------------------
__global__ __launch_bounds__(256) void k_mix(const float* __restrict__ W) {
    __shared__ float Ws[8 * 1028];
    __shared__ float Ss[8 * 256];
    int t = threadIdx.x;
    int x0 = blockIdx.x * 8;
    #pragma unroll
    for (int rep = 0; rep < 32; rep++) {
        int idx = rep * 256 + t;
        int xl = idx & 7, io = idx >> 3;
        Ws[xl * 1028 + io] = W[(size_t)io * NX + x0 + xl];
    }
    #pragma unroll
    for (int rep = 0; rep < 8; rep++) {
        int idx = rep * 256 + t;
        int xl = idx >> 8, bc = idx & 255;
        Ss[xl * 256 + bc] = d_spec[(size_t)(x0 + xl) * 256 + bc];
    }
    __syncthreads();
    int b = t >> 5, o = t & 31;
    float acc[8] = {};
    #pragma unroll
    for (int xl = 0; xl < 8; xl++)
        #pragma unroll
        for (int i = 0; i < 32; i++)
            acc[xl] += Ss[xl * 256 + b * 32 + i] * Ws[xl * 1028 + i * 32 + o];
    #pragma unroll
    for (int xl = 0; xl < 8; xl++)
        d_out2[(size_t)(x0 + xl) * 256 + t] = acc[xl];
}

// ---------------------------------------------------------------------------
// G4: rr[2m+ri][k*256+bo] = sum_l PCTT[m][k][l] * out2[(l*129+m)*2+ri][bo]
// grid (4, 256)
// ---------------------------------------------------------------------------
__global__ __launch_bounds__(256, 2) void k_g4() {
    __shared__ float Ast[2][8 * 132];
    __shared__ float Bs [2][8 * 132];
    int t = threadIdx.x;
    int k0g = (blockIdx.x >> 1) * 128;
    int bo0 = (blockIdx.x & 1) * 128;
    int mri = blockIdx.y;
    int m = mri >> 1, ri = mri & 1;
    const float* A = d_PCTT + (size_t)m * NLAT * LMAX;     // [k][l]
    int am = t >> 1, ak4 = (t & 1) * 4;
    int bk = t >> 5, bn4 = (t & 31) * 4;
    int tc = t & 15, tn = t >> 4;
    float4 av = *reinterpret_cast<const float4*>(&A[(size_t)(k0g + am) * 128 + ak4]);
    float4 bv;
    {
        size_t xrow = ((size_t)bk * 129 + m) * 2 + ri;
        bv = *reinterpret_cast<const float4*>(&d_out2[xrow * 256 + bo0 + bn4]);
    }
    A_TSTORE(Ast[0], av);
    *reinterpret_cast<float4*>(&Bs[0][bk * 132 + bn4]) = bv;
    __syncthreads();
    float acc[8][8] = {};
    for (int lt = 0; lt < 16; lt++) {
        int cur = lt & 1;
        bool more = (lt + 1 < 16);
        float4 an, bn_;
        if (more) {
            int l0 = (lt + 1) * 8;
            an = *reinterpret_cast<const float4*>(&A[(size_t)(k0g + am) * 128 + l0 + ak4]);
            size_t xrow = ((size_t)(l0 + bk) * 129 + m) * 2 + ri;
            bn_ = *reinterpret_cast<const float4*>(&d_out2[xrow * 256 + bo0 + bn4]);
        }
        GEMM_COMPUTE(Ast[cur], Bs[cur]);
        if (more) {
            A_TSTORE(Ast[cur ^ 1], an);
            *reinterpret_cast<float4*>(&Bs[cur ^ 1][bk * 132 + bn4]) = bn_;
            __syncthreads();
        }
    }
    #pragma unroll
    for (int ph = 0; ph < 2; ph++)
        #pragma unroll
        for (int e = 0; e < 4; e++) {
            int k = k0g + ph * 64 + tn * 4 + e;
            float* dst = &d_rr[(size_t)mri * NROW + (size_t)k * 256 + bo0];
            *reinterpret_cast<float4*>(dst + tc * 4) =
                make_float4(acc[ph*4+e][0], acc[ph*4+e][1], acc[ph*4+e][2], acc[ph*4+e][3]);
            *reinterpret_cast<float4*>(dst + tc * 4 + 64) =
                make_float4(acc[ph*4+e][4], acc[ph*4+e][5], acc[ph*4+e][6], acc[ph*4+e][7]);
        }
}

// ---------------------------------------------------------------------------
// G5 folded+fused: C[col][j]=sum_m Gc[m][j]*rr[2m][col], S likewise (Gs, rr odd)
// y[col -> bo,k][j] = C-S ; y[..][256-j] = C+S (j>=1). Tile: 128 col x 64 j.
// grid (512, 2)
// ---------------------------------------------------------------------------
__global__ __launch_bounds__(256, 2) void k_g5f(float* __restrict__ out) {
    __shared__ float AeS[2][8 * 132];
    __shared__ float AoS[2][8 * 132];
    __shared__ float BcS[2][8 * 68];
    __shared__ float BsS[2][8 * 68];
    int t = threadIdx.x;
    int col0 = blockIdx.x * 128;
    int j0   = blockIdx.y * 64;
    int ar = t >> 5, ac4 = (t & 31) * 4;
    int mr = (t & 127) >> 4, jc = t & 15;
    int tc = t & 15, tn = t >> 4;
    float4 ave = *reinterpret_cast<const float4*>(&d_rr[(size_t)(2 * ar) * NROW + col0 + ac4]);
    float4 avo = *reinterpret_cast<const float4*>(&d_rr[(size_t)(2 * ar + 1) * NROW + col0 + ac4]);
    float4 bvx;
    if (t < 128) bvx = *reinterpret_cast<const float4*>(&d_Gc[mr * 128 + j0 + jc * 4]);
    else         bvx = *reinterpret_cast<const float4*>(&d_Gs[mr * 128 + j0 + jc * 4]);
    *reinterpret_cast<float4*>(&AeS[0][ar * 132 + ac4]) = ave;
    *reinterpret_cast<float4*>(&AoS[0][ar * 132 + ac4]) = avo;
    if (t < 128) *reinterpret_cast<float4*>(&BcS[0][mr * 68 + jc * 4]) = bvx;
    else         *reinterpret_cast<float4*>(&BsS[0][mr * 68 + jc * 4]) = bvx;
    __syncthreads();
    float accC[8][4] = {};
    float accS[8][4] = {};
    for (int kt = 0; kt < 16; kt++) {
        int cur = kt & 1;
        bool more = (kt + 1 < 16);
        float4 ane, ano, bn_;
        if (more) {
            int m0 = (kt + 1) * 8;
            ane = *reinterpret_cast<const float4*>(&d_rr[(size_t)(2 * (m0 + ar)) * NROW + col0 + ac4]);
            ano = *reinterpret_cast<const float4*>(&d_rr[(size_t)(2 * (m0 + ar) + 1) * NROW + col0 + ac4]);
            if (t < 128) bn_ = *reinterpret_cast<const float4*>(&d_Gc[(m0 + mr) * 128 + j0 + jc * 4]);
            else         bn_ = *reinterpret_cast<const float4*>(&d_Gs[(m0 + mr) * 128 + j0 + jc * 4]);
        }
        const float* Ae = AeS[cur]; const float* Ao = AoS[cur];
        const float* Bc = BcS[cur]; const float* Bss = BsS[cur];
        #pragma unroll
        for (int j = 0; j < 8; j++) {
            float4 e0 = *reinterpret_cast<const float4*>(&Ae[j * 132 + tn * 4]);
            float4 e1 = *reinterpret_cast<const float4*>(&Ae[j * 132 + tn * 4 + 64]);
            float4 o0 = *reinterpret_cast<const float4*>(&Ao[j * 132 + tn * 4]);
            float4 o1 = *reinterpret_cast<const float4*>(&Ao[j * 132 + tn * 4 + 64]);
            float4 cc = *reinterpret_cast<const float4*>(&Bc[j * 68 + tc * 4]);
            float4 ss = *reinterpret_cast<const float4*>(&Bss[j * 68 + tc * 4]);
            float ae[8] = {e0.x,e0.y,e0.z,e0.w,e1.x,e1.y,e1.z,e1.w};
            float ao[8] = {o0.x,o0.y,o0.z,o0.w,o1.x,o1.y,o1.z,o1.w};
            float bc_[4] = {cc.x,cc.y,cc.z,cc.w};
            float bs_[4] = {ss.x,ss.y,ss.z,ss.w};
            #pragma unroll
            for (int p = 0; p < 8; p++)
                #pragma unroll
                for (int q = 0; q < 4; q++) {
                    accC[p][q] += ae[p] * bc_[q];
                    accS[p][q] += ao[p] * bs_[q];
                }
        }
        if (more) {
            *reinterpret_cast<float4*>(&AeS[cur ^ 1][ar * 132 + ac4]) = ane;
            *reinterpret_cast<float4*>(&AoS[cur ^ 1][ar * 132 + ac4]) = ano;
            if (t < 128) *reinterpret_cast<float4*>(&BcS[cur ^ 1][mr * 68 + jc * 4]) = bn_;
            else         *reinterpret_cast<float4*>(&BsS[cur ^ 1][mr * 68 + jc * 4]) = bn_;
            __syncthreads();
        }
    }
    int jj0 = j0 + tc * 4;
    #pragma unroll
    for (int ph = 0; ph < 2; ph++)
        #pragma unroll
        for (int e = 0; e < 4; e++) {
            int p = ph * 4 + e;
            int col = col0 + ph * 64 + tn * 4 + e;
            int bo = col & 255, k = col >> 8;
            float* base = &out[(size_t)bo * 65536 + (size_t)k * 256];
            *reinterpret_cast<float4*>(base + jj0) =
                make_float4(accC[p][0] - accS[p][0], accC[p][1] - accS[p][1],
                            accC[p][2] - accS[p][2], accC[p][3] - accS[p][3]);
            #pragma unroll
            for (int q = 0; q < 4; q++) {
                int jj = jj0 + q;
                if (jj > 0) base[256 - jj] = accC[p][q] + accS[p][q];
            }
        }
}

// ---------------------------------------------------------------------------
// y[128] column: out[bo][k][128] = sum_m wm*(-1)^m * rr[2m][col]
// ---------------------------------------------------------------------------
__global__ __launch_bounds__(256) void k_y128(float* __restrict__ out) {
    int col = blockIdx.x * 256 + threadIdx.x;
    float acc = 0.f;
    #pragma unroll
    for (int m = 0; m < 128; m++) {
        float g = (m == 0) ? 1.f : ((m & 1) ? -2.f : 2.f);
        acc += g * d_rr[(size_t)(2 * m) * NROW + col];
    }
    int bo = col & 255, k = col >> 8;
    out[(size_t)bo * 65536 + (size_t)k * 256 + 128] = acc;
}

// ---------------------------------------------------------------------------
extern "C" void kernel_launch(void* const* d_in, const int* in_sizes, int n_in,
                              void* d_out, int out_size) {
    const float* x = (const float*)d_in[0];
    const float* w = (const float*)d_in[1];
    float* out = (float*)d_out;

    k_quad<<<256, 128>>>();
    k_four2<<<128, 256>>>();
    k_legendre<<<129, 256>>>();

    k_fold<<<2048, 256>>>(x);
    k_g1f<0><<<512, 256>>>();      // Re rows (n=2m), K=136
    k_g1f<1><<<512, 256>>>();      // Im rows (n=2m+1), K=128
    dim3 g2(2, 256);   k_g2<<<g2, 256>>>();
    k_mix<<<NX / 8, 256>>>(w);
    dim3 g4(4, 256);   k_g4<<<g4, 256>>>();
    dim3 g5(512, 2);   k_g5f<<<g5, 256>>>(out);
    k_y128<<<256, 256>>>(out);
}

// round 9
// speedup vs baseline: 1.7548x; 1.1731x over previous
#include <cuda_runtime.h>
#include <math.h>

#define NLAT  256
#define NLON  256
#define LMAX  128
#define MMAX  129
#define NM    256           // effective 2*128 (m=128 plane identically zero)
#define NX    33024         // 2*LMAX*MMAX
#define BCH   256           // BATCH*CIN = BATCH*COUT
#define NROW  65536         // BCH*NLAT
#define KEPAD 136           // padded K for cos GEMM (valid j = 0..128)

// ---------------------------------------------------------------------------
// Static device scratch (no allocations; zero-initialized at load)
// ---------------------------------------------------------------------------
__device__ float d_wq[NLAT];
__device__ float d_Fc[LMAX * KEPAD];                   // [m][j] sc*cos, j<=128, else 0
__device__ float d_Fs[LMAX * 128];                     // [m][j] -sc*sin
__device__ float d_Gc[LMAX * 128];                     // [m][j] wm*cos
__device__ float d_Gs[LMAX * 128];                     // [m][j] wm*sin
// latitude-parity stacked Legendre tables, k < 128 only.
// li = ((l+m)&1)*64 + (l>>1)   (li<64: l+m even -> "E", li>=64: odd -> "O")
__device__ float d_PCTW2[(size_t)LMAX * 128 * 128];    // [m][li][k]  (P*w)
__device__ float d_PCTT2[(size_t)LMAX * 128 * 128];    // [m][k][li]  (P)
__device__ float d_xe  [(size_t)KEPAD * NROW];         // folded even, rows 129..135 stay 0
__device__ float d_xo  [(size_t)128 * NROW];           // folded odd
__device__ float d_xh  [(size_t)NM * NROW];            // [n=2m+ri][k*256+bc]
__device__ float d_spec[(size_t)NX * BCH];             // (m=128 rows stay 0)
__device__ float d_out2[(size_t)NX * BCH];
__device__ float d_rr  [(size_t)NM * NROW];            // [n][k*256+bo]

// ---------------------------------------------------------------------------
// Clenshaw-Curtis quadrature weights
// ---------------------------------------------------------------------------
__global__ __launch_bounds__(128) void k_quad() {
    int j = blockIdx.x;
    int k = threadIdx.x;
    double tj = M_PI * (double)j / 255.0;
    double v = 0.0;
    if (k >= 1) v = cos(2.0 * tj * (double)k) * (2.0 / (4.0 * (double)k * k - 1.0));
    __shared__ double red[128];
    red[k] = v;
    __syncthreads();
    for (int s = 64; s > 0; s >>= 1) {
        if (k < s) red[k] += red[k + s];
        __syncthreads();
    }
    if (k == 0) {
        double c = (j == 0 || j == 255) ? 1.0 : 2.0;
        d_wq[j] = (float)(c / 255.0 * (1.0 - red[0]));
    }
}

// ---------------------------------------------------------------------------
// Fourier tables (exact mod-256 phase reduction)
// ---------------------------------------------------------------------------
__global__ __launch_bounds__(256) void k_four2() {
    int m = blockIdx.x;                  // 0..127
    int j = threadIdx.x;                 // 0..255
    int r = (m * j) & 255;
    float s, c;
    sincosf((float)(2.0 * M_PI / 256.0 * (double)r), &s, &c);
    const float sc = (float)(2.0 * M_PI / 256.0);
    if (j < KEPAD) d_Fc[m * KEPAD + j] = (j <= 128) ? sc * c : 0.f;
    if (j < 128) {
        d_Fs[m * 128 + j] = -sc * s;
        float wm = (m == 0) ? 1.f : 2.f;
        d_Gc[m * 128 + j] = wm * c;
        d_Gs[m * 128 + j] = wm * s;
    }
}

// ---------------------------------------------------------------------------
// Legendre tables, parity-stacked, nodes k<128 (double precision recurrence)
// grid: 128 blocks (m), 128 threads (node kk = l-helper index)
// ---------------------------------------------------------------------------
__global__ __launch_bounds__(128) void k_legendre() {
    int m  = blockIdx.x;                 // 0..127
    int kk = threadIdx.x;                // 0..127 node index
    __shared__ double s_a[LMAX], s_b[LMAX];
    __shared__ double s_sect;
    {
        int l = kk;
        if (l >= m + 2) {
            double fl = (double)l, fm = (double)m, g = fl - 1.0;
            s_a[l] = sqrt((4.0 * fl * fl - 1.0) / (fl * fl - fm * fm));
            s_b[l] = sqrt((g * g - fm * fm) / (4.0 * g * g - 1.0));
        }
    }
    if (kk == 0) {
        double pr = 1.0;
        for (int i = 1; i <= m; i++) pr *= (2.0 * i + 1.0) / (2.0 * i);
        s_sect = sqrt(pr);
    }
    __syncthreads();
    double tt = M_PI * (double)kk / 255.0;
    double ct = cos(tt), st = sin(tt);
    double w  = (double)d_wq[kk];
    size_t baseW = (size_t)m * 128 * 128;
    size_t baseT = (size_t)m * 128 * 128 + (size_t)kk * 128;
    // zero-fill l<m
    for (int l = 0; l < m; l++) {
        int li = (((l + m) & 1) << 6) | (l >> 1);
        d_PCTW2[baseW + (size_t)li * 128 + kk] = 0.f;
        d_PCTT2[baseT + li] = 0.f;
    }
    double powv = 1.0;
    for (int i = 0; i < m; i++) powv *= -st;
    double p2 = 0.28209479177387814347 * s_sect * powv;   // p[m][m], parity even
    {
        int li = (m >> 1);                                 // (m+m)&1 == 0
        d_PCTW2[baseW + (size_t)li * 128 + kk] = (float)(p2 * w);
        d_PCTT2[baseT + li] = (float)p2;
    }
    if (m + 1 < LMAX) {
        double p1 = sqrt(2.0 * m + 3.0) * ct * p2;
        {
            int li = 64 + ((m + 1) >> 1);                  // parity odd
            d_PCTW2[baseW + (size_t)li * 128 + kk] = (float)(p1 * w);
            d_PCTT2[baseT + li] = (float)p1;
        }
        for (int l = m + 2; l < LMAX; l++) {
            double p = s_a[l] * (ct * p1 - s_b[l] * p2);
            int li = (((l + m) & 1) << 6) | (l >> 1);
            d_PCTW2[baseW + (size_t)li * 128 + kk] = (float)(p * w);
            d_PCTT2[baseT + li] = (float)p;
            p2 = p1; p1 = p;
        }
    }
}

// ---------------------------------------------------------------------------
// Fold (longitude): xe[j]=x[j]+x[256-j], xo[j]=x[j]-x[256-j]
// ---------------------------------------------------------------------------
__global__ __launch_bounds__(256) void k_fold(const float* __restrict__ x) {
    __shared__ float s[32][257];
    int t = threadIdx.x;
    int col0 = blockIdx.x * 32;
    int klat = col0 >> 8;
    int bc0  = col0 & 255;
    #pragma unroll 4
    for (int r = 0; r < 32; r++)
        s[r][t] = x[(size_t)(bc0 + r) * 65536 + klat * 256 + t];
    __syncthreads();
    #pragma unroll 4
    for (int it = 0; it < 16; it++) {
        int idx = it * 256 + t;
        int j = idx >> 5, c = idx & 31;
        float a = s[c][j];
        float b = s[c][(256 - j) & 255];
        float xe = (j == 0) ? a : a + b;
        float xo = (j == 0) ? 0.f : a - b;
        d_xe[(size_t)j * NROW + col0 + c] = xe;
        d_xo[(size_t)j * NROW + col0 + c] = xo;
    }
    if (t < 32) d_xe[(size_t)128 * NROW + col0 + t] = s[t][128];
}

// ===========================================================================
// GEMM helpers
// ===========================================================================
#define GEMM_COMPUTE(Ap, Bp)                                                  \
    _Pragma("unroll")                                                         \
    for (int j = 0; j < 8; j++) {                                             \
        float4 a0 = *reinterpret_cast<const float4*>(&(Ap)[j*132 + tn*4]);    \
        float4 a1 = *reinterpret_cast<const float4*>(&(Ap)[j*132 + tn*4 + 64]);\
        float4 b0 = *reinterpret_cast<const float4*>(&(Bp)[j*132 + tc*4]);    \
        float4 b1 = *reinterpret_cast<const float4*>(&(Bp)[j*132 + tc*4 + 64]);\
        float ar[8] = {a0.x,a0.y,a0.z,a0.w,a1.x,a1.y,a1.z,a1.w};              \
        float br[8] = {b0.x,b0.y,b0.z,b0.w,b1.x,b1.y,b1.z,b1.w};              \
        _Pragma("unroll")                                                     \
        for (int p = 0; p < 8; p++)                                           \
            _Pragma("unroll")                                                 \
            for (int q = 0; q < 8; q++) acc[p][q] += ar[p] * br[q];           \
    }

#define A_TSTORE(buf, v)                                                      \
    do { (buf)[(ak4+0)*132+am] = (v).x; (buf)[(ak4+1)*132+am] = (v).y;        \
         (buf)[(ak4+2)*132+am] = (v).z; (buf)[(ak4+3)*132+am] = (v).w; } while(0)

// ---------------------------------------------------------------------------
// G1 folded: xh[2*mm+PAR][col] = sum_j Atab[mm][j] * Bmat[j][col]
// ---------------------------------------------------------------------------
template<int PAR>
__global__ __launch_bounds__(256, 2) void k_g1f() {
    const float* Atab = PAR ? d_Fs : d_Fc;
    const float* Bmat = PAR ? d_xo : d_xe;
    const int astr = PAR ? 128 : KEPAD;
    const int KT   = PAR ? 16 : 17;
    __shared__ float Ast[2][8 * 132];
    __shared__ float Bs [2][8 * 132];
    int t = threadIdx.x;
    int col0 = blockIdx.x * 128;
    int am = t >> 1, ak4 = (t & 1) * 4;
    int bk = t >> 5, bn4 = (t & 31) * 4;
    int tc = t & 15, tn = t >> 4;
    float4 av = *reinterpret_cast<const float4*>(&Atab[am * astr + ak4]);
    float4 bv = *reinterpret_cast<const float4*>(&Bmat[(size_t)bk * NROW + col0 + bn4]);
    A_TSTORE(Ast[0], av);
    *reinterpret_cast<float4*>(&Bs[0][bk * 132 + bn4]) = bv;
    __syncthreads();
    float acc[8][8] = {};
    for (int kt = 0; kt < KT; kt++) {
        int cur = kt & 1;
        bool more = (kt + 1 < KT);
        float4 an, bn_;
        if (more) {
            int k0 = (kt + 1) * 8;
            an  = *reinterpret_cast<const float4*>(&Atab[am * astr + k0 + ak4]);
            bn_ = *reinterpret_cast<const float4*>(&Bmat[(size_t)(k0 + bk) * NROW + col0 + bn4]);
        }
        GEMM_COMPUTE(Ast[cur], Bs[cur]);
        if (more) {
            A_TSTORE(Ast[cur ^ 1], an);
            *reinterpret_cast<float4*>(&Bs[cur ^ 1][bk * 132 + bn4]) = bn_;
            __syncthreads();
        }
    }
    #pragma unroll
    for (int ph = 0; ph < 2; ph++)
        #pragma unroll
        for (int e = 0; e < 4; e++) {
            int mm = ph * 64 + tn * 4 + e;
            float* dst = &d_xh[(size_t)(2 * mm + PAR) * NROW + col0];
            *reinterpret_cast<float4*>(dst + tc * 4) =
                make_float4(acc[ph*4+e][0], acc[ph*4+e][1], acc[ph*4+e][2], acc[ph*4+e][3]);
            *reinterpret_cast<float4*>(dst + tc * 4 + 64) =
                make_float4(acc[ph*4+e][4], acc[ph*4+e][5], acc[ph*4+e][6], acc[ph*4+e][7]);
        }
}

// ---------------------------------------------------------------------------
// G2 latitude-folded: per (mri): M=li (128: 64 E + 64 O), N=bc (128), K=k (128)
//   Be[k] = xh[k] + xh[255-k], Bo[k] = xh[k] - xh[255-k]  (built in smem)
//   rows li<64 (E) consume Be, rows li>=64 (O) consume Bo.
// grid (2, 256)
// ---------------------------------------------------------------------------
__global__ __launch_bounds__(256, 2) void k_g2f() {
    __shared__ float Ast[2][8 * 132];
    __shared__ float BeS[2][8 * 132];
    __shared__ float BoS[2][8 * 132];
    int t = threadIdx.x;
    int bc0 = blockIdx.x * 128;
    int mri = blockIdx.y;
    int m = mri >> 1, ri = mri & 1, par0 = m & 1;
    const float* A = d_PCTW2 + (size_t)m * 128 * 128;      // [li][k]
    const float* B = d_xh + (size_t)mri * NROW;            // [k*256+bc]
    int am = t >> 1, ak4 = (t & 1) * 4;
    int bk = t >> 5, bn4 = (t & 31) * 4;
    int tc = t & 15, tn = t >> 4;
    float4 av = *reinterpret_cast<const float4*>(&A[am * 128 + ak4]);
    float4 bt = *reinterpret_cast<const float4*>(&B[(size_t)bk * 256 + bc0 + bn4]);
    float4 bb = *reinterpret_cast<const float4*>(&B[(size_t)(255 - bk) * 256 + bc0 + bn4]);
    A_TSTORE(Ast[0], av);
    *reinterpret_cast<float4*>(&BeS[0][bk * 132 + bn4]) =
        make_float4(bt.x + bb.x, bt.y + bb.y, bt.z + bb.z, bt.w + bb.w);
    *reinterpret_cast<float4*>(&BoS[0][bk * 132 + bn4]) =
        make_float4(bt.x - bb.x, bt.y - bb.y, bt.z - bb.z, bt.w - bb.w);
    __syncthreads();
    float acc[8][8] = {};
    for (int kt = 0; kt < 16; kt++) {
        int cur = kt & 1;
        bool more = (kt + 1 < 16);
        float4 an, btn, bbn;
        if (more) {
            int k0 = (kt + 1) * 8;
            an  = *reinterpret_cast<const float4*>(&A[am * 128 + k0 + ak4]);
            btn = *reinterpret_cast<const float4*>(&B[(size_t)(k0 + bk) * 256 + bc0 + bn4]);
            bbn = *reinterpret_cast<const float4*>(&B[(size_t)(255 - k0 - bk) * 256 + bc0 + bn4]);
        }
        const float* Ap = Ast[cur];
        const float* Be = BeS[cur];
        const float* Bo = BoS[cur];
        #pragma unroll
        for (int j = 0; j < 8; j++) {
            // E half: rows tn*4 .. +3 against Be
            {
                float4 a0 = *reinterpret_cast<const float4*>(&Ap[j*132 + tn*4]);
                float4 b0 = *reinterpret_cast<const float4*>(&Be[j*132 + tc*4]);
                float4 b1 = *reinterpret_cast<const float4*>(&Be[j*132 + tc*4 + 64]);
                float ar[4] = {a0.x,a0.y,a0.z,a0.w};
                float br[8] = {b0.x,b0.y,b0.z,b0.w,b1.x,b1.y,b1.z,b1.w};
                #pragma unroll
                for (int p = 0; p < 4; p++)
                    #pragma unroll
                    for (int q = 0; q < 8; q++) acc[p][q] += ar[p] * br[q];
            }
            // O half: rows 64+tn*4 .. +3 against Bo
            {
                float4 a1 = *reinterpret_cast<const float4*>(&Ap[j*132 + tn*4 + 64]);
                float4 b0 = *reinterpret_cast<const float4*>(&Bo[j*132 + tc*4]);
                float4 b1 = *reinterpret_cast<const float4*>(&Bo[j*132 + tc*4 + 64]);
                float ar[4] = {a1.x,a1.y,a1.z,a1.w};
                float br[8] = {b0.x,b0.y,b0.z,b0.w,b1.x,b1.y,b1.z,b1.w};
                #pragma unroll
                for (int p = 0; p < 4; p++)
                    #pragma unroll
                    for (int q = 0; q < 8; q++) acc[4 + p][q] += ar[p] * br[q];
            }
        }
        if (more) {
            A_TSTORE(Ast[cur ^ 1], an);
            *reinterpret_cast<float4*>(&BeS[cur ^ 1][bk * 132 + bn4]) =
                make_float4(btn.x + bbn.x, btn.y + bbn.y, btn.z + bbn.z, btn.w + bbn.w);
            *reinterpret_cast<float4*>(&BoS[cur ^ 1][bk * 132 + bn4]) =
                make_float4(btn.x - bbn.x, btn.y - bbn.y, btn.z - bbn.z, btn.w - bbn.w);
            __syncthreads();
        }
    }
    #pragma unroll
    for (int ph = 0; ph < 2; ph++)
        #pragma unroll
        for (int e = 0; e < 4; e++) {
            int le = tn * 4 + e;
            int l = (ph == 0) ? (2 * le + par0) : (2 * le + 1 - par0);
            size_t xrow = ((size_t)l * 129 + m) * 2 + ri;
            float* dst = &d_spec[xrow * 256 + bc0];
            int p = ph * 4 + e;
            *reinterpret_cast<float4*>(dst + tc * 4) =
                make_float4(acc[p][0], acc[p][1], acc[p][2], acc[p][3]);
            *reinterpret_cast<float4*>(dst + tc * 4 + 64) =
                make_float4(acc[p][4], acc[p][5], acc[p][6], acc[p][7]);
        }
}

// ---------------------------------------------------------------------------
// G3: out2[x][b*32+o] = sum_i spec[x][b*32+i] * W[(i*32+o)*NX + x]
// ---------------------------------------------------------------------------
__global__ __launch_bounds__(256) void k_mix(const float* __restrict__ W) {
    __shared__ float Ws[8 * 1028];
    __shared__ float Ss[8 * 256];
    int t = threadIdx.x;
    int x0 = blockIdx.x * 8;
    #pragma unroll
    for (int rep = 0; rep < 32; rep++) {
        int idx = rep * 256 + t;
        int xl = idx & 7, io = idx >> 3;
        Ws[xl * 1028 + io] = W[(size_t)io * NX + x0 + xl];
    }
    #pragma unroll
    for (int rep = 0; rep < 8; rep++) {
        int idx = rep * 256 + t;
        int xl = idx >> 8, bc = idx & 255;
        Ss[xl * 256 + bc] = d_spec[(size_t)(x0 + xl) * 256 + bc];
    }
    __syncthreads();
    int b = t >> 5, o = t & 31;
    float acc[8] = {};
    #pragma unroll
    for (int xl = 0; xl < 8; xl++)
        #pragma unroll
        for (int i = 0; i < 32; i++)
            acc[xl] += Ss[xl * 256 + b * 32 + i] * Ws[xl * 1028 + i * 32 + o];
    #pragma unroll
    for (int xl = 0; xl < 8; xl++)
        d_out2[(size_t)(x0 + xl) * 256 + t] = acc[xl];
}

// ---------------------------------------------------------------------------
// G4 latitude-folded: per (mri): M=k<128 (128), N=bo (64), K=le (64) x2 parities
//   accE = sum_le PT[k][E(le)] out2[E(le)], accO likewise.
//   rr[k] = accE+accO ; rr[255-k] = accE-accO (fused unfold).
// grid (4, 256)
// ---------------------------------------------------------------------------
__global__ __launch_bounds__(256, 2) void k_g4f() {
    __shared__ float AeS[2][8 * 132];
    __shared__ float AoS[2][8 * 132];
    __shared__ float BeS[2][8 * 68];
    __shared__ float BoS[2][8 * 68];
    int t = threadIdx.x;
    int bo0 = blockIdx.x * 64;
    int mri = blockIdx.y;
    int m = mri >> 1, ri = mri & 1, par0 = m & 1;
    const float* A = d_PCTT2 + (size_t)m * 128 * 128;      // [k][li]
    int am = t >> 1, ak4 = (t & 1) * 4;
    int blr = (t & 127) >> 4, bn4 = (t & 15) * 4;          // B: row le, 64-wide bo
    int isBo = t >> 7;                                     // 0: Be loader, 1: Bo loader
    int tc = t & 15, tn = t >> 4;
    // initial tile (l0 = 0)
    float4 ave = *reinterpret_cast<const float4*>(&A[am * 128 + ak4]);
    float4 avo = *reinterpret_cast<const float4*>(&A[am * 128 + 64 + ak4]);
    float4 bv;
    {
        int l = 2 * blr + (isBo ? (1 - par0) : par0);
        size_t xrow = ((size_t)l * 129 + m) * 2 + ri;
        bv = *reinterpret_cast<const float4*>(&d_out2[xrow * 256 + bo0 + bn4]);
    }
    A_TSTORE(AeS[0], ave);
    { float* buf = AoS[0];
      buf[(ak4+0)*132+am] = avo.x; buf[(ak4+1)*132+am] = avo.y;
      buf[(ak4+2)*132+am] = avo.z; buf[(ak4+3)*132+am] = avo.w; }
    if (isBo) *reinterpret_cast<float4*>(&BoS[0][blr * 68 + bn4]) = bv;
    else      *reinterpret_cast<float4*>(&BeS[0][blr * 68 + bn4]) = bv;
    __syncthreads();
    float accE[8][4] = {};
    float accO[8][4] = {};
    for (int lt = 0; lt < 8; lt++) {
        int cur = lt & 1;
        bool more = (lt + 1 < 8);
        float4 ane, ano, bn_;
        if (more) {
            int l0 = (lt + 1) * 8;
            ane = *reinterpret_cast<const float4*>(&A[am * 128 + l0 + ak4]);
            ano = *reinterpret_cast<const float4*>(&A[am * 128 + 64 + l0 + ak4]);
            int l = 2 * (l0 + blr) + (isBo ? (1 - par0) : par0);
            size_t xrow = ((size_t)l * 129 + m) * 2 + ri;
            bn_ = *reinterpret_cast<const float4*>(&d_out2[xrow * 256 + bo0 + bn4]);
        }
        const float* Ae = AeS[cur]; const float* Ao = AoS[cur];
        const float* Be = BeS[cur]; const float* Bo = BoS[cur];
        #pragma unroll
        for (int j = 0; j < 8; j++) {
            float4 e0 = *reinterpret_cast<const float4*>(&Ae[j*132 + tn*4]);
            float4 e1 = *reinterpret_cast<const float4*>(&Ae[j*132 + tn*4 + 64]);
            float4 o0 = *reinterpret_cast<const float4*>(&Ao[j*132 + tn*4]);
            float4 o1 = *reinterpret_cast<const float4*>(&Ao[j*132 + tn*4 + 64]);
            float4 be = *reinterpret_cast<const float4*>(&Be[j*68 + tc*4]);
            float4 bo = *reinterpret_cast<const float4*>(&Bo[j*68 + tc*4]);
            float ae[8] = {e0.x,e0.y,e0.z,e0.w,e1.x,e1.y,e1.z,e1.w};
            float ao[8] = {o0.x,o0.y,o0.z,o0.w,o1.x,o1.y,o1.z,o1.w};
            float bre[4] = {be.x,be.y,be.z,be.w};
            float bro[4] = {bo.x,bo.y,bo.z,bo.w};
            #pragma unroll
            for (int p = 0; p < 8; p++)
                #pragma unroll
                for (int q = 0; q < 4; q++) {
                    accE[p][q] += ae[p] * bre[q];
                    accO[p][q] += ao[p] * bro[q];
                }
        }
        if (more) {
            A_TSTORE(AeS[cur ^ 1], ane);
            { float* buf = AoS[cur ^ 1];
              buf[(ak4+0)*132+am] = ano.x; buf[(ak4+1)*132+am] = ano.y;
              buf[(ak4+2)*132+am] = ano.z; buf[(ak4+3)*132+am] = ano.w; }
            if (isBo) *reinterpret_cast<float4*>(&BoS[cur ^ 1][blr * 68 + bn4]) = bn_;
            else      *reinterpret_cast<float4*>(&BeS[cur ^ 1][blr * 68 + bn4]) = bn_;
            __syncthreads();
        }
    }
    #pragma unroll
    for (int ph = 0; ph < 2; ph++)
        #pragma unroll
        for (int e = 0; e < 4; e++) {
            int p = ph * 4 + e;
            int k = ph * 64 + tn * 4 + e;                  // k < 128
            float* base = &d_rr[(size_t)mri * NROW];
            *reinterpret_cast<float4*>(base + (size_t)k * 256 + bo0 + tc * 4) =
                make_float4(accE[p][0] + accO[p][0], accE[p][1] + accO[p][1],
                            accE[p][2] + accO[p][2], accE[p][3] + accO[p][3]);
            *reinterpret_cast<float4*>(base + (size_t)(255 - k) * 256 + bo0 + tc * 4) =
                make_float4(accE[p][0] - accO[p][0], accE[p][1] - accO[p][1],
                            accE[p][2] - accO[p][2], accE[p][3] - accO[p][3]);
        }
}

// ---------------------------------------------------------------------------
// G5 folded+fused: C[col][j]=sum_m Gc[m][j]*rr[2m][col], S likewise (Gs, rr odd)
// y[j] = C-S ; y[256-j] = C+S (j>=1). grid (512, 2)
// ---------------------------------------------------------------------------
__global__ __launch_bounds__(256, 2) void k_g5f(float* __restrict__ out) {
    __shared__ float AeS[2][8 * 132];
    __shared__ float AoS[2][8 * 132];
    __shared__ float BcS[2][8 * 68];
    __shared__ float BsS[2][8 * 68];
    int t = threadIdx.x;
    int col0 = blockIdx.x * 128;
    int j0   = blockIdx.y * 64;
    int ar = t >> 5, ac4 = (t & 31) * 4;
    int mr = (t & 127) >> 4, jc = t & 15;
    int tc = t & 15, tn = t >> 4;
    float4 ave = *reinterpret_cast<const float4*>(&d_rr[(size_t)(2 * ar) * NROW + col0 + ac4]);
    float4 avo = *reinterpret_cast<const float4*>(&d_rr[(size_t)(2 * ar + 1) * NROW + col0 + ac4]);
    float4 bvx;
    if (t < 128) bvx = *reinterpret_cast<const float4*>(&d_Gc[mr * 128 + j0 + jc * 4]);
    else         bvx = *reinterpret_cast<const float4*>(&d_Gs[mr * 128 + j0 + jc * 4]);
    *reinterpret_cast<float4*>(&AeS[0][ar * 132 + ac4]) = ave;
    *reinterpret_cast<float4*>(&AoS[0][ar * 132 + ac4]) = avo;
    if (t < 128) *reinterpret_cast<float4*>(&BcS[0][mr * 68 + jc * 4]) = bvx;
    else         *reinterpret_cast<float4*>(&BsS[0][mr * 68 + jc * 4]) = bvx;
    __syncthreads();
    float accC[8][4] = {};
    float accS[8][4] = {};
    for (int kt = 0; kt < 16; kt++) {
        int cur = kt & 1;
        bool more = (kt + 1 < 16);
        float4 ane, ano, bn_;
        if (more) {
            int m0 = (kt + 1) * 8;
            ane = *reinterpret_cast<const float4*>(&d_rr[(size_t)(2 * (m0 + ar)) * NROW + col0 + ac4]);
            ano = *reinterpret_cast<const float4*>(&d_rr[(size_t)(2 * (m0 + ar) + 1) * NROW + col0 + ac4]);
            if (t < 128) bn_ = *reinterpret_cast<const float4*>(&d_Gc[(m0 + mr) * 128 + j0 + jc * 4]);
            else         bn_ = *reinterpret_cast<const float4*>(&d_Gs[(m0 + mr) * 128 + j0 + jc * 4]);
        }
        const float* Ae = AeS[cur]; const float* Ao = AoS[cur];
        const float* Bc = BcS[cur]; const float* Bss = BsS[cur];
        #pragma unroll
        for (int j = 0; j < 8; j++) {
            float4 e0 = *reinterpret_cast<const float4*>(&Ae[j * 132 + tn * 4]);
            float4 e1 = *reinterpret_cast<const float4*>(&Ae[j * 132 + tn * 4 + 64]);
            float4 o0 = *reinterpret_cast<const float4*>(&Ao[j * 132 + tn * 4]);
            float4 o1 = *reinterpret_cast<const float4*>(&Ao[j * 132 + tn * 4 + 64]);
            float4 cc = *reinterpret_cast<const float4*>(&Bc[j * 68 + tc * 4]);
            float4 ss = *reinterpret_cast<const float4*>(&Bss[j * 68 + tc * 4]);
            float ae[8] = {e0.x,e0.y,e0.z,e0.w,e1.x,e1.y,e1.z,e1.w};
            float ao[8] = {o0.x,o0.y,o0.z,o0.w,o1.x,o1.y,o1.z,o1.w};
            float bc_[4] = {cc.x,cc.y,cc.z,cc.w};
            float bs_[4] = {ss.x,ss.y,ss.z,ss.w};
            #pragma unroll
            for (int p = 0; p < 8; p++)
                #pragma unroll
                for (int q = 0; q < 4; q++) {
                    accC[p][q] += ae[p] * bc_[q];
                    accS[p][q] += ao[p] * bs_[q];
                }
        }
        if (more) {
            *reinterpret_cast<float4*>(&AeS[cur ^ 1][ar * 132 + ac4]) = ane;
            *reinterpret_cast<float4*>(&AoS[cur ^ 1][ar * 132 + ac4]) = ano;
            if (t < 128) *reinterpret_cast<float4*>(&BcS[cur ^ 1][mr * 68 + jc * 4]) = bn_;
            else         *reinterpret_cast<float4*>(&BsS[cur ^ 1][mr * 68 + jc * 4]) = bn_;
            __syncthreads();
        }
    }
    int jj0 = j0 + tc * 4;
    #pragma unroll
    for (int ph = 0; ph < 2; ph++)
        #pragma unroll
        for (int e = 0; e < 4; e++) {
            int p = ph * 4 + e;
            int col = col0 + ph * 64 + tn * 4 + e;
            int bo = col & 255, k = col >> 8;
            float* base = &out[(size_t)bo * 65536 + (size_t)k * 256];
            *reinterpret_cast<float4*>(base + jj0) =
                make_float4(accC[p][0] - accS[p][0], accC[p][1] - accS[p][1],
                            accC[p][2] - accS[p][2], accC[p][3] - accS[p][3]);
            #pragma unroll
            for (int q = 0; q < 4; q++) {
                int jj = jj0 + q;
                if (jj > 0) base[256 - jj] = accC[p][q] + accS[p][q];
            }
        }
}

// ---------------------------------------------------------------------------
// y[128] column: out[bo][k][128] = sum_m wm*(-1)^m * rr[2m][col]
// ---------------------------------------------------------------------------
__global__ __launch_bounds__(256) void k_y128(float* __restrict__ out) {
    int col = blockIdx.x * 256 + threadIdx.x;
    float acc = 0.f;
    #pragma unroll
    for (int m = 0; m < 128; m++) {
        float g = (m == 0) ? 1.f : ((m & 1) ? -2.f : 2.f);
        acc += g * d_rr[(size_t)(2 * m) * NROW + col];
    }
    int bo = col & 255, k = col >> 8;
    out[(size_t)bo * 65536 + (size_t)k * 256 + 128] = acc;
}

// ---------------------------------------------------------------------------
extern "C" void kernel_launch(void* const* d_in, const int* in_sizes, int n_in,
                              void* d_out, int out_size) {
    const float* x = (const float*)d_in[0];
    const float* w = (const float*)d_in[1];
    float* out = (float*)d_out;

    k_quad<<<256, 128>>>();
    k_four2<<<128, 256>>>();
    k_legendre<<<128, 128>>>();

    k_fold<<<2048, 256>>>(x);
    k_g1f<0><<<512, 256>>>();      // Re rows (n=2m), K=136
    k_g1f<1><<<512, 256>>>();      // Im rows (n=2m+1), K=128
    dim3 g2(2, 256);   k_g2f<<<g2, 256>>>();
    k_mix<<<NX / 8, 256>>>(w);
    dim3 g4(4, 256);   k_g4f<<<g4, 256>>>();
    dim3 g5(512, 2);   k_g5f<<<g5, 256>>>(out);
    k_y128<<<256, 256>>>(out);
}

// round 10
// speedup vs baseline: 1.7811x; 1.0150x over previous
#include <cuda_runtime.h>
#include <math.h>

#define NLAT  256
#define NLON  256
#define LMAX  128
#define MMAX  129
#define NM    256           // effective 2*128 (m=128 plane identically zero)
#define NX    33024         // 2*LMAX*MMAX
#define BCH   256           // BATCH*CIN = BATCH*COUT
#define NROW  65536         // BCH*NLAT
#define KEPAD 136           // padded K for cos GEMM (valid j = 0..128)

typedef unsigned long long u64;
__device__ __forceinline__ u64 pk2(float x, float y) {
    u64 r; asm("mov.b64 %0, {%1, %2};" : "=l"(r) : "f"(x), "f"(y)); return r;
}
__device__ __forceinline__ u64 dup2(float x) { return pk2(x, x); }
__device__ __forceinline__ void fma2(u64 &d, u64 a, u64 b) {
    asm("fma.rn.f32x2 %0, %1, %2, %3;" : "=l"(d) : "l"(a), "l"(b), "l"(d));
}
__device__ __forceinline__ float2 un2(u64 v) {
    float2 f; asm("mov.b64 {%0, %1}, %2;" : "=f"(f.x), "=f"(f.y) : "l"(v)); return f;
}

// ---------------------------------------------------------------------------
// Static device scratch (no allocations; zero-initialized at load)
// ---------------------------------------------------------------------------
__device__ float d_wq[NLAT];
__device__ float d_Fc[LMAX * KEPAD];                   // [m][j] sc*cos, j<=128, else 0
__device__ float d_Fs[LMAX * 128];                     // [m][j] -sc*sin
__device__ float d_Gc[LMAX * 128];                     // [m][j] wm*cos
__device__ float d_Gs[LMAX * 128];                     // [m][j] wm*sin
// latitude-parity stacked Legendre tables, k < 128 only.
// li = ((l+m)&1)*64 + (l>>1)
__device__ float d_PCTW2[(size_t)LMAX * 128 * 128];    // [m][li][k]  (P*w)
__device__ float d_PCTT2[(size_t)LMAX * 128 * 128];    // [m][k][li]  (P)
__device__ float d_xe  [(size_t)KEPAD * NROW];         // folded even, rows 129..135 stay 0
__device__ float d_xo  [(size_t)128 * NROW];           // folded odd
__device__ float d_xh  [(size_t)NM * NROW];            // [n=2m+ri][k*256+bc]
__device__ float d_spec[(size_t)NX * BCH];             // (m=128 rows stay 0)
__device__ float d_out2[(size_t)NX * BCH];
__device__ float d_rr  [(size_t)NM * NROW];            // [n][k*256+bo]

// ---------------------------------------------------------------------------
// Clenshaw-Curtis quadrature weights
// ---------------------------------------------------------------------------
__global__ __launch_bounds__(128) void k_quad() {
    int j = blockIdx.x;
    int k = threadIdx.x;
    double tj = M_PI * (double)j / 255.0;
    double v = 0.0;
    if (k >= 1) v = cos(2.0 * tj * (double)k) * (2.0 / (4.0 * (double)k * k - 1.0));
    __shared__ double red[128];
    red[k] = v;
    __syncthreads();
    for (int s = 64; s > 0; s >>= 1) {
        if (k < s) red[k] += red[k + s];
        __syncthreads();
    }
    if (k == 0) {
        double c = (j == 0 || j == 255) ? 1.0 : 2.0;
        d_wq[j] = (float)(c / 255.0 * (1.0 - red[0]));
    }
}

// ---------------------------------------------------------------------------
// Fourier tables (exact mod-256 phase reduction)
// ---------------------------------------------------------------------------
__global__ __launch_bounds__(256) void k_four2() {
    int m = blockIdx.x;                  // 0..127
    int j = threadIdx.x;                 // 0..255
    int r = (m * j) & 255;
    float s, c;
    sincosf((float)(2.0 * M_PI / 256.0 * (double)r), &s, &c);
    const float sc = (float)(2.0 * M_PI / 256.0);
    if (j < KEPAD) d_Fc[m * KEPAD + j] = (j <= 128) ? sc * c : 0.f;
    if (j < 128) {
        d_Fs[m * 128 + j] = -sc * s;
        float wm = (m == 0) ? 1.f : 2.f;
        d_Gc[m * 128 + j] = wm * c;
        d_Gs[m * 128 + j] = wm * s;
    }
}

// ---------------------------------------------------------------------------
// Legendre tables, parity-stacked, nodes k<128 (double precision recurrence)
// ---------------------------------------------------------------------------
__global__ __launch_bounds__(128) void k_legendre() {
    int m  = blockIdx.x;                 // 0..127
    int kk = threadIdx.x;                // 0..127
    __shared__ double s_a[LMAX], s_b[LMAX];
    __shared__ double s_sect;
    {
        int l = kk;
        if (l >= m + 2) {
            double fl = (double)l, fm = (double)m, g = fl - 1.0;
            s_a[l] = sqrt((4.0 * fl * fl - 1.0) / (fl * fl - fm * fm));
            s_b[l] = sqrt((g * g - fm * fm) / (4.0 * g * g - 1.0));
        }
    }
    if (kk == 0) {
        double pr = 1.0;
        for (int i = 1; i <= m; i++) pr *= (2.0 * i + 1.0) / (2.0 * i);
        s_sect = sqrt(pr);
    }
    __syncthreads();
    double tt = M_PI * (double)kk / 255.0;
    double ct = cos(tt), st = sin(tt);
    double w  = (double)d_wq[kk];
    size_t baseW = (size_t)m * 128 * 128;
    size_t baseT = (size_t)m * 128 * 128 + (size_t)kk * 128;
    for (int l = 0; l < m; l++) {
        int li = (((l + m) & 1) << 6) | (l >> 1);
        d_PCTW2[baseW + (size_t)li * 128 + kk] = 0.f;
        d_PCTT2[baseT + li] = 0.f;
    }
    double powv = 1.0;
    for (int i = 0; i < m; i++) powv *= -st;
    double p2 = 0.28209479177387814347 * s_sect * powv;   // p[m][m], parity even
    {
        int li = (m >> 1);
        d_PCTW2[baseW + (size_t)li * 128 + kk] = (float)(p2 * w);
        d_PCTT2[baseT + li] = (float)p2;
    }
    if (m + 1 < LMAX) {
        double p1 = sqrt(2.0 * m + 3.0) * ct * p2;
        {
            int li = 64 + ((m + 1) >> 1);
            d_PCTW2[baseW + (size_t)li * 128 + kk] = (float)(p1 * w);
            d_PCTT2[baseT + li] = (float)p1;
        }
        for (int l = m + 2; l < LMAX; l++) {
            double p = s_a[l] * (ct * p1 - s_b[l] * p2);
            int li = (((l + m) & 1) << 6) | (l >> 1);
            d_PCTW2[baseW + (size_t)li * 128 + kk] = (float)(p * w);
            d_PCTT2[baseT + li] = (float)p;
            p2 = p1; p1 = p;
        }
    }
}

// ---------------------------------------------------------------------------
// Fold (longitude): xe[j]=x[j]+x[256-j], xo[j]=x[j]-x[256-j]
// ---------------------------------------------------------------------------
__global__ __launch_bounds__(256) void k_fold(const float* __restrict__ x) {
    __shared__ float s[32][257];
    int t = threadIdx.x;
    int col0 = blockIdx.x * 32;
    int klat = col0 >> 8;
    int bc0  = col0 & 255;
    #pragma unroll 4
    for (int r = 0; r < 32; r++)
        s[r][t] = x[(size_t)(bc0 + r) * 65536 + klat * 256 + t];
    __syncthreads();
    #pragma unroll 4
    for (int it = 0; it < 16; it++) {
        int idx = it * 256 + t;
        int j = idx >> 5, c = idx & 31;
        float a = s[c][j];
        float b = s[c][(256 - j) & 255];
        float xe = (j == 0) ? a : a + b;
        float xo = (j == 0) ? 0.f : a - b;
        d_xe[(size_t)j * NROW + col0 + c] = xe;
        d_xo[(size_t)j * NROW + col0 + c] = xo;
    }
    if (t < 32) d_xe[(size_t)128 * NROW + col0 + t] = s[t][128];
}

// ===========================================================================
// GEMM helpers (f32x2 packed-FMA cores)
// ===========================================================================
#define A_TSTORE(buf, v)                                                      \
    do { (buf)[(ak4+0)*132+am] = (v).x; (buf)[(ak4+1)*132+am] = (v).y;        \
         (buf)[(ak4+2)*132+am] = (v).z; (buf)[(ak4+3)*132+am] = (v).w; } while(0)

// full 8x8 (8 rows from Ap, 8 cols = tc*4 & tc*4+64 from Bp), acc2[8][4]
#define GEMM_COMPUTE2(Ap, Bp)                                                 \
    _Pragma("unroll")                                                         \
    for (int j = 0; j < 8; j++) {                                             \
        float4 a0 = *reinterpret_cast<const float4*>(&(Ap)[j*132 + tn*4]);    \
        float4 a1 = *reinterpret_cast<const float4*>(&(Ap)[j*132 + tn*4 + 64]);\
        float4 b0 = *reinterpret_cast<const float4*>(&(Bp)[j*132 + tc*4]);    \
        float4 b1 = *reinterpret_cast<const float4*>(&(Bp)[j*132 + tc*4 + 64]);\
        u64 bb[4] = {pk2(b0.x,b0.y), pk2(b0.z,b0.w), pk2(b1.x,b1.y), pk2(b1.z,b1.w)}; \
        float ar[8] = {a0.x,a0.y,a0.z,a0.w,a1.x,a1.y,a1.z,a1.w};              \
        _Pragma("unroll")                                                     \
        for (int p = 0; p < 8; p++) {                                         \
            u64 aa = dup2(ar[p]);                                             \
            _Pragma("unroll")                                                 \
            for (int q = 0; q < 4; q++) fma2(acc2[p][q], aa, bb[q]);          \
        }                                                                     \
    }

// ---------------------------------------------------------------------------
// G1 folded: xh[2*mm+PAR][col] = sum_j Atab[mm][j] * Bmat[j][col]
// ---------------------------------------------------------------------------
template<int PAR>
__global__ __launch_bounds__(256, 2) void k_g1f() {
    const float* Atab = PAR ? d_Fs : d_Fc;
    const float* Bmat = PAR ? d_xo : d_xe;
    const int astr = PAR ? 128 : KEPAD;
    const int KT   = PAR ? 16 : 17;
    __shared__ float Ast[2][8 * 132];
    __shared__ float Bs [2][8 * 132];
    int t = threadIdx.x;
    int col0 = blockIdx.x * 128;
    int am = t >> 1, ak4 = (t & 1) * 4;
    int bk = t >> 5, bn4 = (t & 31) * 4;
    int tc = t & 15, tn = t >> 4;
    float4 av = *reinterpret_cast<const float4*>(&Atab[am * astr + ak4]);
    float4 bv = *reinterpret_cast<const float4*>(&Bmat[(size_t)bk * NROW + col0 + bn4]);
    A_TSTORE(Ast[0], av);
    *reinterpret_cast<float4*>(&Bs[0][bk * 132 + bn4]) = bv;
    __syncthreads();
    u64 acc2[8][4] = {};
    for (int kt = 0; kt < KT; kt++) {
        int cur = kt & 1;
        bool more = (kt + 1 < KT);
        float4 an, bn_;
        if (more) {
            int k0 = (kt + 1) * 8;
            an  = *reinterpret_cast<const float4*>(&Atab[am * astr + k0 + ak4]);
            bn_ = *reinterpret_cast<const float4*>(&Bmat[(size_t)(k0 + bk) * NROW + col0 + bn4]);
        }
        GEMM_COMPUTE2(Ast[cur], Bs[cur]);
        if (more) {
            A_TSTORE(Ast[cur ^ 1], an);
            *reinterpret_cast<float4*>(&Bs[cur ^ 1][bk * 132 + bn4]) = bn_;
            __syncthreads();
        }
    }
    #pragma unroll
    for (int ph = 0; ph < 2; ph++)
        #pragma unroll
        for (int e = 0; e < 4; e++) {
            int p = ph * 4 + e;
            int mm = ph * 64 + tn * 4 + e;
            float2 c0 = un2(acc2[p][0]), c1 = un2(acc2[p][1]);
            float2 c2 = un2(acc2[p][2]), c3 = un2(acc2[p][3]);
            float* dst = &d_xh[(size_t)(2 * mm + PAR) * NROW + col0];
            *reinterpret_cast<float4*>(dst + tc * 4)      = make_float4(c0.x, c0.y, c1.x, c1.y);
            *reinterpret_cast<float4*>(dst + tc * 4 + 64) = make_float4(c2.x, c2.y, c3.x, c3.y);
        }
}

// ---------------------------------------------------------------------------
// G2 latitude-folded: per (mri): M=li (128: 64 E + 64 O), N=bc (128), K=k (128)
// grid (2, 256)
// ---------------------------------------------------------------------------
__global__ __launch_bounds__(256, 2) void k_g2f() {
    __shared__ float Ast[2][8 * 132];
    __shared__ float BeS[2][8 * 132];
    __shared__ float BoS[2][8 * 132];
    int t = threadIdx.x;
    int bc0 = blockIdx.x * 128;
    int mri = blockIdx.y;
    int m = mri >> 1, ri = mri & 1, par0 = m & 1;
    const float* A = d_PCTW2 + (size_t)m * 128 * 128;      // [li][k]
    const float* B = d_xh + (size_t)mri * NROW;            // [k*256+bc]
    int am = t >> 1, ak4 = (t & 1) * 4;
    int bk = t >> 5, bn4 = (t & 31) * 4;
    int tc = t & 15, tn = t >> 4;
    float4 av = *reinterpret_cast<const float4*>(&A[am * 128 + ak4]);
    float4 bt = *reinterpret_cast<const float4*>(&B[(size_t)bk * 256 + bc0 + bn4]);
    float4 bb = *reinterpret_cast<const float4*>(&B[(size_t)(255 - bk) * 256 + bc0 + bn4]);
    A_TSTORE(Ast[0], av);
    *reinterpret_cast<float4*>(&BeS[0][bk * 132 + bn4]) =
        make_float4(bt.x + bb.x, bt.y + bb.y, bt.z + bb.z, bt.w + bb.w);
    *reinterpret_cast<float4*>(&BoS[0][bk * 132 + bn4]) =
        make_float4(bt.x - bb.x, bt.y - bb.y, bt.z - bb.z, bt.w - bb.w);
    __syncthreads();
    u64 acc2[8][4] = {};
    for (int kt = 0; kt < 16; kt++) {
        int cur = kt & 1;
        bool more = (kt + 1 < 16);
        float4 an, btn, bbn;
        if (more) {
            int k0 = (kt + 1) * 8;
            an  = *reinterpret_cast<const float4*>(&A[am * 128 + k0 + ak4]);
            btn = *reinterpret_cast<const float4*>(&B[(size_t)(k0 + bk) * 256 + bc0 + bn4]);
            bbn = *reinterpret_cast<const float4*>(&B[(size_t)(255 - k0 - bk) * 256 + bc0 + bn4]);
        }
        const float* Ap = Ast[cur];
        const float* Be = BeS[cur];
        const float* Bo = BoS[cur];
        #pragma unroll
        for (int j = 0; j < 8; j++) {
            // E half: rows tn*4..+3 vs Be (8 cols)
            {
                float4 a0 = *reinterpret_cast<const float4*>(&Ap[j*132 + tn*4]);
                float4 b0 = *reinterpret_cast<const float4*>(&Be[j*132 + tc*4]);
                float4 b1 = *reinterpret_cast<const float4*>(&Be[j*132 + tc*4 + 64]);
                u64 bbv[4] = {pk2(b0.x,b0.y), pk2(b0.z,b0.w), pk2(b1.x,b1.y), pk2(b1.z,b1.w)};
                float ar[4] = {a0.x,a0.y,a0.z,a0.w};
                #pragma unroll
                for (int p = 0; p < 4; p++) {
                    u64 aa = dup2(ar[p]);
                    #pragma unroll
                    for (int q = 0; q < 4; q++) fma2(acc2[p][q], aa, bbv[q]);
                }
            }
            // O half: rows 64+tn*4..+3 vs Bo
            {
                float4 a1 = *reinterpret_cast<const float4*>(&Ap[j*132 + tn*4 + 64]);
                float4 b0 = *reinterpret_cast<const float4*>(&Bo[j*132 + tc*4]);
                float4 b1 = *reinterpret_cast<const float4*>(&Bo[j*132 + tc*4 + 64]);
                u64 bbv[4] = {pk2(b0.x,b0.y), pk2(b0.z,b0.w), pk2(b1.x,b1.y), pk2(b1.z,b1.w)};
                float ar[4] = {a1.x,a1.y,a1.z,a1.w};
                #pragma unroll
                for (int p = 0; p < 4; p++) {
                    u64 aa = dup2(ar[p]);
                    #pragma unroll
                    for (int q = 0; q < 4; q++) fma2(acc2[4 + p][q], aa, bbv[q]);
                }
            }
        }
        if (more) {
            A_TSTORE(Ast[cur ^ 1], an);
            *reinterpret_cast<float4*>(&BeS[cur ^ 1][bk * 132 + bn4]) =
                make_float4(btn.x + bbn.x, btn.y + bbn.y, btn.z + bbn.z, btn.w + bbn.w);
            *reinterpret_cast<float4*>(&BoS[cur ^ 1][bk * 132 + bn4]) =
                make_float4(btn.x - bbn.x, btn.y - bbn.y, btn.z - bbn.z, btn.w - bbn.w);
            __syncthreads();
        }
    }
    #pragma unroll
    for (int ph = 0; ph < 2; ph++)
        #pragma unroll
        for (int e = 0; e < 4; e++) {
            int le = tn * 4 + e;
            int l = (ph == 0) ? (2 * le + par0) : (2 * le + 1 - par0);
            size_t xrow = ((size_t)l * 129 + m) * 2 + ri;
            int p = ph * 4 + e;
            float2 c0 = un2(acc2[p][0]), c1 = un2(acc2[p][1]);
            float2 c2 = un2(acc2[p][2]), c3 = un2(acc2[p][3]);
            float* dst = &d_spec[xrow * 256 + bc0];
            *reinterpret_cast<float4*>(dst + tc * 4)      = make_float4(c0.x, c0.y, c1.x, c1.y);
            *reinterpret_cast<float4*>(dst + tc * 4 + 64) = make_float4(c2.x, c2.y, c3.x, c3.y);
        }
}

// ---------------------------------------------------------------------------
// G3: out2[x][b*32+o] = sum_i spec[x][b*32+i] * W[(i*32+o)*NX + x]
// ---------------------------------------------------------------------------
__global__ __launch_bounds__(256) void k_mix(const float* __restrict__ W) {
    __shared__ float Ws[8 * 1028];
    __shared__ float Ss[8 * 256];
    int t = threadIdx.x;
    int x0 = blockIdx.x * 8;
    #pragma unroll
    for (int rep = 0; rep < 32; rep++) {
        int idx = rep * 256 + t;
        int xl = idx & 7, io = idx >> 3;
        Ws[xl * 1028 + io] = W[(size_t)io * NX + x0 + xl];
    }
    #pragma unroll
    for (int rep = 0; rep < 8; rep++) {
        int idx = rep * 256 + t;
        int xl = idx >> 8, bc = idx & 255;
        Ss[xl * 256 + bc] = d_spec[(size_t)(x0 + xl) * 256 + bc];
    }
    __syncthreads();
    int b = t >> 5, o = t & 31;
    float acc[8] = {};
    #pragma unroll
    for (int xl = 0; xl < 8; xl++)
        #pragma unroll
        for (int i = 0; i < 32; i++)
            acc[xl] += Ss[xl * 256 + b * 32 + i] * Ws[xl * 1028 + i * 32 + o];
    #pragma unroll
    for (int xl = 0; xl < 8; xl++)
        d_out2[(size_t)(x0 + xl) * 256 + t] = acc[xl];
}

// ---------------------------------------------------------------------------
// G4 latitude-folded: per (mri): M=k<128 (128), N=bo (64), K=le (64) x2 parities
//   rr[k] = accE+accO ; rr[255-k] = accE-accO (fused unfold). grid (4, 256)
// ---------------------------------------------------------------------------
__global__ __launch_bounds__(256, 2) void k_g4f() {
    __shared__ float AeS[2][8 * 132];
    __shared__ float AoS[2][8 * 132];
    __shared__ float BeS[2][8 * 68];
    __shared__ float BoS[2][8 * 68];
    int t = threadIdx.x;
    int bo0 = blockIdx.x * 64;
    int mri = blockIdx.y;
    int m = mri >> 1, ri = mri & 1, par0 = m & 1;
    const float* A = d_PCTT2 + (size_t)m * 128 * 128;      // [k][li]
    int am = t >> 1, ak4 = (t & 1) * 4;
    int blr = (t & 127) >> 4, bn4 = (t & 15) * 4;
    int isBo = t >> 7;
    int tc = t & 15, tn = t >> 4;
    float4 ave = *reinterpret_cast<const float4*>(&A[am * 128 + ak4]);
    float4 avo = *reinterpret_cast<const float4*>(&A[am * 128 + 64 + ak4]);
    float4 bv;
    {
        int l = 2 * blr + (isBo ? (1 - par0) : par0);
        size_t xrow = ((size_t)l * 129 + m) * 2 + ri;
        bv = *reinterpret_cast<const float4*>(&d_out2[xrow * 256 + bo0 + bn4]);
    }
    A_TSTORE(AeS[0], ave);
    { float* buf = AoS[0];
      buf[(ak4+0)*132+am] = avo.x; buf[(ak4+1)*132+am] = avo.y;
      buf[(ak4+2)*132+am] = avo.z; buf[(ak4+3)*132+am] = avo.w; }
    if (isBo) *reinterpret_cast<float4*>(&BoS[0][blr * 68 + bn4]) = bv;
    else      *reinterpret_cast<float4*>(&BeS[0][blr * 68 + bn4]) = bv;
    __syncthreads();
    u64 acc2E[8][2] = {};
    u64 acc2O[8][2] = {};
    for (int lt = 0; lt < 8; lt++) {
        int cur = lt & 1;
        bool more = (lt + 1 < 8);
        float4 ane, ano, bn_;
        if (more) {
            int l0 = (lt + 1) * 8;
            ane = *reinterpret_cast<const float4*>(&A[am * 128 + l0 + ak4]);
            ano = *reinterpret_cast<const float4*>(&A[am * 128 + 64 + l0 + ak4]);
            int l = 2 * (l0 + blr) + (isBo ? (1 - par0) : par0);
            size_t xrow = ((size_t)l * 129 + m) * 2 + ri;
            bn_ = *reinterpret_cast<const float4*>(&d_out2[xrow * 256 + bo0 + bn4]);
        }
        const float* Ae = AeS[cur]; const float* Ao = AoS[cur];
        const float* Be = BeS[cur]; const float* Bo = BoS[cur];
        #pragma unroll
        for (int j = 0; j < 8; j++) {
            float4 e0 = *reinterpret_cast<const float4*>(&Ae[j*132 + tn*4]);
            float4 e1 = *reinterpret_cast<const float4*>(&Ae[j*132 + tn*4 + 64]);
            float4 o0 = *reinterpret_cast<const float4*>(&Ao[j*132 + tn*4]);
            float4 o1 = *reinterpret_cast<const float4*>(&Ao[j*132 + tn*4 + 64]);
            float4 be = *reinterpret_cast<const float4*>(&Be[j*68 + tc*4]);
            float4 bo = *reinterpret_cast<const float4*>(&Bo[j*68 + tc*4]);
            u64 bbe[2] = {pk2(be.x,be.y), pk2(be.z,be.w)};
            u64 bbo[2] = {pk2(bo.x,bo.y), pk2(bo.z,bo.w)};
            float ae[8] = {e0.x,e0.y,e0.z,e0.w,e1.x,e1.y,e1.z,e1.w};
            float ao[8] = {o0.x,o0.y,o0.z,o0.w,o1.x,o1.y,o1.z,o1.w};
            #pragma unroll
            for (int p = 0; p < 8; p++) {
                u64 aaE = dup2(ae[p]);
                fma2(acc2E[p][0], aaE, bbe[0]);
                fma2(acc2E[p][1], aaE, bbe[1]);
                u64 aaO = dup2(ao[p]);
                fma2(acc2O[p][0], aaO, bbo[0]);
                fma2(acc2O[p][1], aaO, bbo[1]);
            }
        }
        if (more) {
            A_TSTORE(AeS[cur ^ 1], ane);
            { float* buf = AoS[cur ^ 1];
              buf[(ak4+0)*132+am] = ano.x; buf[(ak4+1)*132+am] = ano.y;
              buf[(ak4+2)*132+am] = ano.z; buf[(ak4+3)*132+am] = ano.w; }
            if (isBo) *reinterpret_cast<float4*>(&BoS[cur ^ 1][blr * 68 + bn4]) = bn_;
            else      *reinterpret_cast<float4*>(&BeS[cur ^ 1][blr * 68 + bn4]) = bn_;
            __syncthreads();
        }
    }
    #pragma unroll
    for (int ph = 0; ph < 2; ph++)
        #pragma unroll
        for (int e = 0; e < 4; e++) {
            int p = ph * 4 + e;
            int k = ph * 64 + tn * 4 + e;                  // k < 128
            float2 E0 = un2(acc2E[p][0]), E1 = un2(acc2E[p][1]);
            float2 O0 = un2(acc2O[p][0]), O1 = un2(acc2O[p][1]);
            float* base = &d_rr[(size_t)mri * NROW];
            *reinterpret_cast<float4*>(base + (size_t)k * 256 + bo0 + tc * 4) =
                make_float4(E0.x + O0.x, E0.y + O0.y, E1.x + O1.x, E1.y + O1.y);
            *reinterpret_cast<float4*>(base + (size_t)(255 - k) * 256 + bo0 + tc * 4) =
                make_float4(E0.x - O0.x, E0.y - O0.y, E1.x - O1.x, E1.y - O1.y);
        }
}

// ---------------------------------------------------------------------------
// G5 folded+fused: C[col][j]=sum_m Gc[m][j]*rr[2m][col], S likewise (Gs, rr odd)
// y[j] = C-S ; y[256-j] = C+S (j>=1). grid (512, 2)
// ---------------------------------------------------------------------------
__global__ __launch_bounds__(256, 2) void k_g5f(float* __restrict__ out) {
    __shared__ float AeS[2][8 * 132];
    __shared__ float AoS[2][8 * 132];
    __shared__ float BcS[2][8 * 68];
    __shared__ float BsS[2][8 * 68];
    int t = threadIdx.x;
    int col0 = blockIdx.x * 128;
    int j0   = blockIdx.y * 64;
    int ar = t >> 5, ac4 = (t & 31) * 4;
    int mr = (t & 127) >> 4, jc = t & 15;
    int tc = t & 15, tn = t >> 4;
    float4 ave = *reinterpret_cast<const float4*>(&d_rr[(size_t)(2 * ar) * NROW + col0 + ac4]);
    float4 avo = *reinterpret_cast<const float4*>(&d_rr[(size_t)(2 * ar + 1) * NROW + col0 + ac4]);
    float4 bvx;
    if (t < 128) bvx = *reinterpret_cast<const float4*>(&d_Gc[mr * 128 + j0 + jc * 4]);
    else         bvx = *reinterpret_cast<const float4*>(&d_Gs[mr * 128 + j0 + jc * 4]);
    *reinterpret_cast<float4*>(&AeS[0][ar * 132 + ac4]) = ave;
    *reinterpret_cast<float4*>(&AoS[0][ar * 132 + ac4]) = avo;
    if (t < 128) *reinterpret_cast<float4*>(&BcS[0][mr * 68 + jc * 4]) = bvx;
    else         *reinterpret_cast<float4*>(&BsS[0][mr * 68 + jc * 4]) = bvx;
    __syncthreads();
    u64 acc2C[8][2] = {};
    u64 acc2S[8][2] = {};
    for (int kt = 0; kt < 16; kt++) {
        int cur = kt & 1;
        bool more = (kt + 1 < 16);
        float4 ane, ano, bn_;
        if (more) {
            int m0 = (kt + 1) * 8;
            ane = *reinterpret_cast<const float4*>(&d_rr[(size_t)(2 * (m0 + ar)) * NROW + col0 + ac4]);
            ano = *reinterpret_cast<const float4*>(&d_rr[(size_t)(2 * (m0 + ar) + 1) * NROW + col0 + ac4]);
            if (t < 128) bn_ = *reinterpret_cast<const float4*>(&d_Gc[(m0 + mr) * 128 + j0 + jc * 4]);
            else         bn_ = *reinterpret_cast<const float4*>(&d_Gs[(m0 + mr) * 128 + j0 + jc * 4]);
        }
        const float* Ae = AeS[cur]; const float* Ao = AoS[cur];
        const float* Bc = BcS[cur]; const float* Bss = BsS[cur];
        #pragma unroll
        for (int j = 0; j < 8; j++) {
            float4 e0 = *reinterpret_cast<const float4*>(&Ae[j * 132 + tn * 4]);
            float4 e1 = *reinterpret_cast<const float4*>(&Ae[j * 132 + tn * 4 + 64]);
            float4 o0 = *reinterpret_cast<const float4*>(&Ao[j * 132 + tn * 4]);
            float4 o1 = *reinterpret_cast<const float4*>(&Ao[j * 132 + tn * 4 + 64]);
            float4 cc = *reinterpret_cast<const float4*>(&Bc[j * 68 + tc * 4]);
            float4 ss = *reinterpret_cast<const float4*>(&Bss[j * 68 + tc * 4]);
            u64 bbc[2] = {pk2(cc.x,cc.y), pk2(cc.z,cc.w)};
            u64 bbs[2] = {pk2(ss.x,ss.y), pk2(ss.z,ss.w)};
            float ae[8] = {e0.x,e0.y,e0.z,e0.w,e1.x,e1.y,e1.z,e1.w};
            float ao[8] = {o0.x,o0.y,o0.z,o0.w,o1.x,o1.y,o1.z,o1.w};
            #pragma unroll
            for (int p = 0; p < 8; p++) {
                u64 aaC = dup2(ae[p]);
                fma2(acc2C[p][0], aaC, bbc[0]);
                fma2(acc2C[p][1], aaC, bbc[1]);
                u64 aaS = dup2(ao[p]);
                fma2(acc2S[p][0], aaS, bbs[0]);
                fma2(acc2S[p][1], aaS, bbs[1]);
            }
        }
        if (more) {
            *reinterpret_cast<float4*>(&AeS[cur ^ 1][ar * 132 + ac4]) = ane;
            *reinterpret_cast<float4*>(&AoS[cur ^ 1][ar * 132 + ac4]) = ano;
            if (t < 128) *reinterpret_cast<float4*>(&BcS[cur ^ 1][mr * 68 + jc * 4]) = bn_;
            else         *reinterpret_cast<float4*>(&BsS[cur ^ 1][mr * 68 + jc * 4]) = bn_;
            __syncthreads();
        }
    }
    int jj0 = j0 + tc * 4;
    #pragma unroll
    for (int ph = 0; ph < 2; ph++)
        #pragma unroll
        for (int e = 0; e < 4; e++) {
            int p = ph * 4 + e;
            int col = col0 + ph * 64 + tn * 4 + e;
            int bo = col & 255, k = col >> 8;
            float2 C0 = un2(acc2C[p][0]), C1 = un2(acc2C[p][1]);
            float2 S0 = un2(acc2S[p][0]), S1 = un2(acc2S[p][1]);
            float cA[4] = {C0.x, C0.y, C1.x, C1.y};
            float sA[4] = {S0.x, S0.y, S1.x, S1.y};
            float* base = &out[(size_t)bo * 65536 + (size_t)k * 256];
            *reinterpret_cast<float4*>(base + jj0) =
                make_float4(cA[0] - sA[0], cA[1] - sA[1], cA[2] - sA[2], cA[3] - sA[3]);
            #pragma unroll
            for (int q = 0; q < 4; q++) {
                int jj = jj0 + q;
                if (jj > 0) base[256 - jj] = cA[q] + sA[q];
            }
        }
}

// ---------------------------------------------------------------------------
// y[128] column: out[bo][k][128] = sum_m wm*(-1)^m * rr[2m][col]
// ---------------------------------------------------------------------------
__global__ __launch_bounds__(256) void k_y128(float* __restrict__ out) {
    int col = blockIdx.x * 256 + threadIdx.x;
    float acc = 0.f;
    #pragma unroll
    for (int m = 0; m < 128; m++) {
        float g = (m == 0) ? 1.f : ((m & 1) ? -2.f : 2.f);
        acc += g * d_rr[(size_t)(2 * m) * NROW + col];
    }
    int bo = col & 255, k = col >> 8;
    out[(size_t)bo * 65536 + (size_t)k * 256 + 128] = acc;
}

// ---------------------------------------------------------------------------
extern "C" void kernel_launch(void* const* d_in, const int* in_sizes, int n_in,
                              void* d_out, int out_size) {
    const float* x = (const float*)d_in[0];
    const float* w = (const float*)d_in[1];
    float* out = (float*)d_out;

    k_quad<<<256, 128>>>();
    k_four2<<<128, 256>>>();
    k_legendre<<<128, 128>>>();

    k_fold<<<2048, 256>>>(x);
    k_g1f<0><<<512, 256>>>();      // Re rows (n=2m), K=136
    k_g1f<1><<<512, 256>>>();      // Im rows (n=2m+1), K=128
    dim3 g2(2, 256);   k_g2f<<<g2, 256>>>();
    k_mix<<<NX / 8, 256>>>(w);
    dim3 g4(4, 256);   k_g4f<<<g4, 256>>>();
    dim3 g5(512, 2);   k_g5f<<<g5, 256>>>(out);
    k_y128<<<256, 256>>>(out);
}

// round 11
// speedup vs baseline: 1.7814x; 1.0002x over previous
#include <cuda_runtime.h>
#include <math.h>

#define NLAT  256
#define NLON  256
#define LMAX  128
#define MMAX  129
#define NM    256           // effective 2*128 (m=128 plane identically zero)
#define NX    33024         // 2*LMAX*MMAX
#define BCH   256           // BATCH*CIN = BATCH*COUT
#define NROW  65536         // BCH*NLAT
#define KEPAD 136           // padded K for cos GEMM (valid j = 0..128)

typedef unsigned long long u64;
__device__ __forceinline__ u64 pk2(float x, float y) {
    u64 r; asm("mov.b64 %0, {%1, %2};" : "=l"(r) : "f"(x), "f"(y)); return r;
}
__device__ __forceinline__ u64 dup2(float x) { return pk2(x, x); }
__device__ __forceinline__ void fma2(u64 &d, u64 a, u64 b) {
    asm("fma.rn.f32x2 %0, %1, %2, %3;" : "=l"(d) : "l"(a), "l"(b), "l"(d));
}
__device__ __forceinline__ float2 un2(u64 v) {
    float2 f; asm("mov.b64 {%0, %1}, %2;" : "=f"(f.x), "=f"(f.y) : "l"(v)); return f;
}

// ---------------------------------------------------------------------------
// Static device scratch (no allocations; zero-initialized at load)
// ---------------------------------------------------------------------------
__device__ float d_wq[NLAT];
__device__ float d_Fc[LMAX * KEPAD];                   // [m][j] sc*cos, j<=128, else 0
__device__ float d_Fs[LMAX * 128];                     // [m][j] -sc*sin
__device__ float d_Gc[LMAX * 128];                     // [m][j] wm*cos
__device__ float d_Gs[LMAX * 128];                     // [m][j] wm*sin
// latitude-parity stacked Legendre tables, k < 128 only.
// li = ((l+m)&1)*64 + (l>>1)
__device__ float d_PCTW2[(size_t)LMAX * 128 * 128];    // [m][li][k]  (P*w)
__device__ float d_PCTT2[(size_t)LMAX * 128 * 128];    // [m][k][li]  (P)
__device__ float d_xe  [(size_t)KEPAD * NROW];         // folded even, rows 129..135 stay 0
__device__ float d_xo  [(size_t)128 * NROW];           // folded odd
__device__ float d_xh  [(size_t)NM * NROW];            // [n=2m+ri][k*256+bc]
__device__ float d_spec[(size_t)NX * BCH];             // (m=128 rows stay 0)
__device__ float d_out2[(size_t)NX * BCH];
__device__ float d_rr  [(size_t)NM * NROW];            // [n][k*256+bo]

// ---------------------------------------------------------------------------
// Clenshaw-Curtis quadrature weights
// ---------------------------------------------------------------------------
__global__ __launch_bounds__(128) void k_quad() {
    int j = blockIdx.x;
    int k = threadIdx.x;
    double tj = M_PI * (double)j / 255.0;
    double v = 0.0;
    if (k >= 1) v = cos(2.0 * tj * (double)k) * (2.0 / (4.0 * (double)k * k - 1.0));
    __shared__ double red[128];
    red[k] = v;
    __syncthreads();
    for (int s = 64; s > 0; s >>= 1) {
        if (k < s) red[k] += red[k + s];
        __syncthreads();
    }
    if (k == 0) {
        double c = (j == 0 || j == 255) ? 1.0 : 2.0;
        d_wq[j] = (float)(c / 255.0 * (1.0 - red[0]));
    }
}

// ---------------------------------------------------------------------------
// Fourier tables (exact mod-256 phase reduction)
// ---------------------------------------------------------------------------
__global__ __launch_bounds__(256) void k_four2() {
    int m = blockIdx.x;                  // 0..127
    int j = threadIdx.x;                 // 0..255
    int r = (m * j) & 255;
    float s, c;
    sincosf((float)(2.0 * M_PI / 256.0 * (double)r), &s, &c);
    const float sc = (float)(2.0 * M_PI / 256.0);
    if (j < KEPAD) d_Fc[m * KEPAD + j] = (j <= 128) ? sc * c : 0.f;
    if (j < 128) {
        d_Fs[m * 128 + j] = -sc * s;
        float wm = (m == 0) ? 1.f : 2.f;
        d_Gc[m * 128 + j] = wm * c;
        d_Gs[m * 128 + j] = wm * s;
    }
}

// ---------------------------------------------------------------------------
// Legendre tables, parity-stacked, nodes k<128 (double precision recurrence)
// ---------------------------------------------------------------------------
__global__ __launch_bounds__(128) void k_legendre() {
    int m  = blockIdx.x;                 // 0..127
    int kk = threadIdx.x;                // 0..127
    __shared__ double s_a[LMAX], s_b[LMAX];
    __shared__ double s_sect;
    {
        int l = kk;
        if (l >= m + 2) {
            double fl = (double)l, fm = (double)m, g = fl - 1.0;
            s_a[l] = sqrt((4.0 * fl * fl - 1.0) / (fl * fl - fm * fm));
            s_b[l] = sqrt((g * g - fm * fm) / (4.0 * g * g - 1.0));
        }
    }
    if (kk == 0) {
        double pr = 1.0;
        for (int i = 1; i <= m; i++) pr *= (2.0 * i + 1.0) / (2.0 * i);
        s_sect = sqrt(pr);
    }
    __syncthreads();
    double tt = M_PI * (double)kk / 255.0;
    double ct = cos(tt), st = sin(tt);
    double w  = (double)d_wq[kk];
    size_t baseW = (size_t)m * 128 * 128;
    size_t baseT = (size_t)m * 128 * 128 + (size_t)kk * 128;
    for (int l = 0; l < m; l++) {
        int li = (((l + m) & 1) << 6) | (l >> 1);
        d_PCTW2[baseW + (size_t)li * 128 + kk] = 0.f;
        d_PCTT2[baseT + li] = 0.f;
    }
    double powv = 1.0;
    for (int i = 0; i < m; i++) powv *= -st;
    double p2 = 0.28209479177387814347 * s_sect * powv;   // p[m][m], parity even
    {
        int li = (m >> 1);
        d_PCTW2[baseW + (size_t)li * 128 + kk] = (float)(p2 * w);
        d_PCTT2[baseT + li] = (float)p2;
    }
    if (m + 1 < LMAX) {
        double p1 = sqrt(2.0 * m + 3.0) * ct * p2;
        {
            int li = 64 + ((m + 1) >> 1);
            d_PCTW2[baseW + (size_t)li * 128 + kk] = (float)(p1 * w);
            d_PCTT2[baseT + li] = (float)p1;
        }
        for (int l = m + 2; l < LMAX; l++) {
            double p = s_a[l] * (ct * p1 - s_b[l] * p2);
            int li = (((l + m) & 1) << 6) | (l >> 1);
            d_PCTW2[baseW + (size_t)li * 128 + kk] = (float)(p * w);
            d_PCTT2[baseT + li] = (float)p;
            p2 = p1; p1 = p;
        }
    }
}

// ---------------------------------------------------------------------------
// Fold (longitude): xe[j]=x[j]+x[256-j], xo[j]=x[j]-x[256-j]
// ---------------------------------------------------------------------------
__global__ __launch_bounds__(256) void k_fold(const float* __restrict__ x) {
    __shared__ float s[32][257];
    int t = threadIdx.x;
    int col0 = blockIdx.x * 32;
    int klat = col0 >> 8;
    int bc0  = col0 & 255;
    #pragma unroll 4
    for (int r = 0; r < 32; r++)
        s[r][t] = x[(size_t)(bc0 + r) * 65536 + klat * 256 + t];
    __syncthreads();
    #pragma unroll 4
    for (int it = 0; it < 16; it++) {
        int idx = it * 256 + t;
        int j = idx >> 5, c = idx & 31;
        float a = s[c][j];
        float b = s[c][(256 - j) & 255];
        float xe = (j == 0) ? a : a + b;
        float xo = (j == 0) ? 0.f : a - b;
        d_xe[(size_t)j * NROW + col0 + c] = xe;
        d_xo[(size_t)j * NROW + col0 + c] = xo;
    }
    if (t < 32) d_xe[(size_t)128 * NROW + col0 + t] = s[t][128];
}

// ===========================================================================
// GEMM helpers (f32x2 packed-FMA cores)
// ===========================================================================
#define A_TSTORE(buf, v)                                                      \
    do { (buf)[(ak4+0)*132+am] = (v).x; (buf)[(ak4+1)*132+am] = (v).y;        \
         (buf)[(ak4+2)*132+am] = (v).z; (buf)[(ak4+3)*132+am] = (v).w; } while(0)

// full 8x8 (8 rows from Ap, 8 cols = tc*4 & tc*4+64 from Bp), acc2[8][4]
#define GEMM_COMPUTE2(Ap, Bp)                                                 \
    _Pragma("unroll")                                                         \
    for (int j = 0; j < 8; j++) {                                             \
        float4 a0 = *reinterpret_cast<const float4*>(&(Ap)[j*132 + tn*4]);    \
        float4 a1 = *reinterpret_cast<const float4*>(&(Ap)[j*132 + tn*4 + 64]);\
        float4 b0 = *reinterpret_cast<const float4*>(&(Bp)[j*132 + tc*4]);    \
        float4 b1 = *reinterpret_cast<const float4*>(&(Bp)[j*132 + tc*4 + 64]);\
        u64 bb[4] = {pk2(b0.x,b0.y), pk2(b0.z,b0.w), pk2(b1.x,b1.y), pk2(b1.z,b1.w)}; \
        float ar[8] = {a0.x,a0.y,a0.z,a0.w,a1.x,a1.y,a1.z,a1.w};              \
        _Pragma("unroll")                                                     \
        for (int p = 0; p < 8; p++) {                                         \
            u64 aa = dup2(ar[p]);                                             \
            _Pragma("unroll")                                                 \
            for (int q = 0; q < 4; q++) fma2(acc2[p][q], aa, bb[q]);          \
        }                                                                     \
    }

// ---------------------------------------------------------------------------
// G1 folded: xh[2*mm+PAR][col] = sum_j Atab[mm][j] * Bmat[j][col]
// ---------------------------------------------------------------------------
template<int PAR>
__global__ __launch_bounds__(256, 2) void k_g1f() {
    const float* Atab = PAR ? d_Fs : d_Fc;
    const float* Bmat = PAR ? d_xo : d_xe;
    const int astr = PAR ? 128 : KEPAD;
    const int KT   = PAR ? 16 : 17;
    __shared__ float Ast[2][8 * 132];
    __shared__ float Bs [2][8 * 132];
    int t = threadIdx.x;
    int col0 = blockIdx.x * 128;
    int am = t >> 1, ak4 = (t & 1) * 4;
    int bk = t >> 5, bn4 = (t & 31) * 4;
    int tc = t & 15, tn = t >> 4;
    float4 av = *reinterpret_cast<const float4*>(&Atab[am * astr + ak4]);
    float4 bv = *reinterpret_cast<const float4*>(&Bmat[(size_t)bk * NROW + col0 + bn4]);
    A_TSTORE(Ast[0], av);
    *reinterpret_cast<float4*>(&Bs[0][bk * 132 + bn4]) = bv;
    __syncthreads();
    u64 acc2[8][4] = {};
    for (int kt = 0; kt < KT; kt++) {
        int cur = kt & 1;
        bool more = (kt + 1 < KT);
        float4 an, bn_;
        if (more) {
            int k0 = (kt + 1) * 8;
            an  = *reinterpret_cast<const float4*>(&Atab[am * astr + k0 + ak4]);
            bn_ = *reinterpret_cast<const float4*>(&Bmat[(size_t)(k0 + bk) * NROW + col0 + bn4]);
        }
        GEMM_COMPUTE2(Ast[cur], Bs[cur]);
        if (more) {
            A_TSTORE(Ast[cur ^ 1], an);
            *reinterpret_cast<float4*>(&Bs[cur ^ 1][bk * 132 + bn4]) = bn_;
            __syncthreads();
        }
    }
    #pragma unroll
    for (int ph = 0; ph < 2; ph++)
        #pragma unroll
        for (int e = 0; e < 4; e++) {
            int p = ph * 4 + e;
            int mm = ph * 64 + tn * 4 + e;
            float2 c0 = un2(acc2[p][0]), c1 = un2(acc2[p][1]);
            float2 c2 = un2(acc2[p][2]), c3 = un2(acc2[p][3]);
            float* dst = &d_xh[(size_t)(2 * mm + PAR) * NROW + col0];
            *reinterpret_cast<float4*>(dst + tc * 4)      = make_float4(c0.x, c0.y, c1.x, c1.y);
            *reinterpret_cast<float4*>(dst + tc * 4 + 64) = make_float4(c2.x, c2.y, c3.x, c3.y);
        }
}

// ---------------------------------------------------------------------------
// G2 latitude-folded: per (mri): M=li (128: 64 E + 64 O), N=bc (128), K=k (128)
// grid (2, 256)
// ---------------------------------------------------------------------------
__global__ __launch_bounds__(256, 2) void k_g2f() {
    __shared__ float Ast[2][8 * 132];
    __shared__ float BeS[2][8 * 132];
    __shared__ float BoS[2][8 * 132];
    int t = threadIdx.x;
    int bc0 = blockIdx.x * 128;
    int mri = blockIdx.y;
    int m = mri >> 1, ri = mri & 1, par0 = m & 1;
    const float* A = d_PCTW2 + (size_t)m * 128 * 128;      // [li][k]
    const float* B = d_xh + (size_t)mri * NROW;            // [k*256+bc]
    int am = t >> 1, ak4 = (t & 1) * 4;
    int bk = t >> 5, bn4 = (t & 31) * 4;
    int tc = t & 15, tn = t >> 4;
    float4 av = *reinterpret_cast<const float4*>(&A[am * 128 + ak4]);
    float4 bt = *reinterpret_cast<const float4*>(&B[(size_t)bk * 256 + bc0 + bn4]);
    float4 bb = *reinterpret_cast<const float4*>(&B[(size_t)(255 - bk) * 256 + bc0 + bn4]);
    A_TSTORE(Ast[0], av);
    *reinterpret_cast<float4*>(&BeS[0][bk * 132 + bn4]) =
        make_float4(bt.x + bb.x, bt.y + bb.y, bt.z + bb.z, bt.w + bb.w);
    *reinterpret_cast<float4*>(&BoS[0][bk * 132 + bn4]) =
        make_float4(bt.x - bb.x, bt.y - bb.y, bt.z - bb.z, bt.w - bb.w);
    __syncthreads();
    u64 acc2[8][4] = {};
    for (int kt = 0; kt < 16; kt++) {
        int cur = kt & 1;
        bool more = (kt + 1 < 16);
        float4 an, btn, bbn;
        if (more) {
            int k0 = (kt + 1) * 8;
            an  = *reinterpret_cast<const float4*>(&A[am * 128 + k0 + ak4]);
            btn = *reinterpret_cast<const float4*>(&B[(size_t)(k0 + bk) * 256 + bc0 + bn4]);
            bbn = *reinterpret_cast<const float4*>(&B[(size_t)(255 - k0 - bk) * 256 + bc0 + bn4]);
        }
        const float* Ap = Ast[cur];
        const float* Be = BeS[cur];
        const float* Bo = BoS[cur];
        #pragma unroll
        for (int j = 0; j < 8; j++) {
            // E half: rows tn*4..+3 vs Be (8 cols)
            {
                float4 a0 = *reinterpret_cast<const float4*>(&Ap[j*132 + tn*4]);
                float4 b0 = *reinterpret_cast<const float4*>(&Be[j*132 + tc*4]);
                float4 b1 = *reinterpret_cast<const float4*>(&Be[j*132 + tc*4 + 64]);
                u64 bbv[4] = {pk2(b0.x,b0.y), pk2(b0.z,b0.w), pk2(b1.x,b1.y), pk2(b1.z,b1.w)};
                float ar[4] = {a0.x,a0.y,a0.z,a0.w};
                #pragma unroll
                for (int p = 0; p < 4; p++) {
                    u64 aa = dup2(ar[p]);
                    #pragma unroll
                    for (int q = 0; q < 4; q++) fma2(acc2[p][q], aa, bbv[q]);
                }
            }
            // O half: rows 64+tn*4..+3 vs Bo
            {
                float4 a1 = *reinterpret_cast<const float4*>(&Ap[j*132 + tn*4 + 64]);
                float4 b0 = *reinterpret_cast<const float4*>(&Bo[j*132 + tc*4]);
                float4 b1 = *reinterpret_cast<const float4*>(&Bo[j*132 + tc*4 + 64]);
                u64 bbv[4] = {pk2(b0.x,b0.y), pk2(b0.z,b0.w), pk2(b1.x,b1.y), pk2(b1.z,b1.w)};
                float ar[4] = {a1.x,a1.y,a1.z,a1.w};
                #pragma unroll
                for (int p = 0; p < 4; p++) {
                    u64 aa = dup2(ar[p]);
                    #pragma unroll
                    for (int q = 0; q < 4; q++) fma2(acc2[4 + p][q], aa, bbv[q]);
                }
            }
        }
        if (more) {
            A_TSTORE(Ast[cur ^ 1], an);
            *reinterpret_cast<float4*>(&BeS[cur ^ 1][bk * 132 + bn4]) =
                make_float4(btn.x + bbn.x, btn.y + bbn.y, btn.z + bbn.z, btn.w + bbn.w);
            *reinterpret_cast<float4*>(&BoS[cur ^ 1][bk * 132 + bn4]) =
                make_float4(btn.x - bbn.x, btn.y - bbn.y, btn.z - bbn.z, btn.w - bbn.w);
            __syncthreads();
        }
    }
    #pragma unroll
    for (int ph = 0; ph < 2; ph++)
        #pragma unroll
        for (int e = 0; e < 4; e++) {
            int le = tn * 4 + e;
            int l = (ph == 0) ? (2 * le + par0) : (2 * le + 1 - par0);
            size_t xrow = ((size_t)l * 129 + m) * 2 + ri;
            int p = ph * 4 + e;
            float2 c0 = un2(acc2[p][0]), c1 = un2(acc2[p][1]);
            float2 c2 = un2(acc2[p][2]), c3 = un2(acc2[p][3]);
            float* dst = &d_spec[xrow * 256 + bc0];
            *reinterpret_cast<float4*>(dst + tc * 4)      = make_float4(c0.x, c0.y, c1.x, c1.y);
            *reinterpret_cast<float4*>(dst + tc * 4 + 64) = make_float4(c2.x, c2.y, c3.x, c3.y);
        }
}

// ---------------------------------------------------------------------------
// G3: out2[x][b*32+o] = sum_i spec[x][b*32+i] * W[(i*32+o)*NX + x]
// ---------------------------------------------------------------------------
__global__ __launch_bounds__(256) void k_mix(const float* __restrict__ W) {
    __shared__ float Ws[8 * 1028];
    __shared__ float Ss[8 * 256];
    int t = threadIdx.x;
    int x0 = blockIdx.x * 8;
    #pragma unroll
    for (int rep = 0; rep < 32; rep++) {
        int idx = rep * 256 + t;
        int xl = idx & 7, io = idx >> 3;
        Ws[xl * 1028 + io] = W[(size_t)io * NX + x0 + xl];
    }
    #pragma unroll
    for (int rep = 0; rep < 8; rep++) {
        int idx = rep * 256 + t;
        int xl = idx >> 8, bc = idx & 255;
        Ss[xl * 256 + bc] = d_spec[(size_t)(x0 + xl) * 256 + bc];
    }
    __syncthreads();
    int b = t >> 5, o = t & 31;
    float acc[8] = {};
    #pragma unroll
    for (int xl = 0; xl < 8; xl++)
        #pragma unroll
        for (int i = 0; i < 32; i++)
            acc[xl] += Ss[xl * 256 + b * 32 + i] * Ws[xl * 1028 + i * 32 + o];
    #pragma unroll
    for (int xl = 0; xl < 8; xl++)
        d_out2[(size_t)(x0 + xl) * 256 + t] = acc[xl];
}

// ---------------------------------------------------------------------------
// G4 latitude-folded: per (mri): M=k<128 (128), N=bo (64), K=le (64) x2 parities
//   rr[k] = accE+accO ; rr[255-k] = accE-accO (fused unfold). grid (4, 256)
// ---------------------------------------------------------------------------
__global__ __launch_bounds__(256, 2) void k_g4f() {
    __shared__ float AeS[2][8 * 132];
    __shared__ float AoS[2][8 * 132];
    __shared__ float BeS[2][8 * 68];
    __shared__ float BoS[2][8 * 68];
    int t = threadIdx.x;
    int bo0 = blockIdx.x * 64;
    int mri = blockIdx.y;
    int m = mri >> 1, ri = mri & 1, par0 = m & 1;
    const float* A = d_PCTT2 + (size_t)m * 128 * 128;      // [k][li]
    int am = t >> 1, ak4 = (t & 1) * 4;
    int blr = (t & 127) >> 4, bn4 = (t & 15) * 4;
    int isBo = t >> 7;
    int tc = t & 15, tn = t >> 4;
    float4 ave = *reinterpret_cast<const float4*>(&A[am * 128 + ak4]);
    float4 avo = *reinterpret_cast<const float4*>(&A[am * 128 + 64 + ak4]);
    float4 bv;
    {
        int l = 2 * blr + (isBo ? (1 - par0) : par0);
        size_t xrow = ((size_t)l * 129 + m) * 2 + ri;
        bv = *reinterpret_cast<const float4*>(&d_out2[xrow * 256 + bo0 + bn4]);
    }
    A_TSTORE(AeS[0], ave);
    { float* buf = AoS[0];
      buf[(ak4+0)*132+am] = avo.x; buf[(ak4+1)*132+am] = avo.y;
      buf[(ak4+2)*132+am] = avo.z; buf[(ak4+3)*132+am] = avo.w; }
    if (isBo) *reinterpret_cast<float4*>(&BoS[0][blr * 68 + bn4]) = bv;
    else      *reinterpret_cast<float4*>(&BeS[0][blr * 68 + bn4]) = bv;
    __syncthreads();
    u64 acc2E[8][2] = {};
    u64 acc2O[8][2] = {};
    for (int lt = 0; lt < 8; lt++) {
        int cur = lt & 1;
        bool more = (lt + 1 < 8);
        float4 ane, ano, bn_;
        if (more) {
            int l0 = (lt + 1) * 8;
            ane = *reinterpret_cast<const float4*>(&A[am * 128 + l0 + ak4]);
            ano = *reinterpret_cast<const float4*>(&A[am * 128 + 64 + l0 + ak4]);
            int l = 2 * (l0 + blr) + (isBo ? (1 - par0) : par0);
            size_t xrow = ((size_t)l * 129 + m) * 2 + ri;
            bn_ = *reinterpret_cast<const float4*>(&d_out2[xrow * 256 + bo0 + bn4]);
        }
        const float* Ae = AeS[cur]; const float* Ao = AoS[cur];
        const float* Be = BeS[cur]; const float* Bo = BoS[cur];
        #pragma unroll
        for (int j = 0; j < 8; j++) {
            float4 e0 = *reinterpret_cast<const float4*>(&Ae[j*132 + tn*4]);
            float4 e1 = *reinterpret_cast<const float4*>(&Ae[j*132 + tn*4 + 64]);
            float4 o0 = *reinterpret_cast<const float4*>(&Ao[j*132 + tn*4]);
            float4 o1 = *reinterpret_cast<const float4*>(&Ao[j*132 + tn*4 + 64]);
            float4 be = *reinterpret_cast<const float4*>(&Be[j*68 + tc*4]);
            float4 bo = *reinterpret_cast<const float4*>(&Bo[j*68 + tc*4]);
            u64 bbe[2] = {pk2(be.x,be.y), pk2(be.z,be.w)};
            u64 bbo[2] = {pk2(bo.x,bo.y), pk2(bo.z,bo.w)};
            float ae[8] = {e0.x,e0.y,e0.z,e0.w,e1.x,e1.y,e1.z,e1.w};
            float ao[8] = {o0.x,o0.y,o0.z,o0.w,o1.x,o1.y,o1.z,o1.w};
            #pragma unroll
            for (int p = 0; p < 8; p++) {
                u64 aaE = dup2(ae[p]);
                fma2(acc2E[p][0], aaE, bbe[0]);
                fma2(acc2E[p][1], aaE, bbe[1]);
                u64 aaO = dup2(ao[p]);
                fma2(acc2O[p][0], aaO, bbo[0]);
                fma2(acc2O[p][1], aaO, bbo[1]);
            }
        }
        if (more) {
            A_TSTORE(AeS[cur ^ 1], ane);
            { float* buf = AoS[cur ^ 1];
              buf[(ak4+0)*132+am] = ano.x; buf[(ak4+1)*132+am] = ano.y;
              buf[(ak4+2)*132+am] = ano.z; buf[(ak4+3)*132+am] = ano.w; }
            if (isBo) *reinterpret_cast<float4*>(&BoS[cur ^ 1][blr * 68 + bn4]) = bn_;
            else      *reinterpret_cast<float4*>(&BeS[cur ^ 1][blr * 68 + bn4]) = bn_;
            __syncthreads();
        }
    }
    #pragma unroll
    for (int ph = 0; ph < 2; ph++)
        #pragma unroll
        for (int e = 0; e < 4; e++) {
            int p = ph * 4 + e;
            int k = ph * 64 + tn * 4 + e;                  // k < 128
            float2 E0 = un2(acc2E[p][0]), E1 = un2(acc2E[p][1]);
            float2 O0 = un2(acc2O[p][0]), O1 = un2(acc2O[p][1]);
            float* base = &d_rr[(size_t)mri * NROW];
            *reinterpret_cast<float4*>(base + (size_t)k * 256 + bo0 + tc * 4) =
                make_float4(E0.x + O0.x, E0.y + O0.y, E1.x + O1.x, E1.y + O1.y);
            *reinterpret_cast<float4*>(base + (size_t)(255 - k) * 256 + bo0 + tc * 4) =
                make_float4(E0.x - O0.x, E0.y - O0.y, E1.x - O1.x, E1.y - O1.y);
        }
}

// ---------------------------------------------------------------------------
// G5 folded+fused: C[col][j]=sum_m Gc[m][j]*rr[2m][col], S likewise (Gs, rr odd)
// y[j] = C-S ; y[256-j] = C+S (j>=1). grid (512, 2)
// ---------------------------------------------------------------------------
__global__ __launch_bounds__(256, 2) void k_g5f(float* __restrict__ out) {
    __shared__ float AeS[2][8 * 132];
    __shared__ float AoS[2][8 * 132];
    __shared__ float BcS[2][8 * 68];
    __shared__ float BsS[2][8 * 68];
    int t = threadIdx.x;
    int col0 = blockIdx.x * 128;
    int j0   = blockIdx.y * 64;
    int ar = t >> 5, ac4 = (t & 31) * 4;
    int mr = (t & 127) >> 4, jc = t & 15;
    int tc = t & 15, tn = t >> 4;
    float4 ave = *reinterpret_cast<const float4*>(&d_rr[(size_t)(2 * ar) * NROW + col0 + ac4]);
    float4 avo = *reinterpret_cast<const float4*>(&d_rr[(size_t)(2 * ar + 1) * NROW + col0 + ac4]);
    float4 bvx;
    if (t < 128) bvx = *reinterpret_cast<const float4*>(&d_Gc[mr * 128 + j0 + jc * 4]);
    else         bvx = *reinterpret_cast<const float4*>(&d_Gs[mr * 128 + j0 + jc * 4]);
    *reinterpret_cast<float4*>(&AeS[0][ar * 132 + ac4]) = ave;
    *reinterpret_cast<float4*>(&AoS[0][ar * 132 + ac4]) = avo;
    if (t < 128) *reinterpret_cast<float4*>(&BcS[0][mr * 68 + jc * 4]) = bvx;
    else         *reinterpret_cast<float4*>(&BsS[0][mr * 68 + jc * 4]) = bvx;
    __syncthreads();
    u64 acc2C[8][2] = {};
    u64 acc2S[8][2] = {};
    for (int kt = 0; kt < 16; kt++) {
        int cur = kt & 1;
        bool more = (kt + 1 < 16);
        float4 ane, ano, bn_;
        if (more) {
            int m0 = (kt + 1) * 8;
            ane = *reinterpret_cast<const float4*>(&d_rr[(size_t)(2 * (m0 + ar)) * NROW + col0 + ac4]);
            ano = *reinterpret_cast<const float4*>(&d_rr[(size_t)(2 * (m0 + ar) + 1) * NROW + col0 + ac4]);
            if (t < 128) bn_ = *reinterpret_cast<const float4*>(&d_Gc[(m0 + mr) * 128 + j0 + jc * 4]);
            else         bn_ = *reinterpret_cast<const float4*>(&d_Gs[(m0 + mr) * 128 + j0 + jc * 4]);
        }
        const float* Ae = AeS[cur]; const float* Ao = AoS[cur];
        const float* Bc = BcS[cur]; const float* Bss = BsS[cur];
        #pragma unroll
        for (int j = 0; j < 8; j++) {
            float4 e0 = *reinterpret_cast<const float4*>(&Ae[j * 132 + tn * 4]);
            float4 e1 = *reinterpret_cast<const float4*>(&Ae[j * 132 + tn * 4 + 64]);
            float4 o0 = *reinterpret_cast<const float4*>(&Ao[j * 132 + tn * 4]);
            float4 o1 = *reinterpret_cast<const float4*>(&Ao[j * 132 + tn * 4 + 64]);
            float4 cc = *reinterpret_cast<const float4*>(&Bc[j * 68 + tc * 4]);
            float4 ss = *reinterpret_cast<const float4*>(&Bss[j * 68 + tc * 4]);
            u64 bbc[2] = {pk2(cc.x,cc.y), pk2(cc.z,cc.w)};
            u64 bbs[2] = {pk2(ss.x,ss.y), pk2(ss.z,ss.w)};
            float ae[8] = {e0.x,e0.y,e0.z,e0.w,e1.x,e1.y,e1.z,e1.w};
            float ao[8] = {o0.x,o0.y,o0.z,o0.w,o1.x,o1.y,o1.z,o1.w};
            #pragma unroll
            for (int p = 0; p < 8; p++) {
                u64 aaC = dup2(ae[p]);
                fma2(acc2C[p][0], aaC, bbc[0]);
                fma2(acc2C[p][1], aaC, bbc[1]);
                u64 aaS = dup2(ao[p]);
                fma2(acc2S[p][0], aaS, bbs[0]);
                fma2(acc2S[p][1], aaS, bbs[1]);
            }
        }
        if (more) {
            *reinterpret_cast<float4*>(&AeS[cur ^ 1][ar * 132 + ac4]) = ane;
            *reinterpret_cast<float4*>(&AoS[cur ^ 1][ar * 132 + ac4]) = ano;
            if (t < 128) *reinterpret_cast<float4*>(&BcS[cur ^ 1][mr * 68 + jc * 4]) = bn_;
            else         *reinterpret_cast<float4*>(&BsS[cur ^ 1][mr * 68 + jc * 4]) = bn_;
            __syncthreads();
        }
    }
    int jj0 = j0 + tc * 4;
    #pragma unroll
    for (int ph = 0; ph < 2; ph++)
        #pragma unroll
        for (int e = 0; e < 4; e++) {
            int p = ph * 4 + e;
            int col = col0 + ph * 64 + tn * 4 + e;
            int bo = col & 255, k = col >> 8;
            float2 C0 = un2(acc2C[p][0]), C1 = un2(acc2C[p][1]);
            float2 S0 = un2(acc2S[p][0]), S1 = un2(acc2S[p][1]);
            float cA[4] = {C0.x, C0.y, C1.x, C1.y};
            float sA[4] = {S0.x, S0.y, S1.x, S1.y};
            float* base = &out[(size_t)bo * 65536 + (size_t)k * 256];
            *reinterpret_cast<float4*>(base + jj0) =
                make_float4(cA[0] - sA[0], cA[1] - sA[1], cA[2] - sA[2], cA[3] - sA[3]);
            #pragma unroll
            for (int q = 0; q < 4; q++) {
                int jj = jj0 + q;
                if (jj > 0) base[256 - jj] = cA[q] + sA[q];
            }
        }
}

// ---------------------------------------------------------------------------
// y[128] column: out[bo][k][128] = sum_m wm*(-1)^m * rr[2m][col]
// ---------------------------------------------------------------------------
__global__ __launch_bounds__(256) void k_y128(float* __restrict__ out) {
    int col = blockIdx.x * 256 + threadIdx.x;
    float acc = 0.f;
    #pragma unroll
    for (int m = 0; m < 128; m++) {
        float g = (m == 0) ? 1.f : ((m & 1) ? -2.f : 2.f);
        acc += g * d_rr[(size_t)(2 * m) * NROW + col];
    }
    int bo = col & 255, k = col >> 8;
    out[(size_t)bo * 65536 + (size_t)k * 256 + 128] = acc;
}

// ---------------------------------------------------------------------------
extern "C" void kernel_launch(void* const* d_in, const int* in_sizes, int n_in,
                              void* d_out, int out_size) {
    const float* x = (const float*)d_in[0];
    const float* w = (const float*)d_in[1];
    float* out = (float*)d_out;

    k_quad<<<256, 128>>>();
    k_four2<<<128, 256>>>();
    k_legendre<<<128, 128>>>();

    k_fold<<<2048, 256>>>(x);
    k_g1f<0><<<512, 256>>>();      // Re rows (n=2m), K=136
    k_g1f<1><<<512, 256>>>();      // Im rows (n=2m+1), K=128
    dim3 g2(2, 256);   k_g2f<<<g2, 256>>>();
    k_mix<<<NX / 8, 256>>>(w);
    dim3 g4(4, 256);   k_g4f<<<g4, 256>>>();
    dim3 g5(512, 2);   k_g5f<<<g5, 256>>>(out);
    k_y128<<<256, 256>>>(out);
}

// round 14
// speedup vs baseline: 1.8606x; 1.0444x over previous
#include <cuda_runtime.h>
#include <math.h>
#include <stdint.h>

#define NLAT  256
#define LMAX  128
#define NM    256
#define NX    33024
#define NROW  65536
#define KEPAD 136
#define KQ    72            // quarter-folded K pad (valid j = 0..64)

typedef unsigned long long u64;
__device__ __forceinline__ u64 pk2(float x, float y) {
    u64 r; asm("mov.b64 %0, {%1, %2};" : "=l"(r) : "f"(x), "f"(y)); return r;
}
__device__ __forceinline__ u64 dup2(float x) { return pk2(x, x); }
__device__ __forceinline__ void fma2(u64 &d, u64 a, u64 b) {
    asm("fma.rn.f32x2 %0, %1, %2, %3;" : "=l"(d) : "l"(a), "l"(b), "l"(d));
}
__device__ __forceinline__ float2 un2(u64 v) {
    float2 f; asm("mov.b64 {%0, %1}, %2;" : "=f"(f.x), "=f"(f.y) : "l"(v)); return f;
}

// --------------------------- device scratch --------------------------------
__device__ float d_wq[NLAT];
__device__ float d_Gc[LMAX * 128];
__device__ float d_Gs[LMAX * 128];
__device__ float d_Tc2[128 * KQ];   // [li][j] cos table; li<64: m=2li, li>=64: m=2(li-64)+1
__device__ float d_Ts2[128 * KQ];   // [li][j] -sin table, same row mapping
__device__ float d_PCTW2[(size_t)LMAX * 128 * 128];   // [m][li][k]
__device__ float d_PCTT2[(size_t)LMAX * 128 * 128];   // [m][k][li]
__device__ float d_xe[(size_t)KEPAD * NROW];          // rows 0..128 written, rest 0
__device__ float d_xo[(size_t)KEPAD * NROW];          // rows 0..127 written, rest 0
__device__ float d_xh  [(size_t)NM * NROW];
__device__ float d_spec[(size_t)NX * 256];
__device__ float d_out2[(size_t)NX * 256];
__device__ float d_rr  [(size_t)NM * NROW];

// --------------------------- setup ---------------------------------
__global__ __launch_bounds__(128) void k_quad() {
    int j = blockIdx.x, k = threadIdx.x;
    double tj = M_PI * (double)j / 255.0, v = 0.0;
    if (k >= 1) v = cos(2.0 * tj * (double)k) * (2.0 / (4.0 * (double)k * k - 1.0));
    __shared__ double red[128];
    red[k] = v; __syncthreads();
    for (int s = 64; s > 0; s >>= 1) { if (k < s) red[k] += red[k + s]; __syncthreads(); }
    if (k == 0) {
        double c = (j == 0 || j == 255) ? 1.0 : 2.0;
        d_wq[j] = (float)(c / 255.0 * (1.0 - red[0]));
    }
}

__global__ __launch_bounds__(128) void k_tab() {
    int li = blockIdx.x;                    // 0..127
    int j  = threadIdx.x;                   // 0..127
    const float sc = (float)(2.0 * M_PI / 256.0);
    {
        int r = (li * j) & 255;
        float s, c;
        sincosf(sc * (float)r, &s, &c);
        float wm = (li == 0) ? 1.f : 2.f;
        d_Gc[li * 128 + j] = wm * c;
        d_Gs[li * 128 + j] = wm * s;
    }
    if (j < KQ) {
        int m = (li < 64) ? (2 * li) : (2 * (li - 64) + 1);
        int r = (m * j) & 255;
        float s, c;
        sincosf(sc * (float)r, &s, &c);
        float tc = (j <= 64) ? sc * c : 0.f;
        float ts = (j >= 1 && j <= 64) ? -sc * s : 0.f;
        if (j == 64) { tc *= 0.5f; ts *= 0.5f; }   // self-paired singleton
        d_Tc2[li * KQ + j] = tc;
        d_Ts2[li * KQ + j] = ts;
    }
}

__global__ __launch_bounds__(128) void k_legendre() {
    int m = blockIdx.x, kk = threadIdx.x;
    __shared__ double s_a[LMAX], s_b[LMAX];
    __shared__ double s_sect;
    {
        int l = kk;
        if (l >= m + 2) {
            double fl = (double)l, fm = (double)m, g = fl - 1.0;
            s_a[l] = sqrt((4.0 * fl * fl - 1.0) / (fl * fl - fm * fm));
            s_b[l] = sqrt((g * g - fm * fm) / (4.0 * g * g - 1.0));
        }
    }
    if (kk == 0) {
        double pr = 1.0;
        for (int i = 1; i <= m; i++) pr *= (2.0 * i + 1.0) / (2.0 * i);
        s_sect = sqrt(pr);
    }
    __syncthreads();
    double tt = M_PI * (double)kk / 255.0;
    double ct = cos(tt), st = sin(tt), w = (double)d_wq[kk];
    size_t baseW = (size_t)m * 128 * 128;
    size_t baseT = (size_t)m * 128 * 128 + (size_t)kk * 128;
    for (int l = 0; l < m; l++) {
        int li = (((l + m) & 1) << 6) | (l >> 1);
        d_PCTW2[baseW + (size_t)li * 128 + kk] = 0.f;
        d_PCTT2[baseT + li] = 0.f;
    }
    double powv = 1.0;
    for (int i = 0; i < m; i++) powv *= -st;
    double p2 = 0.28209479177387814347 * s_sect * powv;
    {
        int li = (m >> 1);
        d_PCTW2[baseW + (size_t)li * 128 + kk] = (float)(p2 * w);
        d_PCTT2[baseT + li] = (float)p2;
    }
    if (m + 1 < LMAX) {
        double p1 = sqrt(2.0 * m + 3.0) * ct * p2;
        {
            int li = 64 + ((m + 1) >> 1);
            d_PCTW2[baseW + (size_t)li * 128 + kk] = (float)(p1 * w);
            d_PCTT2[baseT + li] = (float)p1;
        }
        for (int l = m + 2; l < LMAX; l++) {
            double p = s_a[l] * (ct * p1 - s_b[l] * p2);
            int li = (((l + m) & 1) << 6) | (l >> 1);
            d_PCTW2[baseW + (size_t)li * 128 + kk] = (float)(p * w);
            d_PCTT2[baseT + li] = (float)p;
            p2 = p1; p1 = p;
        }
    }
}

// Fold (longitude): xe[j]=x[j]+x[256-j], xo[j]=x[j]-x[256-j], layout [j][col]
__global__ __launch_bounds__(256) void k_fold(const float* __restrict__ x) {
    __shared__ float s[32][257];
    int t = threadIdx.x;
    int col0 = blockIdx.x * 32;
    int klat = col0 >> 8;
    int bc0  = col0 & 255;
    #pragma unroll 4
    for (int r = 0; r < 32; r++)
        s[r][t] = x[(size_t)(bc0 + r) * 65536 + klat * 256 + t];
    __syncthreads();
    #pragma unroll 4
    for (int it = 0; it < 16; it++) {
        int idx = it * 256 + t;
        int j = idx >> 5, c = idx & 31;
        float a = s[c][j];
        float b = s[c][(256 - j) & 255];
        float xe = (j == 0) ? a : a + b;
        float xo = (j == 0) ? 0.f : a - b;
        d_xe[(size_t)j * NROW + col0 + c] = xe;
        d_xo[(size_t)j * NROW + col0 + c] = xo;
    }
    if (t < 32) d_xe[(size_t)128 * NROW + col0 + t] = s[t][128];
}

#define A_TSTORE(buf, v) \
    do { (buf)[(ak4+0)*132+am] = (v).x; (buf)[(ak4+1)*132+am] = (v).y; \
         (buf)[(ak4+2)*132+am] = (v).z; (buf)[(ak4+3)*132+am] = (v).w; } while(0)

// ---------------------------------------------------------------------------
// G1 quarter-folded: M=128 li rows, N=128 cols, K=72.
//   Bsum[j] = B[j]+B[128-j], Bdif[j] = B[j]-B[128-j]
//   cos (IM=0): even-m rows (li<64) x Bsum, odd-m rows x Bdif
//   sin (IM=1): even-m rows x Bdif, odd-m rows x Bsum   (parity flipped!)
// ---------------------------------------------------------------------------
template<int IM>
__global__ __launch_bounds__(256, 2) void k_g1p() {
    __shared__ float Ast[2][8 * 132];
    __shared__ float BpS[2][8 * 132];   // sum
    __shared__ float BmS[2][8 * 132];   // diff
    int t = threadIdx.x;
    int col0 = blockIdx.x * 128;
    const float* A = IM ? d_Ts2 : d_Tc2;                  // [li][KQ]
    const float* B = IM ? d_xo : d_xe;                    // [j][NROW]
    int am = t >> 1, ak4 = (t & 1) * 4;
    int bk = t >> 5, bn4 = (t & 31) * 4;
    int tc = t & 15, tn = t >> 4;
    float4 av = *reinterpret_cast<const float4*>(&A[am * KQ + ak4]);
    float4 bt = *reinterpret_cast<const float4*>(&B[(size_t)bk * NROW + col0 + bn4]);
    float4 bb = *reinterpret_cast<const float4*>(&B[(size_t)(128 - bk) * NROW + col0 + bn4]);
    A_TSTORE(Ast[0], av);
    *reinterpret_cast<float4*>(&BpS[0][bk * 132 + bn4]) =
        make_float4(bt.x + bb.x, bt.y + bb.y, bt.z + bb.z, bt.w + bb.w);
    *reinterpret_cast<float4*>(&BmS[0][bk * 132 + bn4]) =
        make_float4(bt.x - bb.x, bt.y - bb.y, bt.z - bb.z, bt.w - bb.w);
    __syncthreads();
    u64 acc2[8][4] = {};
    for (int kt = 0; kt < 9; kt++) {
        int cur = kt & 1;
        bool more = (kt + 1 < 9);
        float4 an, btn, bbn;
        if (more) {
            int k0 = (kt + 1) * 8;
            an  = *reinterpret_cast<const float4*>(&A[am * KQ + k0 + ak4]);
            btn = *reinterpret_cast<const float4*>(&B[(size_t)(k0 + bk) * NROW + col0 + bn4]);
            bbn = *reinterpret_cast<const float4*>(&B[(size_t)(128 - k0 - bk) * NROW + col0 + bn4]);
        }
        const float* Ap = Ast[cur];
        const float* Bev = IM ? BmS[cur] : BpS[cur];   // even-m rows
        const float* Bod = IM ? BpS[cur] : BmS[cur];   // odd-m rows
        #pragma unroll
        for (int j = 0; j < 8; j++) {
            {
                float4 a0 = *reinterpret_cast<const float4*>(&Ap[j*132 + tn*4]);
                float4 b0 = *reinterpret_cast<const float4*>(&Bev[j*132 + tc*4]);
                float4 b1 = *reinterpret_cast<const float4*>(&Bev[j*132 + tc*4 + 64]);
                u64 bbv[4] = {pk2(b0.x,b0.y), pk2(b0.z,b0.w), pk2(b1.x,b1.y), pk2(b1.z,b1.w)};
                float ar[4] = {a0.x,a0.y,a0.z,a0.w};
                #pragma unroll
                for (int p = 0; p < 4; p++) {
                    u64 aa = dup2(ar[p]);
                    #pragma unroll
                    for (int q = 0; q < 4; q++) fma2(acc2[p][q], aa, bbv[q]);
                }
            }
            {
                float4 a1 = *reinterpret_cast<const float4*>(&Ap[j*132 + tn*4 + 64]);
                float4 b0 = *reinterpret_cast<const float4*>(&Bod[j*132 + tc*4]);
                float4 b1 = *reinterpret_cast<const float4*>(&Bod[j*132 + tc*4 + 64]);
                u64 bbv[4] = {pk2(b0.x,b0.y), pk2(b0.z,b0.w), pk2(b1.x,b1.y), pk2(b1.z,b1.w)};
                float ar[4] = {a1.x,a1.y,a1.z,a1.w};
                #pragma unroll
                for (int p = 0; p < 4; p++) {
                    u64 aa = dup2(ar[p]);
                    #pragma unroll
                    for (int q = 0; q < 4; q++) fma2(acc2[4 + p][q], aa, bbv[q]);
                }
            }
        }
        if (more) {
            A_TSTORE(Ast[cur ^ 1], an);
            *reinterpret_cast<float4*>(&BpS[cur ^ 1][bk * 132 + bn4]) =
                make_float4(btn.x + bbn.x, btn.y + bbn.y, btn.z + bbn.z, btn.w + bbn.w);
            *reinterpret_cast<float4*>(&BmS[cur ^ 1][bk * 132 + bn4]) =
                make_float4(btn.x - bbn.x, btn.y - bbn.y, btn.z - bbn.z, btn.w - bbn.w);
            __syncthreads();
        }
    }
    #pragma unroll
    for (int ph = 0; ph < 2; ph++)
        #pragma unroll
        for (int e = 0; e < 4; e++) {
            int le = tn * 4 + e;
            int xr = (ph == 0) ? (4 * le + IM) : (4 * le + 2 + IM);
            int p = ph * 4 + e;
            float2 c0 = un2(acc2[p][0]), c1 = un2(acc2[p][1]);
            float2 c2 = un2(acc2[p][2]), c3 = un2(acc2[p][3]);
            float* dst = &d_xh[(size_t)xr * NROW + col0];
            *reinterpret_cast<float4*>(dst + tc * 4)      = make_float4(c0.x, c0.y, c1.x, c1.y);
            *reinterpret_cast<float4*>(dst + tc * 4 + 64) = make_float4(c2.x, c2.y, c3.x, c3.y);
        }
}

// ---------------------------------------------------------------------------
// G2 latitude-folded (proven)
// ---------------------------------------------------------------------------
__global__ __launch_bounds__(256, 2) void k_g2f() {
    __shared__ float Ast[2][8 * 132];
    __shared__ float BeS[2][8 * 132];
    __shared__ float BoS[2][8 * 132];
    int t = threadIdx.x;
    int bc0 = blockIdx.x * 128;
    int mri = blockIdx.y;
    int m = mri >> 1, ri = mri & 1, par0 = m & 1;
    const float* A = d_PCTW2 + (size_t)m * 128 * 128;
    const float* B = d_xh + (size_t)mri * NROW;
    int am = t >> 1, ak4 = (t & 1) * 4;
    int bk = t >> 5, bn4 = (t & 31) * 4;
    int tc = t & 15, tn = t >> 4;
    float4 av = *reinterpret_cast<const float4*>(&A[am * 128 + ak4]);
    float4 bt = *reinterpret_cast<const float4*>(&B[(size_t)bk * 256 + bc0 + bn4]);
    float4 bb = *reinterpret_cast<const float4*>(&B[(size_t)(255 - bk) * 256 + bc0 + bn4]);
    A_TSTORE(Ast[0], av);
    *reinterpret_cast<float4*>(&BeS[0][bk * 132 + bn4]) =
        make_float4(bt.x + bb.x, bt.y + bb.y, bt.z + bb.z, bt.w + bb.w);
    *reinterpret_cast<float4*>(&BoS[0][bk * 132 + bn4]) =
        make_float4(bt.x - bb.x, bt.y - bb.y, bt.z - bb.z, bt.w - bb.w);
    __syncthreads();
    u64 acc2[8][4] = {};
    for (int kt = 0; kt < 16; kt++) {
        int cur = kt & 1;
        bool more = (kt + 1 < 16);
        float4 an, btn, bbn;
        if (more) {
            int k0 = (kt + 1) * 8;
            an  = *reinterpret_cast<const float4*>(&A[am * 128 + k0 + ak4]);
            btn = *reinterpret_cast<const float4*>(&B[(size_t)(k0 + bk) * 256 + bc0 + bn4]);
            bbn = *reinterpret_cast<const float4*>(&B[(size_t)(255 - k0 - bk) * 256 + bc0 + bn4]);
        }
        const float* Ap = Ast[cur];
        const float* Be = BeS[cur];
        const float* Bo = BoS[cur];
        #pragma unroll
        for (int j = 0; j < 8; j++) {
            {
                float4 a0 = *reinterpret_cast<const float4*>(&Ap[j*132 + tn*4]);
                float4 b0 = *reinterpret_cast<const float4*>(&Be[j*132 + tc*4]);
                float4 b1 = *reinterpret_cast<const float4*>(&Be[j*132 + tc*4 + 64]);
                u64 bbv[4] = {pk2(b0.x,b0.y), pk2(b0.z,b0.w), pk2(b1.x,b1.y), pk2(b1.z,b1.w)};
                float ar[4] = {a0.x,a0.y,a0.z,a0.w};
                #pragma unroll
                for (int p = 0; p < 4; p++) {
                    u64 aa = dup2(ar[p]);
                    #pragma unroll
                    for (int q = 0; q < 4; q++) fma2(acc2[p][q], aa, bbv[q]);
                }
            }
            {
                float4 a1 = *reinterpret_cast<const float4*>(&Ap[j*132 + tn*4 + 64]);
                float4 b0 = *reinterpret_cast<const float4*>(&Bo[j*132 + tc*4]);
                float4 b1 = *reinterpret_cast<const float4*>(&Bo[j*132 + tc*4 + 64]);
                u64 bbv[4] = {pk2(b0.x,b0.y), pk2(b0.z,b0.w), pk2(b1.x,b1.y), pk2(b1.z,b1.w)};
                float ar[4] = {a1.x,a1.y,a1.z,a1.w};
                #pragma unroll
                for (int p = 0; p < 4; p++) {
                    u64 aa = dup2(ar[p]);
                    #pragma unroll
                    for (int q = 0; q < 4; q++) fma2(acc2[4 + p][q], aa, bbv[q]);
                }
            }
        }
        if (more) {
            A_TSTORE(Ast[cur ^ 1], an);
            *reinterpret_cast<float4*>(&BeS[cur ^ 1][bk * 132 + bn4]) =
                make_float4(btn.x + bbn.x, btn.y + bbn.y, btn.z + bbn.z, btn.w + bbn.w);
            *reinterpret_cast<float4*>(&BoS[cur ^ 1][bk * 132 + bn4]) =
                make_float4(btn.x - bbn.x, btn.y - bbn.y, btn.z - bbn.z, btn.w - bbn.w);
            __syncthreads();
        }
    }
    #pragma unroll
    for (int ph = 0; ph < 2; ph++)
        #pragma unroll
        for (int e = 0; e < 4; e++) {
            int le = tn * 4 + e;
            int l = (ph == 0) ? (2 * le + par0) : (2 * le + 1 - par0);
            size_t xrow = ((size_t)l * 129 + m) * 2 + ri;
            int p = ph * 4 + e;
            float2 c0 = un2(acc2[p][0]), c1 = un2(acc2[p][1]);
            float2 c2 = un2(acc2[p][2]), c3 = un2(acc2[p][3]);
            float* dst = &d_spec[xrow * 256 + bc0];
            *reinterpret_cast<float4*>(dst + tc * 4)      = make_float4(c0.x, c0.y, c1.x, c1.y);
            *reinterpret_cast<float4*>(dst + tc * 4 + 64) = make_float4(c2.x, c2.y, c3.x, c3.y);
        }
}

__global__ __launch_bounds__(256) void k_mix(const float* __restrict__ W) {
    __shared__ float Ws[8 * 1028];
    __shared__ float Ss[8 * 256];
    int t = threadIdx.x;
    int x0 = blockIdx.x * 8;
    #pragma unroll
    for (int rep = 0; rep < 32; rep++) {
        int idx = rep * 256 + t;
        int xl = idx & 7, io = idx >> 3;
        Ws[xl * 1028 + io] = W[(size_t)io * NX + x0 + xl];
    }
    #pragma unroll
    for (int rep = 0; rep < 8; rep++) {
        int idx = rep * 256 + t;
        int xl = idx >> 8, bc = idx & 255;
        Ss[xl * 256 + bc] = d_spec[(size_t)(x0 + xl) * 256 + bc];
    }
    __syncthreads();
    int b = t >> 5, o = t & 31;
    float acc[8] = {};
    #pragma unroll
    for (int xl = 0; xl < 8; xl++)
        #pragma unroll
        for (int i = 0; i < 32; i++)
            acc[xl] += Ss[xl * 256 + b * 32 + i] * Ws[xl * 1028 + i * 32 + o];
    #pragma unroll
    for (int xl = 0; xl < 8; xl++)
        d_out2[(size_t)(x0 + xl) * 256 + t] = acc[xl];
}

__global__ __launch_bounds__(256, 2) void k_g4f() {
    __shared__ float AeS[2][8 * 132];
    __shared__ float AoS[2][8 * 132];
    __shared__ float BeS[2][8 * 68];
    __shared__ float BoS[2][8 * 68];
    int t = threadIdx.x;
    int bo0 = blockIdx.x * 64;
    int mri = blockIdx.y;
    int m = mri >> 1, ri = mri & 1, par0 = m & 1;
    const float* A = d_PCTT2 + (size_t)m * 128 * 128;
    int am = t >> 1, ak4 = (t & 1) * 4;
    int blr = (t & 127) >> 4, bn4 = (t & 15) * 4;
    int isBo = t >> 7;
    int tc = t & 15, tn = t >> 4;
    float4 ave = *reinterpret_cast<const float4*>(&A[am * 128 + ak4]);
    float4 avo = *reinterpret_cast<const float4*>(&A[am * 128 + 64 + ak4]);
    float4 bv;
    {
        int l = 2 * blr + (isBo ? (1 - par0) : par0);
        size_t xrow = ((size_t)l * 129 + m) * 2 + ri;
        bv = *reinterpret_cast<const float4*>(&d_out2[xrow * 256 + bo0 + bn4]);
    }
    A_TSTORE(AeS[0], ave);
    { float* buf = AoS[0];
      buf[(ak4+0)*132+am] = avo.x; buf[(ak4+1)*132+am] = avo.y;
      buf[(ak4+2)*132+am] = avo.z; buf[(ak4+3)*132+am] = avo.w; }
    if (isBo) *reinterpret_cast<float4*>(&BoS[0][blr * 68 + bn4]) = bv;
    else      *reinterpret_cast<float4*>(&BeS[0][blr * 68 + bn4]) = bv;
    __syncthreads();
    u64 acc2E[8][2] = {};
    u64 acc2O[8][2] = {};
    for (int lt = 0; lt < 8; lt++) {
        int cur = lt & 1;
        bool more = (lt + 1 < 8);
        float4 ane, ano, bn_;
        if (more) {
            int l0 = (lt + 1) * 8;
            ane = *reinterpret_cast<const float4*>(&A[am * 128 + l0 + ak4]);
            ano = *reinterpret_cast<const float4*>(&A[am * 128 + 64 + l0 + ak4]);
            int l = 2 * (l0 + blr) + (isBo ? (1 - par0) : par0);
            size_t xrow = ((size_t)l * 129 + m) * 2 + ri;
            bn_ = *reinterpret_cast<const float4*>(&d_out2[xrow * 256 + bo0 + bn4]);
        }
        const float* Ae = AeS[cur]; const float* Ao = AoS[cur];
        const float* Be = BeS[cur]; const float* Bo = BoS[cur];
        #pragma unroll
        for (int j = 0; j < 8; j++) {
            float4 e0 = *reinterpret_cast<const float4*>(&Ae[j*132 + tn*4]);
            float4 e1 = *reinterpret_cast<const float4*>(&Ae[j*132 + tn*4 + 64]);
            float4 o0 = *reinterpret_cast<const float4*>(&Ao[j*132 + tn*4]);
            float4 o1 = *reinterpret_cast<const float4*>(&Ao[j*132 + tn*4 + 64]);
            float4 be = *reinterpret_cast<const float4*>(&Be[j*68 + tc*4]);
            float4 bo = *reinterpret_cast<const float4*>(&Bo[j*68 + tc*4]);
            u64 bbe[2] = {pk2(be.x,be.y), pk2(be.z,be.w)};
            u64 bbo[2] = {pk2(bo.x,bo.y), pk2(bo.z,bo.w)};
            float ae[8] = {e0.x,e0.y,e0.z,e0.w,e1.x,e1.y,e1.z,e1.w};
            float ao[8] = {o0.x,o0.y,o0.z,o0.w,o1.x,o1.y,o1.z,o1.w};
            #pragma unroll
            for (int p = 0; p < 8; p++) {
                u64 aaE = dup2(ae[p]);
                fma2(acc2E[p][0], aaE, bbe[0]);
                fma2(acc2E[p][1], aaE, bbe[1]);
                u64 aaO = dup2(ao[p]);
                fma2(acc2O[p][0], aaO, bbo[0]);
                fma2(acc2O[p][1], aaO, bbo[1]);
            }
        }
        if (more) {
            A_TSTORE(AeS[cur ^ 1], ane);
            { float* buf = AoS[cur ^ 1];
              buf[(ak4+0)*132+am] = ano.x; buf[(ak4+1)*132+am] = ano.y;
              buf[(ak4+2)*132+am] = ano.z; buf[(ak4+3)*132+am] = ano.w; }
            if (isBo) *reinterpret_cast<float4*>(&BoS[cur ^ 1][blr * 68 + bn4]) = bn_;
            else      *reinterpret_cast<float4*>(&BeS[cur ^ 1][blr * 68 + bn4]) = bn_;
            __syncthreads();
        }
    }
    #pragma unroll
    for (int ph = 0; ph < 2; ph++)
        #pragma unroll
        for (int e = 0; e < 4; e++) {
            int p = ph * 4 + e;
            int k = ph * 64 + tn * 4 + e;
            float2 E0 = un2(acc2E[p][0]), E1 = un2(acc2E[p][1]);
            float2 O0 = un2(acc2O[p][0]), O1 = un2(acc2O[p][1]);
            float* base = &d_rr[(size_t)mri * NROW];
            *reinterpret_cast<float4*>(base + (size_t)k * 256 + bo0 + tc * 4) =
                make_float4(E0.x + O0.x, E0.y + O0.y, E1.x + O1.x, E1.y + O1.y);
            *reinterpret_cast<float4*>(base + (size_t)(255 - k) * 256 + bo0 + tc * 4) =
                make_float4(E0.x - O0.x, E0.y - O0.y, E1.x - O1.x, E1.y - O1.y);
        }
}

__global__ __launch_bounds__(256, 2) void k_g5f(float* __restrict__ out) {
    __shared__ float AeS[2][8 * 132];
    __shared__ float AoS[2][8 * 132];
    __shared__ float BcS[2][8 * 68];
    __shared__ float BsS[2][8 * 68];
    int t = threadIdx.x;
    int col0 = blockIdx.x * 128;
    int j0   = blockIdx.y * 64;
    int ar = t >> 5, ac4 = (t & 31) * 4;
    int mr = (t & 127) >> 4, jc = t & 15;
    int tc = t & 15, tn = t >> 4;
    float4 ave = *reinterpret_cast<const float4*>(&d_rr[(size_t)(2 * ar) * NROW + col0 + ac4]);
    float4 avo = *reinterpret_cast<const float4*>(&d_rr[(size_t)(2 * ar + 1) * NROW + col0 + ac4]);
    float4 bvx;
    if (t < 128) bvx = *reinterpret_cast<const float4*>(&d_Gc[mr * 128 + j0 + jc * 4]);
    else         bvx = *reinterpret_cast<const float4*>(&d_Gs[mr * 128 + j0 + jc * 4]);
    *reinterpret_cast<float4*>(&AeS[0][ar * 132 + ac4]) = ave;
    *reinterpret_cast<float4*>(&AoS[0][ar * 132 + ac4]) = avo;
    if (t < 128) *reinterpret_cast<float4*>(&BcS[0][mr * 68 + jc * 4]) = bvx;
    else         *reinterpret_cast<float4*>(&BsS[0][mr * 68 + jc * 4]) = bvx;
    __syncthreads();
    u64 acc2C[8][2] = {};
    u64 acc2S[8][2] = {};
    for (int kt = 0; kt < 16; kt++) {
        int cur = kt & 1;
        bool more = (kt + 1 < 16);
        float4 ane, ano, bn_;
        if (more) {
            int m0 = (kt + 1) * 8;
            ane = *reinterpret_cast<const float4*>(&d_rr[(size_t)(2 * (m0 + ar)) * NROW + col0 + ac4]);
            ano = *reinterpret_cast<const float4*>(&d_rr[(size_t)(2 * (m0 + ar) + 1) * NROW + col0 + ac4]);
            if (t < 128) bn_ = *reinterpret_cast<const float4*>(&d_Gc[(m0 + mr) * 128 + j0 + jc * 4]);
            else         bn_ = *reinterpret_cast<const float4*>(&d_Gs[(m0 + mr) * 128 + j0 + jc * 4]);
        }
        const float* Ae = AeS[cur]; const float* Ao = AoS[cur];
        const float* Bc = BcS[cur]; const float* Bss = BsS[cur];
        #pragma unroll
        for (int j = 0; j < 8; j++) {
            float4 e0 = *reinterpret_cast<const float4*>(&Ae[j * 132 + tn * 4]);
            float4 e1 = *reinterpret_cast<const float4*>(&Ae[j * 132 + tn * 4 + 64]);
            float4 o0 = *reinterpret_cast<const float4*>(&Ao[j * 132 + tn * 4]);
            float4 o1 = *reinterpret_cast<const float4*>(&Ao[j * 132 + tn * 4 + 64]);
            float4 cc = *reinterpret_cast<const float4*>(&Bc[j * 68 + tc * 4]);
            float4 ss = *reinterpret_cast<const float4*>(&Bss[j * 68 + tc * 4]);
            u64 bbc[2] = {pk2(cc.x,cc.y), pk2(cc.z,cc.w)};
            u64 bbs[2] = {pk2(ss.x,ss.y), pk2(ss.z,ss.w)};
            float ae[8] = {e0.x,e0.y,e0.z,e0.w,e1.x,e1.y,e1.z,e1.w};
            float ao[8] = {o0.x,o0.y,o0.z,o0.w,o1.x,o1.y,o1.z,o1.w};
            #pragma unroll
            for (int p = 0; p < 8; p++) {
                u64 aaC = dup2(ae[p]);
                fma2(acc2C[p][0], aaC, bbc[0]);
                fma2(acc2C[p][1], aaC, bbc[1]);
                u64 aaS = dup2(ao[p]);
                fma2(acc2S[p][0], aaS, bbs[0]);
                fma2(acc2S[p][1], aaS, bbs[1]);
            }
        }
        if (more) {
            *reinterpret_cast<float4*>(&AeS[cur ^ 1][ar * 132 + ac4]) = ane;
            *reinterpret_cast<float4*>(&AoS[cur ^ 1][ar * 132 + ac4]) = ano;
            if (t < 128) *reinterpret_cast<float4*>(&BcS[cur ^ 1][mr * 68 + jc * 4]) = bn_;
            else         *reinterpret_cast<float4*>(&BsS[cur ^ 1][mr * 68 + jc * 4]) = bn_;
            __syncthreads();
        }
    }
    int jj0 = j0 + tc * 4;
    #pragma unroll
    for (int ph = 0; ph < 2; ph++)
        #pragma unroll
        for (int e = 0; e < 4; e++) {
            int p = ph * 4 + e;
            int col = col0 + ph * 64 + tn * 4 + e;
            int bo = col & 255, k = col >> 8;
            float2 C0 = un2(acc2C[p][0]), C1 = un2(acc2C[p][1]);
            float2 S0 = un2(acc2S[p][0]), S1 = un2(acc2S[p][1]);
            float cA[4] = {C0.x, C0.y, C1.x, C1.y};
            float sA[4] = {S0.x, S0.y, S1.x, S1.y};
            float* base = &out[(size_t)bo * 65536 + (size_t)k * 256];
            *reinterpret_cast<float4*>(base + jj0) =
                make_float4(cA[0] - sA[0], cA[1] - sA[1], cA[2] - sA[2], cA[3] - sA[3]);
            #pragma unroll
            for (int q = 0; q < 4; q++) {
                int jj = jj0 + q;
                if (jj > 0) base[256 - jj] = cA[q] + sA[q];
            }
        }
}

__global__ __launch_bounds__(256) void k_y128(float* __restrict__ out) {
    int col = blockIdx.x * 256 + threadIdx.x;
    float acc = 0.f;
    #pragma unroll
    for (int m = 0; m < 128; m++) {
        float g = (m == 0) ? 1.f : ((m & 1) ? -2.f : 2.f);
        acc += g * d_rr[(size_t)(2 * m) * NROW + col];
    }
    int bo = col & 255, k = col >> 8;
    out[(size_t)bo * 65536 + (size_t)k * 256 + 128] = acc;
}

// ---------------------------------------------------------------------------
extern "C" void kernel_launch(void* const* d_in, const int* in_sizes, int n_in,
                              void* d_out, int out_size) {
    const float* x = (const float*)d_in[0];
    const float* w = (const float*)d_in[1];
    float* out = (float*)d_out;

    k_quad<<<256, 128>>>();
    k_tab<<<128, 128>>>();
    k_legendre<<<128, 128>>>();

    k_fold<<<2048, 256>>>(x);
    k_g1p<0><<<512, 256>>>();      // Re rows
    k_g1p<1><<<512, 256>>>();      // Im rows
    dim3 g2(2, 256);   k_g2f<<<g2, 256>>>();
    k_mix<<<NX / 8, 256>>>(w);
    dim3 g4(4, 256);   k_g4f<<<g4, 256>>>();
    dim3 g5(512, 2);   k_g5f<<<g5, 256>>>(out);
    k_y128<<<256, 256>>>(out);
}

// round 15
// speedup vs baseline: 1.9782x; 1.0632x over previous
#include <cuda_runtime.h>
#include <math.h>
#include <stdint.h>

#define NLAT  256
#define LMAX  128
#define NM    256
#define NX    33024
#define NROW  65536
#define KEPAD 136
#define KQ    72

typedef unsigned long long u64;
__device__ __forceinline__ u64 pk2(float x, float y) {
    u64 r; asm("mov.b64 %0, {%1, %2};" : "=l"(r) : "f"(x), "f"(y)); return r;
}
__device__ __forceinline__ u64 dup2(float x) { return pk2(x, x); }
__device__ __forceinline__ void fma2(u64 &d, u64 a, u64 b) {
    asm("fma.rn.f32x2 %0, %1, %2, %3;" : "=l"(d) : "l"(a), "l"(b), "l"(d));
}
__device__ __forceinline__ float2 un2(u64 v) {
    float2 f; asm("mov.b64 {%0, %1}, %2;" : "=f"(f.x), "=f"(f.y) : "l"(v)); return f;
}

// --------------------------- device scratch --------------------------------
__device__ float d_wq[NLAT];
__device__ float d_Tc2[128 * KQ];
__device__ float d_Ts2[128 * KQ];
__device__ float d_G5t[4 * 64 * 64];   // [tbl][q][j]; tbl 0:cos even-m 1:sin even 2:cos odd 3:sin odd
__device__ float d_PCTW2[(size_t)LMAX * 128 * 128];
__device__ float d_PCTT2[(size_t)LMAX * 128 * 128];
__device__ float d_xe[(size_t)KEPAD * NROW];
__device__ float d_xo[(size_t)KEPAD * NROW];
__device__ float d_xh  [(size_t)NM * NROW];
__device__ float d_spec[(size_t)NX * 256];
__device__ float d_out2[(size_t)NX * 256];
__device__ float d_rr  [(size_t)NM * NROW];

// --------------------------- setup ---------------------------------
__global__ __launch_bounds__(128) void k_quad() {
    int j = blockIdx.x, k = threadIdx.x;
    double tj = M_PI * (double)j / 255.0, v = 0.0;
    if (k >= 1) v = cos(2.0 * tj * (double)k) * (2.0 / (4.0 * (double)k * k - 1.0));
    __shared__ double red[128];
    red[k] = v; __syncthreads();
    for (int s = 64; s > 0; s >>= 1) { if (k < s) red[k] += red[k + s]; __syncthreads(); }
    if (k == 0) {
        double c = (j == 0 || j == 255) ? 1.0 : 2.0;
        d_wq[j] = (float)(c / 255.0 * (1.0 - red[0]));
    }
}

__global__ __launch_bounds__(128) void k_tab() {
    int li = blockIdx.x;                    // 0..127
    int j  = threadIdx.x;                   // 0..127
    const float sc = (float)(2.0 * M_PI / 256.0);
    if (j < KQ) {   // quarter-folded G1 tables
        int m = (li < 64) ? (2 * li) : (2 * (li - 64) + 1);
        int r = (m * j) & 255;
        float s, c;
        sincosf(sc * (float)r, &s, &c);
        float tc = (j <= 64) ? sc * c : 0.f;
        float ts = (j >= 1 && j <= 64) ? -sc * s : 0.f;
        if (j == 64) { tc *= 0.5f; ts *= 0.5f; }
        d_Tc2[li * KQ + j] = tc;
        d_Ts2[li * KQ + j] = ts;
    }
    if (li < 64 && j < 64) {   // quarter-folded G5 tables, q = li
        int q = li;
        float se, ce, so, co;
        sincosf(sc * (float)((2 * q * j) & 255), &se, &ce);
        sincosf(sc * (float)(((2 * q + 1) * j) & 255), &so, &co);
        float we = (q == 0) ? 1.f : 2.f;
        d_G5t[0 * 4096 + q * 64 + j] = we * ce;
        d_G5t[1 * 4096 + q * 64 + j] = we * se;
        d_G5t[2 * 4096 + q * 64 + j] = 2.f * co;
        d_G5t[3 * 4096 + q * 64 + j] = 2.f * so;
    }
}

__global__ __launch_bounds__(128) void k_legendre() {
    int m = blockIdx.x, kk = threadIdx.x;
    __shared__ double s_a[LMAX], s_b[LMAX];
    __shared__ double s_sect;
    {
        int l = kk;
        if (l >= m + 2) {
            double fl = (double)l, fm = (double)m, g = fl - 1.0;
            s_a[l] = sqrt((4.0 * fl * fl - 1.0) / (fl * fl - fm * fm));
            s_b[l] = sqrt((g * g - fm * fm) / (4.0 * g * g - 1.0));
        }
    }
    if (kk == 0) {
        double pr = 1.0;
        for (int i = 1; i <= m; i++) pr *= (2.0 * i + 1.0) / (2.0 * i);
        s_sect = sqrt(pr);
    }
    __syncthreads();
    double tt = M_PI * (double)kk / 255.0;
    double ct = cos(tt), st = sin(tt), w = (double)d_wq[kk];
    size_t baseW = (size_t)m * 128 * 128;
    size_t baseT = (size_t)m * 128 * 128 + (size_t)kk * 128;
    for (int l = 0; l < m; l++) {
        int li = (((l + m) & 1) << 6) | (l >> 1);
        d_PCTW2[baseW + (size_t)li * 128 + kk] = 0.f;
        d_PCTT2[baseT + li] = 0.f;
    }
    double powv = 1.0;
    for (int i = 0; i < m; i++) powv *= -st;
    double p2 = 0.28209479177387814347 * s_sect * powv;
    {
        int li = (m >> 1);
        d_PCTW2[baseW + (size_t)li * 128 + kk] = (float)(p2 * w);
        d_PCTT2[baseT + li] = (float)p2;
    }
    if (m + 1 < LMAX) {
        double p1 = sqrt(2.0 * m + 3.0) * ct * p2;
        {
            int li = 64 + ((m + 1) >> 1);
            d_PCTW2[baseW + (size_t)li * 128 + kk] = (float)(p1 * w);
            d_PCTT2[baseT + li] = (float)p1;
        }
        for (int l = m + 2; l < LMAX; l++) {
            double p = s_a[l] * (ct * p1 - s_b[l] * p2);
            int li = (((l + m) & 1) << 6) | (l >> 1);
            d_PCTW2[baseW + (size_t)li * 128 + kk] = (float)(p * w);
            d_PCTT2[baseT + li] = (float)p;
            p2 = p1; p1 = p;
        }
    }
}

__global__ __launch_bounds__(256) void k_fold(const float* __restrict__ x) {
    __shared__ float s[32][257];
    int t = threadIdx.x;
    int col0 = blockIdx.x * 32;
    int klat = col0 >> 8;
    int bc0  = col0 & 255;
    #pragma unroll 4
    for (int r = 0; r < 32; r++)
        s[r][t] = x[(size_t)(bc0 + r) * 65536 + klat * 256 + t];
    __syncthreads();
    #pragma unroll 4
    for (int it = 0; it < 16; it++) {
        int idx = it * 256 + t;
        int j = idx >> 5, c = idx & 31;
        float a = s[c][j];
        float b = s[c][(256 - j) & 255];
        float xe = (j == 0) ? a : a + b;
        float xo = (j == 0) ? 0.f : a - b;
        d_xe[(size_t)j * NROW + col0 + c] = xe;
        d_xo[(size_t)j * NROW + col0 + c] = xo;
    }
    if (t < 32) d_xe[(size_t)128 * NROW + col0 + t] = s[t][128];
}

#define A_TSTORE(buf, v) \
    do { (buf)[(ak4+0)*132+am] = (v).x; (buf)[(ak4+1)*132+am] = (v).y; \
         (buf)[(ak4+2)*132+am] = (v).z; (buf)[(ak4+3)*132+am] = (v).w; } while(0)

// ---------------------------------------------------------------------------
// G1 quarter-folded (proven R14)
// ---------------------------------------------------------------------------
template<int IM>
__global__ __launch_bounds__(256, 2) void k_g1p() {
    __shared__ float Ast[2][8 * 132];
    __shared__ float BpS[2][8 * 132];
    __shared__ float BmS[2][8 * 132];
    int t = threadIdx.x;
    int col0 = blockIdx.x * 128;
    const float* A = IM ? d_Ts2 : d_Tc2;
    const float* B = IM ? d_xo : d_xe;
    int am = t >> 1, ak4 = (t & 1) * 4;
    int bk = t >> 5, bn4 = (t & 31) * 4;
    int tc = t & 15, tn = t >> 4;
    float4 av = *reinterpret_cast<const float4*>(&A[am * KQ + ak4]);
    float4 bt = *reinterpret_cast<const float4*>(&B[(size_t)bk * NROW + col0 + bn4]);
    float4 bb = *reinterpret_cast<const float4*>(&B[(size_t)(128 - bk) * NROW + col0 + bn4]);
    A_TSTORE(Ast[0], av);
    *reinterpret_cast<float4*>(&BpS[0][bk * 132 + bn4]) =
        make_float4(bt.x + bb.x, bt.y + bb.y, bt.z + bb.z, bt.w + bb.w);
    *reinterpret_cast<float4*>(&BmS[0][bk * 132 + bn4]) =
        make_float4(bt.x - bb.x, bt.y - bb.y, bt.z - bb.z, bt.w - bb.w);
    __syncthreads();
    u64 acc2[8][4] = {};
    for (int kt = 0; kt < 9; kt++) {
        int cur = kt & 1;
        bool more = (kt + 1 < 9);
        float4 an, btn, bbn;
        if (more) {
            int k0 = (kt + 1) * 8;
            an  = *reinterpret_cast<const float4*>(&A[am * KQ + k0 + ak4]);
            btn = *reinterpret_cast<const float4*>(&B[(size_t)(k0 + bk) * NROW + col0 + bn4]);
            bbn = *reinterpret_cast<const float4*>(&B[(size_t)(128 - k0 - bk) * NROW + col0 + bn4]);
        }
        const float* Ap = Ast[cur];
        const float* Bev = IM ? BmS[cur] : BpS[cur];
        const float* Bod = IM ? BpS[cur] : BmS[cur];
        #pragma unroll
        for (int j = 0; j < 8; j++) {
            {
                float4 a0 = *reinterpret_cast<const float4*>(&Ap[j*132 + tn*4]);
                float4 b0 = *reinterpret_cast<const float4*>(&Bev[j*132 + tc*4]);
                float4 b1 = *reinterpret_cast<const float4*>(&Bev[j*132 + tc*4 + 64]);
                u64 bbv[4] = {pk2(b0.x,b0.y), pk2(b0.z,b0.w), pk2(b1.x,b1.y), pk2(b1.z,b1.w)};
                float ar[4] = {a0.x,a0.y,a0.z,a0.w};
                #pragma unroll
                for (int p = 0; p < 4; p++) {
                    u64 aa = dup2(ar[p]);
                    #pragma unroll
                    for (int q = 0; q < 4; q++) fma2(acc2[p][q], aa, bbv[q]);
                }
            }
            {
                float4 a1 = *reinterpret_cast<const float4*>(&Ap[j*132 + tn*4 + 64]);
                float4 b0 = *reinterpret_cast<const float4*>(&Bod[j*132 + tc*4]);
                float4 b1 = *reinterpret_cast<const float4*>(&Bod[j*132 + tc*4 + 64]);
                u64 bbv[4] = {pk2(b0.x,b0.y), pk2(b0.z,b0.w), pk2(b1.x,b1.y), pk2(b1.z,b1.w)};
                float ar[4] = {a1.x,a1.y,a1.z,a1.w};
                #pragma unroll
                for (int p = 0; p < 4; p++) {
                    u64 aa = dup2(ar[p]);
                    #pragma unroll
                    for (int q = 0; q < 4; q++) fma2(acc2[4 + p][q], aa, bbv[q]);
                }
            }
        }
        if (more) {
            A_TSTORE(Ast[cur ^ 1], an);
            *reinterpret_cast<float4*>(&BpS[cur ^ 1][bk * 132 + bn4]) =
                make_float4(btn.x + bbn.x, btn.y + bbn.y, btn.z + bbn.z, btn.w + bbn.w);
            *reinterpret_cast<float4*>(&BmS[cur ^ 1][bk * 132 + bn4]) =
                make_float4(btn.x - bbn.x, btn.y - bbn.y, btn.z - bbn.z, btn.w - bbn.w);
            __syncthreads();
        }
    }
    #pragma unroll
    for (int ph = 0; ph < 2; ph++)
        #pragma unroll
        for (int e = 0; e < 4; e++) {
            int le = tn * 4 + e;
            int xr = (ph == 0) ? (4 * le + IM) : (4 * le + 2 + IM);
            int p = ph * 4 + e;
            float2 c0 = un2(acc2[p][0]), c1 = un2(acc2[p][1]);
            float2 c2 = un2(acc2[p][2]), c3 = un2(acc2[p][3]);
            float* dst = &d_xh[(size_t)xr * NROW + col0];
            *reinterpret_cast<float4*>(dst + tc * 4)      = make_float4(c0.x, c0.y, c1.x, c1.y);
            *reinterpret_cast<float4*>(dst + tc * 4 + 64) = make_float4(c2.x, c2.y, c3.x, c3.y);
        }
}

// ---------------------------------------------------------------------------
// G2 latitude-folded (proven)
// ---------------------------------------------------------------------------
__global__ __launch_bounds__(256, 2) void k_g2f() {
    __shared__ float Ast[2][8 * 132];
    __shared__ float BeS[2][8 * 132];
    __shared__ float BoS[2][8 * 132];
    int t = threadIdx.x;
    int bc0 = blockIdx.x * 128;
    int mri = blockIdx.y;
    int m = mri >> 1, ri = mri & 1, par0 = m & 1;
    const float* A = d_PCTW2 + (size_t)m * 128 * 128;
    const float* B = d_xh + (size_t)mri * NROW;
    int am = t >> 1, ak4 = (t & 1) * 4;
    int bk = t >> 5, bn4 = (t & 31) * 4;
    int tc = t & 15, tn = t >> 4;
    float4 av = *reinterpret_cast<const float4*>(&A[am * 128 + ak4]);
    float4 bt = *reinterpret_cast<const float4*>(&B[(size_t)bk * 256 + bc0 + bn4]);
    float4 bb = *reinterpret_cast<const float4*>(&B[(size_t)(255 - bk) * 256 + bc0 + bn4]);
    A_TSTORE(Ast[0], av);
    *reinterpret_cast<float4*>(&BeS[0][bk * 132 + bn4]) =
        make_float4(bt.x + bb.x, bt.y + bb.y, bt.z + bb.z, bt.w + bb.w);
    *reinterpret_cast<float4*>(&BoS[0][bk * 132 + bn4]) =
        make_float4(bt.x - bb.x, bt.y - bb.y, bt.z - bb.z, bt.w - bb.w);
    __syncthreads();
    u64 acc2[8][4] = {};
    for (int kt = 0; kt < 16; kt++) {
        int cur = kt & 1;
        bool more = (kt + 1 < 16);
        float4 an, btn, bbn;
        if (more) {
            int k0 = (kt + 1) * 8;
            an  = *reinterpret_cast<const float4*>(&A[am * 128 + k0 + ak4]);
            btn = *reinterpret_cast<const float4*>(&B[(size_t)(k0 + bk) * 256 + bc0 + bn4]);
            bbn = *reinterpret_cast<const float4*>(&B[(size_t)(255 - k0 - bk) * 256 + bc0 + bn4]);
        }
        const float* Ap = Ast[cur];
        const float* Be = BeS[cur];
        const float* Bo = BoS[cur];
        #pragma unroll
        for (int j = 0; j < 8; j++) {
            {
                float4 a0 = *reinterpret_cast<const float4*>(&Ap[j*132 + tn*4]);
                float4 b0 = *reinterpret_cast<const float4*>(&Be[j*132 + tc*4]);
                float4 b1 = *reinterpret_cast<const float4*>(&Be[j*132 + tc*4 + 64]);
                u64 bbv[4] = {pk2(b0.x,b0.y), pk2(b0.z,b0.w), pk2(b1.x,b1.y), pk2(b1.z,b1.w)};
                float ar[4] = {a0.x,a0.y,a0.z,a0.w};
                #pragma unroll
                for (int p = 0; p < 4; p++) {
                    u64 aa = dup2(ar[p]);
                    #pragma unroll
                    for (int q = 0; q < 4; q++) fma2(acc2[p][q], aa, bbv[q]);
                }
            }
            {
                float4 a1 = *reinterpret_cast<const float4*>(&Ap[j*132 + tn*4 + 64]);
                float4 b0 = *reinterpret_cast<const float4*>(&Bo[j*132 + tc*4]);
                float4 b1 = *reinterpret_cast<const float4*>(&Bo[j*132 + tc*4 + 64]);
                u64 bbv[4] = {pk2(b0.x,b0.y), pk2(b0.z,b0.w), pk2(b1.x,b1.y), pk2(b1.z,b1.w)};
                float ar[4] = {a1.x,a1.y,a1.z,a1.w};
                #pragma unroll
                for (int p = 0; p < 4; p++) {
                    u64 aa = dup2(ar[p]);
                    #pragma unroll
                    for (int q = 0; q < 4; q++) fma2(acc2[4 + p][q], aa, bbv[q]);
                }
            }
        }
        if (more) {
            A_TSTORE(Ast[cur ^ 1], an);
            *reinterpret_cast<float4*>(&BeS[cur ^ 1][bk * 132 + bn4]) =
                make_float4(btn.x + bbn.x, btn.y + bbn.y, btn.z + bbn.z, btn.w + bbn.w);
            *reinterpret_cast<float4*>(&BoS[cur ^ 1][bk * 132 + bn4]) =
                make_float4(btn.x - bbn.x, btn.y - bbn.y, btn.z - bbn.z, btn.w - bbn.w);
            __syncthreads();
        }
    }
    #pragma unroll
    for (int ph = 0; ph < 2; ph++)
        #pragma unroll
        for (int e = 0; e < 4; e++) {
            int le = tn * 4 + e;
            int l = (ph == 0) ? (2 * le + par0) : (2 * le + 1 - par0);
            size_t xrow = ((size_t)l * 129 + m) * 2 + ri;
            int p = ph * 4 + e;
            float2 c0 = un2(acc2[p][0]), c1 = un2(acc2[p][1]);
            float2 c2 = un2(acc2[p][2]), c3 = un2(acc2[p][3]);
            float* dst = &d_spec[xrow * 256 + bc0];
            *reinterpret_cast<float4*>(dst + tc * 4)      = make_float4(c0.x, c0.y, c1.x, c1.y);
            *reinterpret_cast<float4*>(dst + tc * 4 + 64) = make_float4(c2.x, c2.y, c3.x, c3.y);
        }
}

__global__ __launch_bounds__(256) void k_mix(const float* __restrict__ W) {
    __shared__ float Ws[8 * 1028];
    __shared__ float Ss[8 * 256];
    int t = threadIdx.x;
    int x0 = blockIdx.x * 8;
    #pragma unroll
    for (int rep = 0; rep < 32; rep++) {
        int idx = rep * 256 + t;
        int xl = idx & 7, io = idx >> 3;
        Ws[xl * 1028 + io] = W[(size_t)io * NX + x0 + xl];
    }
    #pragma unroll
    for (int rep = 0; rep < 8; rep++) {
        int idx = rep * 256 + t;
        int xl = idx >> 8, bc = idx & 255;
        Ss[xl * 256 + bc] = d_spec[(size_t)(x0 + xl) * 256 + bc];
    }
    __syncthreads();
    int b = t >> 5, o = t & 31;
    float acc[8] = {};
    #pragma unroll
    for (int xl = 0; xl < 8; xl++)
        #pragma unroll
        for (int i = 0; i < 32; i++)
            acc[xl] += Ss[xl * 256 + b * 32 + i] * Ws[xl * 1028 + i * 32 + o];
    #pragma unroll
    for (int xl = 0; xl < 8; xl++)
        d_out2[(size_t)(x0 + xl) * 256 + t] = acc[xl];
}

__global__ __launch_bounds__(256, 2) void k_g4f() {
    __shared__ float AeS[2][8 * 132];
    __shared__ float AoS[2][8 * 132];
    __shared__ float BeS[2][8 * 68];
    __shared__ float BoS[2][8 * 68];
    int t = threadIdx.x;
    int bo0 = blockIdx.x * 64;
    int mri = blockIdx.y;
    int m = mri >> 1, ri = mri & 1, par0 = m & 1;
    const float* A = d_PCTT2 + (size_t)m * 128 * 128;
    int am = t >> 1, ak4 = (t & 1) * 4;
    int blr = (t & 127) >> 4, bn4 = (t & 15) * 4;
    int isBo = t >> 7;
    int tc = t & 15, tn = t >> 4;
    float4 ave = *reinterpret_cast<const float4*>(&A[am * 128 + ak4]);
    float4 avo = *reinterpret_cast<const float4*>(&A[am * 128 + 64 + ak4]);
    float4 bv;
    {
        int l = 2 * blr + (isBo ? (1 - par0) : par0);
        size_t xrow = ((size_t)l * 129 + m) * 2 + ri;
        bv = *reinterpret_cast<const float4*>(&d_out2[xrow * 256 + bo0 + bn4]);
    }
    A_TSTORE(AeS[0], ave);
    { float* buf = AoS[0];
      buf[(ak4+0)*132+am] = avo.x; buf[(ak4+1)*132+am] = avo.y;
      buf[(ak4+2)*132+am] = avo.z; buf[(ak4+3)*132+am] = avo.w; }
    if (isBo) *reinterpret_cast<float4*>(&BoS[0][blr * 68 + bn4]) = bv;
    else      *reinterpret_cast<float4*>(&BeS[0][blr * 68 + bn4]) = bv;
    __syncthreads();
    u64 acc2E[8][2] = {};
    u64 acc2O[8][2] = {};
    for (int lt = 0; lt < 8; lt++) {
        int cur = lt & 1;
        bool more = (lt + 1 < 8);
        float4 ane, ano, bn_;
        if (more) {
            int l0 = (lt + 1) * 8;
            ane = *reinterpret_cast<const float4*>(&A[am * 128 + l0 + ak4]);
            ano = *reinterpret_cast<const float4*>(&A[am * 128 + 64 + l0 + ak4]);
            int l = 2 * (l0 + blr) + (isBo ? (1 - par0) : par0);
            size_t xrow = ((size_t)l * 129 + m) * 2 + ri;
            bn_ = *reinterpret_cast<const float4*>(&d_out2[xrow * 256 + bo0 + bn4]);
        }
        const float* Ae = AeS[cur]; const float* Ao = AoS[cur];
        const float* Be = BeS[cur]; const float* Bo = BoS[cur];
        #pragma unroll
        for (int j = 0; j < 8; j++) {
            float4 e0 = *reinterpret_cast<const float4*>(&Ae[j*132 + tn*4]);
            float4 e1 = *reinterpret_cast<const float4*>(&Ae[j*132 + tn*4 + 64]);
            float4 o0 = *reinterpret_cast<const float4*>(&Ao[j*132 + tn*4]);
            float4 o1 = *reinterpret_cast<const float4*>(&Ao[j*132 + tn*4 + 64]);
            float4 be = *reinterpret_cast<const float4*>(&Be[j*68 + tc*4]);
            float4 bo = *reinterpret_cast<const float4*>(&Bo[j*68 + tc*4]);
            u64 bbe[2] = {pk2(be.x,be.y), pk2(be.z,be.w)};
            u64 bbo[2] = {pk2(bo.x,bo.y), pk2(bo.z,bo.w)};
            float ae[8] = {e0.x,e0.y,e0.z,e0.w,e1.x,e1.y,e1.z,e1.w};
            float ao[8] = {o0.x,o0.y,o0.z,o0.w,o1.x,o1.y,o1.z,o1.w};
            #pragma unroll
            for (int p = 0; p < 8; p++) {
                u64 aaE = dup2(ae[p]);
                fma2(acc2E[p][0], aaE, bbe[0]);
                fma2(acc2E[p][1], aaE, bbe[1]);
                u64 aaO = dup2(ao[p]);
                fma2(acc2O[p][0], aaO, bbo[0]);
                fma2(acc2O[p][1], aaO, bbo[1]);
            }
        }
        if (more) {
            A_TSTORE(AeS[cur ^ 1], ane);
            { float* buf = AoS[cur ^ 1];
              buf[(ak4+0)*132+am] = ano.x; buf[(ak4+1)*132+am] = ano.y;
              buf[(ak4+2)*132+am] = ano.z; buf[(ak4+3)*132+am] = ano.w; }
            if (isBo) *reinterpret_cast<float4*>(&BoS[cur ^ 1][blr * 68 + bn4]) = bn_;
            else      *reinterpret_cast<float4*>(&BeS[cur ^ 1][blr * 68 + bn4]) = bn_;
            __syncthreads();
        }
    }
    #pragma unroll
    for (int ph = 0; ph < 2; ph++)
        #pragma unroll
        for (int e = 0; e < 4; e++) {
            int p = ph * 4 + e;
            int k = ph * 64 + tn * 4 + e;
            float2 E0 = un2(acc2E[p][0]), E1 = un2(acc2E[p][1]);
            float2 O0 = un2(acc2O[p][0]), O1 = un2(acc2O[p][1]);
            float* base = &d_rr[(size_t)mri * NROW];
            *reinterpret_cast<float4*>(base + (size_t)k * 256 + bo0 + tc * 4) =
                make_float4(E0.x + O0.x, E0.y + O0.y, E1.x + O1.x, E1.y + O1.y);
            *reinterpret_cast<float4*>(base + (size_t)(255 - k) * 256 + bo0 + tc * 4) =
                make_float4(E0.x - O0.x, E0.y - O0.y, E1.x - O1.x, E1.y - O1.y);
        }
}

// ---------------------------------------------------------------------------
// G5 quarter-folded: block = 64 cols x 64 j, K = 64 q x 4 parity/ri sets.
//   acc[g]: g=0 Ce (rr[4q] x cosE), 1 Se (rr[4q+1] x sinE),
//           2 Co (rr[4q+2] x cosO), 3 So (rr[4q+3] x sinO)
//   y[j]=(Ce+Co)-(Se+So); y[256-j]=(Ce+Co)+(Se+So) (j>0);
//   y[128-j]=(Ce-Co)+(Se-So); y[128+j]=(Ce-Co)-(Se-So)
// ---------------------------------------------------------------------------
__global__ __launch_bounds__(256, 2) void k_g5q(float* __restrict__ out) {
    __shared__ float As[2][4][8 * 68];
    __shared__ float Bs[2][4][8 * 68];
    int t = threadIdx.x;
    int col0 = blockIdx.x * 64;
    int tc = t & 15, tn = t >> 4;
    #pragma unroll
    for (int it = 0; it < 2; it++) {
        int idx = it * 256 + t;
        int row = idx >> 4, c4 = (idx & 15) * 4;
        int g = row & 3, ql = row >> 2;
        float4 av = *reinterpret_cast<const float4*>(&d_rr[(size_t)(4 * ql + g) * NROW + col0 + c4]);
        *reinterpret_cast<float4*>(&As[0][g][ql * 68 + c4]) = av;
        float4 bv = *reinterpret_cast<const float4*>(&d_G5t[g * 4096 + ql * 64 + c4]);
        *reinterpret_cast<float4*>(&Bs[0][g][ql * 68 + c4]) = bv;
    }
    __syncthreads();
    u64 acc[4][4][2] = {};
    for (int kt = 0; kt < 8; kt++) {
        int cur = kt & 1;
        bool more = (kt + 1 < 8);
        float4 pa[2], pb[2];
        if (more) {
            int q0 = (kt + 1) * 8;
            #pragma unroll
            for (int it = 0; it < 2; it++) {
                int idx = it * 256 + t;
                int row = idx >> 4, c4 = (idx & 15) * 4;
                int g = row & 3, ql = row >> 2;
                pa[it] = *reinterpret_cast<const float4*>(&d_rr[(size_t)(4 * (q0 + ql) + g) * NROW + col0 + c4]);
                pb[it] = *reinterpret_cast<const float4*>(&d_G5t[g * 4096 + (q0 + ql) * 64 + c4]);
            }
        }
        #pragma unroll
        for (int q = 0; q < 8; q++) {
            #pragma unroll
            for (int g = 0; g < 4; g++) {
                float4 a = *reinterpret_cast<const float4*>(&As[cur][g][q * 68 + tn * 4]);
                float4 b = *reinterpret_cast<const float4*>(&Bs[cur][g][q * 68 + tc * 4]);
                u64 bb[2] = {pk2(b.x, b.y), pk2(b.z, b.w)};
                float ar[4] = {a.x, a.y, a.z, a.w};
                #pragma unroll
                for (int p = 0; p < 4; p++) {
                    u64 aa = dup2(ar[p]);
                    fma2(acc[g][p][0], aa, bb[0]);
                    fma2(acc[g][p][1], aa, bb[1]);
                }
            }
        }
        if (more) {
            #pragma unroll
            for (int it = 0; it < 2; it++) {
                int idx = it * 256 + t;
                int row = idx >> 4, c4 = (idx & 15) * 4;
                int g = row & 3, ql = row >> 2;
                *reinterpret_cast<float4*>(&As[cur ^ 1][g][ql * 68 + c4]) = pa[it];
                *reinterpret_cast<float4*>(&Bs[cur ^ 1][g][ql * 68 + c4]) = pb[it];
            }
            __syncthreads();
        }
    }
    int jb = tc * 4;
    #pragma unroll
    for (int p = 0; p < 4; p++) {
        int col = col0 + tn * 4 + p;
        int bo = col & 255, k = col >> 8;
        float* base = &out[(size_t)bo * 65536 + (size_t)k * 256];
        float2 Ce0 = un2(acc[0][p][0]), Ce1 = un2(acc[0][p][1]);
        float2 Se0 = un2(acc[1][p][0]), Se1 = un2(acc[1][p][1]);
        float2 Co0 = un2(acc[2][p][0]), Co1 = un2(acc[2][p][1]);
        float2 So0 = un2(acc[3][p][0]), So1 = un2(acc[3][p][1]);
        float Ce[4] = {Ce0.x, Ce0.y, Ce1.x, Ce1.y};
        float Se[4] = {Se0.x, Se0.y, Se1.x, Se1.y};
        float Co[4] = {Co0.x, Co0.y, Co1.x, Co1.y};
        float So[4] = {So0.x, So0.y, So1.x, So1.y};
        float yA[4], yB[4], yC[4], yD[4];
        #pragma unroll
        for (int q = 0; q < 4; q++) {
            float Cp = Ce[q] + Co[q], Cm = Ce[q] - Co[q];
            float Sp = Se[q] + So[q], Sm = Se[q] - So[q];
            yA[q] = Cp - Sp;
            yB[q] = Cp + Sp;
            yC[q] = Cm + Sm;
            yD[q] = Cm - Sm;
        }
        *reinterpret_cast<float4*>(base + jb) = make_float4(yA[0], yA[1], yA[2], yA[3]);
        *reinterpret_cast<float4*>(base + 128 + jb) = make_float4(yD[0], yD[1], yD[2], yD[3]);
        #pragma unroll
        for (int q = 0; q < 4; q++) {
            int j = jb + q;
            base[128 - j] = yC[q];
            if (j > 0) base[256 - j] = yB[q];
        }
    }
}

// y[64], y[192]: C=Σ_q w(-1)^q rr[4q], S=Σ_q 2(-1)^q rr[4q+3]
__global__ __launch_bounds__(256) void k_y64(float* __restrict__ out) {
    int col = blockIdx.x * 256 + threadIdx.x;
    float C = 0.f, S = 0.f;
    #pragma unroll
    for (int q = 0; q < 64; q++) {
        float sg = (q & 1) ? -1.f : 1.f;
        float w = (q == 0) ? 1.f : 2.f;
        C += w * sg * d_rr[(size_t)(4 * q) * NROW + col];
        S += 2.f * sg * d_rr[(size_t)(4 * q + 3) * NROW + col];
    }
    int bo = col & 255, k = col >> 8;
    float* base = &out[(size_t)bo * 65536 + (size_t)k * 256];
    base[64]  = C - S;
    base[192] = C + S;
}

// ---------------------------------------------------------------------------
extern "C" void kernel_launch(void* const* d_in, const int* in_sizes, int n_in,
                              void* d_out, int out_size) {
    const float* x = (const float*)d_in[0];
    const float* w = (const float*)d_in[1];
    float* out = (float*)d_out;

    k_quad<<<256, 128>>>();
    k_tab<<<128, 128>>>();
    k_legendre<<<128, 128>>>();

    k_fold<<<2048, 256>>>(x);
    k_g1p<0><<<512, 256>>>();
    k_g1p<1><<<512, 256>>>();
    dim3 g2(2, 256);   k_g2f<<<g2, 256>>>();
    k_mix<<<NX / 8, 256>>>(w);
    dim3 g4(4, 256);   k_g4f<<<g4, 256>>>();
    k_g5q<<<1024, 256>>>(out);
    k_y64<<<256, 256>>>(out);
}

// round 16
// speedup vs baseline: 2.3010x; 1.1632x over previous
#include <cuda_runtime.h>
#include <math.h>
#include <stdint.h>

#define NLAT  256
#define LMAX  128
#define NM    256
#define NX    33024
#define NROW  65536
#define KEPAD 136
#define KQ    72

typedef unsigned long long u64;
__device__ __forceinline__ u64 pk2(float x, float y) {
    u64 r; asm("mov.b64 %0, {%1, %2};" : "=l"(r) : "f"(x), "f"(y)); return r;
}
__device__ __forceinline__ u64 dup2(float x) { return pk2(x, x); }
__device__ __forceinline__ void fma2(u64 &d, u64 a, u64 b) {
    asm("fma.rn.f32x2 %0, %1, %2, %3;" : "=l"(d) : "l"(a), "l"(b), "l"(d));
}
__device__ __forceinline__ float2 un2(u64 v) {
    float2 f; asm("mov.b64 {%0, %1}, %2;" : "=f"(f.x), "=f"(f.y) : "l"(v)); return f;
}

// --------------------------- device scratch --------------------------------
__device__ float d_wq[NLAT];
__device__ float d_Tc2[128 * KQ];
__device__ float d_Ts2[128 * KQ];
__device__ float d_G5t[4 * 64 * 64];
__device__ float d_PCTW2[(size_t)LMAX * 128 * 128];
__device__ float d_PCTT2[(size_t)LMAX * 128 * 128];
__device__ float d_xe[(size_t)KEPAD * NROW];
__device__ float d_xo[(size_t)KEPAD * NROW];
__device__ float d_xh  [(size_t)NM * NROW];
__device__ float d_spec[(size_t)NX * 256];
__device__ float d_out2[(size_t)NX * 256];   // rows with l<m stay 0 (never written)
__device__ float d_rr  [(size_t)NM * NROW];

// --------------------------- setup ---------------------------------
__global__ __launch_bounds__(128) void k_quad() {
    int j = blockIdx.x, k = threadIdx.x;
    double tj = M_PI * (double)j / 255.0, v = 0.0;
    if (k >= 1) v = cos(2.0 * tj * (double)k) * (2.0 / (4.0 * (double)k * k - 1.0));
    __shared__ double red[128];
    red[k] = v; __syncthreads();
    for (int s = 64; s > 0; s >>= 1) { if (k < s) red[k] += red[k + s]; __syncthreads(); }
    if (k == 0) {
        double c = (j == 0 || j == 255) ? 1.0 : 2.0;
        d_wq[j] = (float)(c / 255.0 * (1.0 - red[0]));
    }
}

__global__ __launch_bounds__(128) void k_tab() {
    int li = blockIdx.x;
    int j  = threadIdx.x;
    const float sc = (float)(2.0 * M_PI / 256.0);
    if (j < KQ) {
        int m = (li < 64) ? (2 * li) : (2 * (li - 64) + 1);
        int r = (m * j) & 255;
        float s, c;
        sincosf(sc * (float)r, &s, &c);
        float tc = (j <= 64) ? sc * c : 0.f;
        float ts = (j >= 1 && j <= 64) ? -sc * s : 0.f;
        if (j == 64) { tc *= 0.5f; ts *= 0.5f; }
        d_Tc2[li * KQ + j] = tc;
        d_Ts2[li * KQ + j] = ts;
    }
    if (li < 64 && j < 64) {
        int q = li;
        float se, ce, so, co;
        sincosf(sc * (float)((2 * q * j) & 255), &se, &ce);
        sincosf(sc * (float)(((2 * q + 1) * j) & 255), &so, &co);
        float we = (q == 0) ? 1.f : 2.f;
        d_G5t[0 * 4096 + q * 64 + j] = we * ce;
        d_G5t[1 * 4096 + q * 64 + j] = we * se;
        d_G5t[2 * 4096 + q * 64 + j] = 2.f * co;
        d_G5t[3 * 4096 + q * 64 + j] = 2.f * so;
    }
}

__global__ __launch_bounds__(128) void k_legendre() {
    int m = blockIdx.x, kk = threadIdx.x;
    __shared__ double s_a[LMAX], s_b[LMAX];
    __shared__ double s_sect;
    {
        int l = kk;
        if (l >= m + 2) {
            double fl = (double)l, fm = (double)m, g = fl - 1.0;
            s_a[l] = sqrt((4.0 * fl * fl - 1.0) / (fl * fl - fm * fm));
            s_b[l] = sqrt((g * g - fm * fm) / (4.0 * g * g - 1.0));
        }
    }
    if (kk == 0) {
        double pr = 1.0;
        for (int i = 1; i <= m; i++) pr *= (2.0 * i + 1.0) / (2.0 * i);
        s_sect = sqrt(pr);
    }
    __syncthreads();
    double tt = M_PI * (double)kk / 255.0;
    double ct = cos(tt), st = sin(tt), w = (double)d_wq[kk];
    size_t baseW = (size_t)m * 128 * 128;
    size_t baseT = (size_t)m * 128 * 128 + (size_t)kk * 128;
    for (int l = 0; l < m; l++) {
        int li = (((l + m) & 1) << 6) | (l >> 1);
        d_PCTW2[baseW + (size_t)li * 128 + kk] = 0.f;
        d_PCTT2[baseT + li] = 0.f;
    }
    double powv = 1.0;
    for (int i = 0; i < m; i++) powv *= -st;
    double p2 = 0.28209479177387814347 * s_sect * powv;
    {
        int li = (m >> 1);
        d_PCTW2[baseW + (size_t)li * 128 + kk] = (float)(p2 * w);
        d_PCTT2[baseT + li] = (float)p2;
    }
    if (m + 1 < LMAX) {
        double p1 = sqrt(2.0 * m + 3.0) * ct * p2;
        {
            int li = 64 + ((m + 1) >> 1);
            d_PCTW2[baseW + (size_t)li * 128 + kk] = (float)(p1 * w);
            d_PCTT2[baseT + li] = (float)p1;
        }
        for (int l = m + 2; l < LMAX; l++) {
            double p = s_a[l] * (ct * p1 - s_b[l] * p2);
            int li = (((l + m) & 1) << 6) | (l >> 1);
            d_PCTW2[baseW + (size_t)li * 128 + kk] = (float)(p * w);
            d_PCTT2[baseT + li] = (float)p;
            p2 = p1; p1 = p;
        }
    }
}

__global__ __launch_bounds__(256) void k_fold(const float* __restrict__ x) {
    __shared__ float s[32][257];
    int t = threadIdx.x;
    int col0 = blockIdx.x * 32;
    int klat = col0 >> 8;
    int bc0  = col0 & 255;
    #pragma unroll 4
    for (int r = 0; r < 32; r++)
        s[r][t] = x[(size_t)(bc0 + r) * 65536 + klat * 256 + t];
    __syncthreads();
    #pragma unroll 4
    for (int it = 0; it < 16; it++) {
        int idx = it * 256 + t;
        int j = idx >> 5, c = idx & 31;
        float a = s[c][j];
        float b = s[c][(256 - j) & 255];
        float xe = (j == 0) ? a : a + b;
        float xo = (j == 0) ? 0.f : a - b;
        d_xe[(size_t)j * NROW + col0 + c] = xe;
        d_xo[(size_t)j * NROW + col0 + c] = xo;
    }
    if (t < 32) d_xe[(size_t)128 * NROW + col0 + t] = s[t][128];
}

#define A_TSTORE(buf, v) \
    do { (buf)[(ak4+0)*132+am] = (v).x; (buf)[(ak4+1)*132+am] = (v).y; \
         (buf)[(ak4+2)*132+am] = (v).z; (buf)[(ak4+3)*132+am] = (v).w; } while(0)

// ---------------------------------------------------------------------------
// G1 quarter-folded (proven)
// ---------------------------------------------------------------------------
template<int IM>
__global__ __launch_bounds__(256, 2) void k_g1p() {
    __shared__ float Ast[2][8 * 132];
    __shared__ float BpS[2][8 * 132];
    __shared__ float BmS[2][8 * 132];
    int t = threadIdx.x;
    int col0 = blockIdx.x * 128;
    const float* A = IM ? d_Ts2 : d_Tc2;
    const float* B = IM ? d_xo : d_xe;
    int am = t >> 1, ak4 = (t & 1) * 4;
    int bk = t >> 5, bn4 = (t & 31) * 4;
    int tc = t & 15, tn = t >> 4;
    float4 av = *reinterpret_cast<const float4*>(&A[am * KQ + ak4]);
    float4 bt = *reinterpret_cast<const float4*>(&B[(size_t)bk * NROW + col0 + bn4]);
    float4 bb = *reinterpret_cast<const float4*>(&B[(size_t)(128 - bk) * NROW + col0 + bn4]);
    A_TSTORE(Ast[0], av);
    *reinterpret_cast<float4*>(&BpS[0][bk * 132 + bn4]) =
        make_float4(bt.x + bb.x, bt.y + bb.y, bt.z + bb.z, bt.w + bb.w);
    *reinterpret_cast<float4*>(&BmS[0][bk * 132 + bn4]) =
        make_float4(bt.x - bb.x, bt.y - bb.y, bt.z - bb.z, bt.w - bb.w);
    __syncthreads();
    u64 acc2[8][4] = {};
    for (int kt = 0; kt < 9; kt++) {
        int cur = kt & 1;
        bool more = (kt + 1 < 9);
        float4 an, btn, bbn;
        if (more) {
            int k0 = (kt + 1) * 8;
            an  = *reinterpret_cast<const float4*>(&A[am * KQ + k0 + ak4]);
            btn = *reinterpret_cast<const float4*>(&B[(size_t)(k0 + bk) * NROW + col0 + bn4]);
            bbn = *reinterpret_cast<const float4*>(&B[(size_t)(128 - k0 - bk) * NROW + col0 + bn4]);
        }
        const float* Ap = Ast[cur];
        const float* Bev = IM ? BmS[cur] : BpS[cur];
        const float* Bod = IM ? BpS[cur] : BmS[cur];
        #pragma unroll
        for (int j = 0; j < 8; j++) {
            {
                float4 a0 = *reinterpret_cast<const float4*>(&Ap[j*132 + tn*4]);
                float4 b0 = *reinterpret_cast<const float4*>(&Bev[j*132 + tc*4]);
                float4 b1 = *reinterpret_cast<const float4*>(&Bev[j*132 + tc*4 + 64]);
                u64 bbv[4] = {pk2(b0.x,b0.y), pk2(b0.z,b0.w), pk2(b1.x,b1.y), pk2(b1.z,b1.w)};
                float ar[4] = {a0.x,a0.y,a0.z,a0.w};
                #pragma unroll
                for (int p = 0; p < 4; p++) {
                    u64 aa = dup2(ar[p]);
                    #pragma unroll
                    for (int q = 0; q < 4; q++) fma2(acc2[p][q], aa, bbv[q]);
                }
            }
            {
                float4 a1 = *reinterpret_cast<const float4*>(&Ap[j*132 + tn*4 + 64]);
                float4 b0 = *reinterpret_cast<const float4*>(&Bod[j*132 + tc*4]);
                float4 b1 = *reinterpret_cast<const float4*>(&Bod[j*132 + tc*4 + 64]);
                u64 bbv[4] = {pk2(b0.x,b0.y), pk2(b0.z,b0.w), pk2(b1.x,b1.y), pk2(b1.z,b1.w)};
                float ar[4] = {a1.x,a1.y,a1.z,a1.w};
                #pragma unroll
                for (int p = 0; p < 4; p++) {
                    u64 aa = dup2(ar[p]);
                    #pragma unroll
                    for (int q = 0; q < 4; q++) fma2(acc2[4 + p][q], aa, bbv[q]);
                }
            }
        }
        if (more) {
            A_TSTORE(Ast[cur ^ 1], an);
            *reinterpret_cast<float4*>(&BpS[cur ^ 1][bk * 132 + bn4]) =
                make_float4(btn.x + bbn.x, btn.y + bbn.y, btn.z + bbn.z, btn.w + bbn.w);
            *reinterpret_cast<float4*>(&BmS[cur ^ 1][bk * 132 + bn4]) =
                make_float4(btn.x - bbn.x, btn.y - bbn.y, btn.z - bbn.z, btn.w - bbn.w);
            __syncthreads();
        }
    }
    #pragma unroll
    for (int ph = 0; ph < 2; ph++)
        #pragma unroll
        for (int e = 0; e < 4; e++) {
            int le = tn * 4 + e;
            int xr = (ph == 0) ? (4 * le + IM) : (4 * le + 2 + IM);
            int p = ph * 4 + e;
            float2 c0 = un2(acc2[p][0]), c1 = un2(acc2[p][1]);
            float2 c2 = un2(acc2[p][2]), c3 = un2(acc2[p][3]);
            float* dst = &d_xh[(size_t)xr * NROW + col0];
            *reinterpret_cast<float4*>(dst + tc * 4)      = make_float4(c0.x, c0.y, c1.x, c1.y);
            *reinterpret_cast<float4*>(dst + tc * 4 + 64) = make_float4(c2.x, c2.y, c3.x, c3.y);
        }
}

// ---------------------------------------------------------------------------
// G2 latitude-folded (proven)
// ---------------------------------------------------------------------------
__global__ __launch_bounds__(256, 2) void k_g2f() {
    __shared__ float Ast[2][8 * 132];
    __shared__ float BeS[2][8 * 132];
    __shared__ float BoS[2][8 * 132];
    int t = threadIdx.x;
    int bc0 = blockIdx.x * 128;
    int mri = blockIdx.y;
    int m = mri >> 1, ri = mri & 1, par0 = m & 1;
    const float* A = d_PCTW2 + (size_t)m * 128 * 128;
    const float* B = d_xh + (size_t)mri * NROW;
    int am = t >> 1, ak4 = (t & 1) * 4;
    int bk = t >> 5, bn4 = (t & 31) * 4;
    int tc = t & 15, tn = t >> 4;
    float4 av = *reinterpret_cast<const float4*>(&A[am * 128 + ak4]);
    float4 bt = *reinterpret_cast<const float4*>(&B[(size_t)bk * 256 + bc0 + bn4]);
    float4 bb = *reinterpret_cast<const float4*>(&B[(size_t)(255 - bk) * 256 + bc0 + bn4]);
    A_TSTORE(Ast[0], av);
    *reinterpret_cast<float4*>(&BeS[0][bk * 132 + bn4]) =
        make_float4(bt.x + bb.x, bt.y + bb.y, bt.z + bb.z, bt.w + bb.w);
    *reinterpret_cast<float4*>(&BoS[0][bk * 132 + bn4]) =
        make_float4(bt.x - bb.x, bt.y - bb.y, bt.z - bb.z, bt.w - bb.w);
    __syncthreads();
    u64 acc2[8][4] = {};
    for (int kt = 0; kt < 16; kt++) {
        int cur = kt & 1;
        bool more = (kt + 1 < 16);
        float4 an, btn, bbn;
        if (more) {
            int k0 = (kt + 1) * 8;
            an  = *reinterpret_cast<const float4*>(&A[am * 128 + k0 + ak4]);
            btn = *reinterpret_cast<const float4*>(&B[(size_t)(k0 + bk) * 256 + bc0 + bn4]);
            bbn = *reinterpret_cast<const float4*>(&B[(size_t)(255 - k0 - bk) * 256 + bc0 + bn4]);
        }
        const float* Ap = Ast[cur];
        const float* Be = BeS[cur];
        const float* Bo = BoS[cur];
        #pragma unroll
        for (int j = 0; j < 8; j++) {
            {
                float4 a0 = *reinterpret_cast<const float4*>(&Ap[j*132 + tn*4]);
                float4 b0 = *reinterpret_cast<const float4*>(&Be[j*132 + tc*4]);
                float4 b1 = *reinterpret_cast<const float4*>(&Be[j*132 + tc*4 + 64]);
                u64 bbv[4] = {pk2(b0.x,b0.y), pk2(b0.z,b0.w), pk2(b1.x,b1.y), pk2(b1.z,b1.w)};
                float ar[4] = {a0.x,a0.y,a0.z,a0.w};
                #pragma unroll
                for (int p = 0; p < 4; p++) {
                    u64 aa = dup2(ar[p]);
                    #pragma unroll
                    for (int q = 0; q < 4; q++) fma2(acc2[p][q], aa, bbv[q]);
                }
            }
            {
                float4 a1 = *reinterpret_cast<const float4*>(&Ap[j*132 + tn*4 + 64]);
                float4 b0 = *reinterpret_cast<const float4*>(&Bo[j*132 + tc*4]);
                float4 b1 = *reinterpret_cast<const float4*>(&Bo[j*132 + tc*4 + 64]);
                u64 bbv[4] = {pk2(b0.x,b0.y), pk2(b0.z,b0.w), pk2(b1.x,b1.y), pk2(b1.z,b1.w)};
                float ar[4] = {a1.x,a1.y,a1.z,a1.w};
                #pragma unroll
                for (int p = 0; p < 4; p++) {
                    u64 aa = dup2(ar[p]);
                    #pragma unroll
                    for (int q = 0; q < 4; q++) fma2(acc2[4 + p][q], aa, bbv[q]);
                }
            }
        }
        if (more) {
            A_TSTORE(Ast[cur ^ 1], an);
            *reinterpret_cast<float4*>(&BeS[cur ^ 1][bk * 132 + bn4]) =
                make_float4(btn.x + bbn.x, btn.y + bbn.y, btn.z + bbn.z, btn.w + bbn.w);
            *reinterpret_cast<float4*>(&BoS[cur ^ 1][bk * 132 + bn4]) =
                make_float4(btn.x - bbn.x, btn.y - bbn.y, btn.z - bbn.z, btn.w - bbn.w);
            __syncthreads();
        }
    }
    #pragma unroll
    for (int ph = 0; ph < 2; ph++)
        #pragma unroll
        for (int e = 0; e < 4; e++) {
            int le = tn * 4 + e;
            int l = (ph == 0) ? (2 * le + par0) : (2 * le + 1 - par0);
            size_t xrow = ((size_t)l * 129 + m) * 2 + ri;
            int p = ph * 4 + e;
            float2 c0 = un2(acc2[p][0]), c1 = un2(acc2[p][1]);
            float2 c2 = un2(acc2[p][2]), c3 = un2(acc2[p][3]);
            float* dst = &d_spec[xrow * 256 + bc0];
            *reinterpret_cast<float4*>(dst + tc * 4)      = make_float4(c0.x, c0.y, c1.x, c1.y);
            *reinterpret_cast<float4*>(dst + tc * 4 + 64) = make_float4(c2.x, c2.y, c3.x, c3.y);
        }
}

// ---------------------------------------------------------------------------
// G3 channel mix; blocks whose 8 x-rows all have l<m are identically zero:
// skip them entirely (out2 rows stay zero from static init).
// ---------------------------------------------------------------------------
__global__ __launch_bounds__(256) void k_mix(const float* __restrict__ W) {
    __shared__ float Ws[8 * 1028];
    __shared__ float Ss[8 * 256];
    int t = threadIdx.x;
    int x0 = blockIdx.x * 8;
    bool allz = true;
    #pragma unroll
    for (int i = 0; i < 8; i++) {
        int lm = (x0 + i) >> 1;
        int l = lm / 129, m = lm - l * 129;
        if (l >= m) allz = false;
    }
    if (allz) return;
    #pragma unroll
    for (int rep = 0; rep < 32; rep++) {
        int idx = rep * 256 + t;
        int xl = idx & 7, io = idx >> 3;
        Ws[xl * 1028 + io] = W[(size_t)io * NX + x0 + xl];
    }
    #pragma unroll
    for (int rep = 0; rep < 8; rep++) {
        int idx = rep * 256 + t;
        int xl = idx >> 8, bc = idx & 255;
        Ss[xl * 256 + bc] = d_spec[(size_t)(x0 + xl) * 256 + bc];
    }
    __syncthreads();
    int b = t >> 5, o = t & 31;
    float acc[8] = {};
    #pragma unroll
    for (int xl = 0; xl < 8; xl++)
        #pragma unroll
        for (int i = 0; i < 32; i++)
            acc[xl] += Ss[xl * 256 + b * 32 + i] * Ws[xl * 1028 + i * 32 + o];
    #pragma unroll
    for (int xl = 0; xl < 8; xl++)
        d_out2[(size_t)(x0 + xl) * 256 + t] = acc[xl];
}

// ---------------------------------------------------------------------------
// G4 latitude-folded + triangle skip: K tiles with le < m/2 contribute zero
// (PCTT2 columns zero AND out2 rows zero) -> start at lt0 = m >> 4.
// ---------------------------------------------------------------------------
__global__ __launch_bounds__(256, 2) void k_g4f() {
    __shared__ float AeS[2][8 * 132];
    __shared__ float AoS[2][8 * 132];
    __shared__ float BeS[2][8 * 68];
    __shared__ float BoS[2][8 * 68];
    int t = threadIdx.x;
    int bo0 = blockIdx.x * 64;
    int mri = blockIdx.y;
    int m = mri >> 1, ri = mri & 1, par0 = m & 1;
    int lt0 = m >> 4;
    const float* A = d_PCTT2 + (size_t)m * 128 * 128;
    int am = t >> 1, ak4 = (t & 1) * 4;
    int blr = (t & 127) >> 4, bn4 = (t & 15) * 4;
    int isBo = t >> 7;
    int tc = t & 15, tn = t >> 4;
    int l0i = lt0 * 8;
    float4 ave = *reinterpret_cast<const float4*>(&A[am * 128 + l0i + ak4]);
    float4 avo = *reinterpret_cast<const float4*>(&A[am * 128 + 64 + l0i + ak4]);
    float4 bv;
    {
        int l = 2 * (l0i + blr) + (isBo ? (1 - par0) : par0);
        size_t xrow = ((size_t)l * 129 + m) * 2 + ri;
        bv = *reinterpret_cast<const float4*>(&d_out2[xrow * 256 + bo0 + bn4]);
    }
    A_TSTORE(AeS[0], ave);
    { float* buf = AoS[0];
      buf[(ak4+0)*132+am] = avo.x; buf[(ak4+1)*132+am] = avo.y;
      buf[(ak4+2)*132+am] = avo.z; buf[(ak4+3)*132+am] = avo.w; }
    if (isBo) *reinterpret_cast<float4*>(&BoS[0][blr * 68 + bn4]) = bv;
    else      *reinterpret_cast<float4*>(&BeS[0][blr * 68 + bn4]) = bv;
    __syncthreads();
    u64 acc2E[8][2] = {};
    u64 acc2O[8][2] = {};
    for (int lt = lt0; lt < 8; lt++) {
        int cur = (lt - lt0) & 1;
        bool more = (lt + 1 < 8);
        float4 ane, ano, bn_;
        if (more) {
            int l0 = (lt + 1) * 8;
            ane = *reinterpret_cast<const float4*>(&A[am * 128 + l0 + ak4]);
            ano = *reinterpret_cast<const float4*>(&A[am * 128 + 64 + l0 + ak4]);
            int l = 2 * (l0 + blr) + (isBo ? (1 - par0) : par0);
            size_t xrow = ((size_t)l * 129 + m) * 2 + ri;
            bn_ = *reinterpret_cast<const float4*>(&d_out2[xrow * 256 + bo0 + bn4]);
        }
        const float* Ae = AeS[cur]; const float* Ao = AoS[cur];
        const float* Be = BeS[cur]; const float* Bo = BoS[cur];
        #pragma unroll
        for (int j = 0; j < 8; j++) {
            float4 e0 = *reinterpret_cast<const float4*>(&Ae[j*132 + tn*4]);
            float4 e1 = *reinterpret_cast<const float4*>(&Ae[j*132 + tn*4 + 64]);
            float4 o0 = *reinterpret_cast<const float4*>(&Ao[j*132 + tn*4]);
            float4 o1 = *reinterpret_cast<const float4*>(&Ao[j*132 + tn*4 + 64]);
            float4 be = *reinterpret_cast<const float4*>(&Be[j*68 + tc*4]);
            float4 bo = *reinterpret_cast<const float4*>(&Bo[j*68 + tc*4]);
            u64 bbe[2] = {pk2(be.x,be.y), pk2(be.z,be.w)};
            u64 bbo[2] = {pk2(bo.x,bo.y), pk2(bo.z,bo.w)};
            float ae[8] = {e0.x,e0.y,e0.z,e0.w,e1.x,e1.y,e1.z,e1.w};
            float ao[8] = {o0.x,o0.y,o0.z,o0.w,o1.x,o1.y,o1.z,o1.w};
            #pragma unroll
            for (int p = 0; p < 8; p++) {
                u64 aaE = dup2(ae[p]);
                fma2(acc2E[p][0], aaE, bbe[0]);
                fma2(acc2E[p][1], aaE, bbe[1]);
                u64 aaO = dup2(ao[p]);
                fma2(acc2O[p][0], aaO, bbo[0]);
                fma2(acc2O[p][1], aaO, bbo[1]);
            }
        }
        if (more) {
            A_TSTORE(AeS[cur ^ 1], ane);
            { float* buf = AoS[cur ^ 1];
              buf[(ak4+0)*132+am] = ano.x; buf[(ak4+1)*132+am] = ano.y;
              buf[(ak4+2)*132+am] = ano.z; buf[(ak4+3)*132+am] = ano.w; }
            if (isBo) *reinterpret_cast<float4*>(&BoS[cur ^ 1][blr * 68 + bn4]) = bn_;
            else      *reinterpret_cast<float4*>(&BeS[cur ^ 1][blr * 68 + bn4]) = bn_;
            __syncthreads();
        }
    }
    #pragma unroll
    for (int ph = 0; ph < 2; ph++)
        #pragma unroll
        for (int e = 0; e < 4; e++) {
            int p = ph * 4 + e;
            int k = ph * 64 + tn * 4 + e;
            float2 E0 = un2(acc2E[p][0]), E1 = un2(acc2E[p][1]);
            float2 O0 = un2(acc2O[p][0]), O1 = un2(acc2O[p][1]);
            float* base = &d_rr[(size_t)mri * NROW];
            *reinterpret_cast<float4*>(base + (size_t)k * 256 + bo0 + tc * 4) =
                make_float4(E0.x + O0.x, E0.y + O0.y, E1.x + O1.x, E1.y + O1.y);
            *reinterpret_cast<float4*>(base + (size_t)(255 - k) * 256 + bo0 + tc * 4) =
                make_float4(E0.x - O0.x, E0.y - O0.y, E1.x - O1.x, E1.y - O1.y);
        }
}

// ---------------------------------------------------------------------------
// G5 quarter-folded (proven)
// ---------------------------------------------------------------------------
__global__ __launch_bounds__(256, 2) void k_g5q(float* __restrict__ out) {
    __shared__ float As[2][4][8 * 68];
    __shared__ float Bs[2][4][8 * 68];
    int t = threadIdx.x;
    int col0 = blockIdx.x * 64;
    int tc = t & 15, tn = t >> 4;
    #pragma unroll
    for (int it = 0; it < 2; it++) {
        int idx = it * 256 + t;
        int row = idx >> 4, c4 = (idx & 15) * 4;
        int g = row & 3, ql = row >> 2;
        float4 av = *reinterpret_cast<const float4*>(&d_rr[(size_t)(4 * ql + g) * NROW + col0 + c4]);
        *reinterpret_cast<float4*>(&As[0][g][ql * 68 + c4]) = av;
        float4 bv = *reinterpret_cast<const float4*>(&d_G5t[g * 4096 + ql * 64 + c4]);
        *reinterpret_cast<float4*>(&Bs[0][g][ql * 68 + c4]) = bv;
    }
    __syncthreads();
    u64 acc[4][4][2] = {};
    for (int kt = 0; kt < 8; kt++) {
        int cur = kt & 1;
        bool more = (kt + 1 < 8);
        float4 pa[2], pb[2];
        if (more) {
            int q0 = (kt + 1) * 8;
            #pragma unroll
            for (int it = 0; it < 2; it++) {
                int idx = it * 256 + t;
                int row = idx >> 4, c4 = (idx & 15) * 4;
                int g = row & 3, ql = row >> 2;
                pa[it] = *reinterpret_cast<const float4*>(&d_rr[(size_t)(4 * (q0 + ql) + g) * NROW + col0 + c4]);
                pb[it] = *reinterpret_cast<const float4*>(&d_G5t[g * 4096 + (q0 + ql) * 64 + c4]);
            }
        }
        #pragma unroll
        for (int q = 0; q < 8; q++) {
            #pragma unroll
            for (int g = 0; g < 4; g++) {
                float4 a = *reinterpret_cast<const float4*>(&As[cur][g][q * 68 + tn * 4]);
                float4 b = *reinterpret_cast<const float4*>(&Bs[cur][g][q * 68 + tc * 4]);
                u64 bb[2] = {pk2(b.x, b.y), pk2(b.z, b.w)};
                float ar[4] = {a.x, a.y, a.z, a.w};
                #pragma unroll
                for (int p = 0; p < 4; p++) {
                    u64 aa = dup2(ar[p]);
                    fma2(acc[g][p][0], aa, bb[0]);
                    fma2(acc[g][p][1], aa, bb[1]);
                }
            }
        }
        if (more) {
            #pragma unroll
            for (int it = 0; it < 2; it++) {
                int idx = it * 256 + t;
                int row = idx >> 4, c4 = (idx & 15) * 4;
                int g = row & 3, ql = row >> 2;
                *reinterpret_cast<float4*>(&As[cur ^ 1][g][ql * 68 + c4]) = pa[it];
                *reinterpret_cast<float4*>(&Bs[cur ^ 1][g][ql * 68 + c4]) = pb[it];
            }
            __syncthreads();
        }
    }
    int jb = tc * 4;
    #pragma unroll
    for (int p = 0; p < 4; p++) {
        int col = col0 + tn * 4 + p;
        int bo = col & 255, k = col >> 8;
        float* base = &out[(size_t)bo * 65536 + (size_t)k * 256];
        float2 Ce0 = un2(acc[0][p][0]), Ce1 = un2(acc[0][p][1]);
        float2 Se0 = un2(acc[1][p][0]), Se1 = un2(acc[1][p][1]);
        float2 Co0 = un2(acc[2][p][0]), Co1 = un2(acc[2][p][1]);
        float2 So0 = un2(acc[3][p][0]), So1 = un2(acc[3][p][1]);
        float Ce[4] = {Ce0.x, Ce0.y, Ce1.x, Ce1.y};
        float Se[4] = {Se0.x, Se0.y, Se1.x, Se1.y};
        float Co[4] = {Co0.x, Co0.y, Co1.x, Co1.y};
        float So[4] = {So0.x, So0.y, So1.x, So1.y};
        float yA[4], yB[4], yC[4], yD[4];
        #pragma unroll
        for (int q = 0; q < 4; q++) {
            float Cp = Ce[q] + Co[q], Cm = Ce[q] - Co[q];
            float Sp = Se[q] + So[q], Sm = Se[q] - So[q];
            yA[q] = Cp - Sp;
            yB[q] = Cp + Sp;
            yC[q] = Cm + Sm;
            yD[q] = Cm - Sm;
        }
        *reinterpret_cast<float4*>(base + jb) = make_float4(yA[0], yA[1], yA[2], yA[3]);
        *reinterpret_cast<float4*>(base + 128 + jb) = make_float4(yD[0], yD[1], yD[2], yD[3]);
        #pragma unroll
        for (int q = 0; q < 4; q++) {
            int j = jb + q;
            base[128 - j] = yC[q];
            if (j > 0) base[256 - j] = yB[q];
        }
    }
}

__global__ __launch_bounds__(256) void k_y64(float* __restrict__ out) {
    int col = blockIdx.x * 256 + threadIdx.x;
    float C = 0.f, S = 0.f;
    #pragma unroll
    for (int q = 0; q < 64; q++) {
        float sg = (q & 1) ? -1.f : 1.f;
        float w = (q == 0) ? 1.f : 2.f;
        C += w * sg * d_rr[(size_t)(4 * q) * NROW + col];
        S += 2.f * sg * d_rr[(size_t)(4 * q + 3) * NROW + col];
    }
    int bo = col & 255, k = col >> 8;
    float* base = &out[(size_t)bo * 65536 + (size_t)k * 256];
    base[64]  = C - S;
    base[192] = C + S;
}

// ---------------------------------------------------------------------------
extern "C" void kernel_launch(void* const* d_in, const int* in_sizes, int n_in,
                              void* d_out, int out_size) {
    const float* x = (const float*)d_in[0];
    const float* w = (const float*)d_in[1];
    float* out = (float*)d_out;

    k_quad<<<256, 128>>>();
    k_tab<<<128, 128>>>();
    k_legendre<<<128, 128>>>();

    k_fold<<<2048, 256>>>(x);
    k_g1p<0><<<512, 256>>>();
    k_g1p<1><<<512, 256>>>();
    dim3 g2(2, 256);   k_g2f<<<g2, 256>>>();
    k_mix<<<NX / 8, 256>>>(w);
    dim3 g4(4, 256);   k_g4f<<<g4, 256>>>();
    k_g5q<<<1024, 256>>>(out);
    k_y64<<<256, 256>>>(out);
}

// round 17
// speedup vs baseline: 2.3040x; 1.0013x over previous
#include <cuda_runtime.h>
#include <math.h>
#include <stdint.h>

#define NLAT  256
#define LMAX  128
#define NM    256
#define NX    33024
#define NROW  65536
#define KEPAD 136
#define KQ    72

typedef unsigned long long u64;
__device__ __forceinline__ u64 pk2(float x, float y) {
    u64 r; asm("mov.b64 %0, {%1, %2};" : "=l"(r) : "f"(x), "f"(y)); return r;
}
__device__ __forceinline__ u64 dup2(float x) { return pk2(x, x); }
__device__ __forceinline__ void fma2(u64 &d, u64 a, u64 b) {
    asm("fma.rn.f32x2 %0, %1, %2, %3;" : "=l"(d) : "l"(a), "l"(b), "l"(d));
}
__device__ __forceinline__ float2 un2(u64 v) {
    float2 f; asm("mov.b64 {%0, %1}, %2;" : "=f"(f.x), "=f"(f.y) : "l"(v)); return f;
}

// --------------------------- device scratch --------------------------------
__device__ float d_wq[NLAT];
__device__ float d_Tc2[128 * KQ];
__device__ float d_Ts2[128 * KQ];
__device__ float d_G5t[4 * 64 * 64];
__device__ float d_PCTW2[(size_t)LMAX * 128 * 128];
__device__ float d_PCTT2[(size_t)LMAX * 128 * 128];
__device__ float d_xe[(size_t)KEPAD * NROW];
__device__ float d_xo[(size_t)KEPAD * NROW];
__device__ float d_xh  [(size_t)NM * NROW];
__device__ float d_spec[(size_t)NX * 256];   // rows l<m stay 0 (zero-init; G2 skips them)
__device__ float d_out2[(size_t)NX * 256];   // rows l<m stay 0
__device__ float d_rr  [(size_t)NM * NROW];

// --------------------------- setup ---------------------------------
__global__ __launch_bounds__(128) void k_quad() {
    int j = blockIdx.x, k = threadIdx.x;
    double tj = M_PI * (double)j / 255.0, v = 0.0;
    if (k >= 1) v = cos(2.0 * tj * (double)k) * (2.0 / (4.0 * (double)k * k - 1.0));
    __shared__ double red[128];
    red[k] = v; __syncthreads();
    for (int s = 64; s > 0; s >>= 1) { if (k < s) red[k] += red[k + s]; __syncthreads(); }
    if (k == 0) {
        double c = (j == 0 || j == 255) ? 1.0 : 2.0;
        d_wq[j] = (float)(c / 255.0 * (1.0 - red[0]));
    }
}

__global__ __launch_bounds__(128) void k_tab() {
    int li = blockIdx.x;
    int j  = threadIdx.x;
    const float sc = (float)(2.0 * M_PI / 256.0);
    if (j < KQ) {
        int m = (li < 64) ? (2 * li) : (2 * (li - 64) + 1);
        int r = (m * j) & 255;
        float s, c;
        sincosf(sc * (float)r, &s, &c);
        float tc = (j <= 64) ? sc * c : 0.f;
        float ts = (j >= 1 && j <= 64) ? -sc * s : 0.f;
        if (j == 64) { tc *= 0.5f; ts *= 0.5f; }
        d_Tc2[li * KQ + j] = tc;
        d_Ts2[li * KQ + j] = ts;
    }
    if (li < 64 && j < 64) {
        int q = li;
        float se, ce, so, co;
        sincosf(sc * (float)((2 * q * j) & 255), &se, &ce);
        sincosf(sc * (float)(((2 * q + 1) * j) & 255), &so, &co);
        float we = (q == 0) ? 1.f : 2.f;
        d_G5t[0 * 4096 + q * 64 + j] = we * ce;
        d_G5t[1 * 4096 + q * 64 + j] = we * se;
        d_G5t[2 * 4096 + q * 64 + j] = 2.f * co;
        d_G5t[3 * 4096 + q * 64 + j] = 2.f * so;
    }
}

__global__ __launch_bounds__(128) void k_legendre() {
    int m = blockIdx.x, kk = threadIdx.x;
    __shared__ double s_a[LMAX], s_b[LMAX];
    __shared__ double s_sect;
    {
        int l = kk;
        if (l >= m + 2) {
            double fl = (double)l, fm = (double)m, g = fl - 1.0;
            s_a[l] = sqrt((4.0 * fl * fl - 1.0) / (fl * fl - fm * fm));
            s_b[l] = sqrt((g * g - fm * fm) / (4.0 * g * g - 1.0));
        }
    }
    if (kk == 0) {
        double pr = 1.0;
        for (int i = 1; i <= m; i++) pr *= (2.0 * i + 1.0) / (2.0 * i);
        s_sect = sqrt(pr);
    }
    __syncthreads();
    double tt = M_PI * (double)kk / 255.0;
    double ct = cos(tt), st = sin(tt), w = (double)d_wq[kk];
    size_t baseW = (size_t)m * 128 * 128;
    size_t baseT = (size_t)m * 128 * 128 + (size_t)kk * 128;
    for (int l = 0; l < m; l++) {
        int li = (((l + m) & 1) << 6) | (l >> 1);
        d_PCTW2[baseW + (size_t)li * 128 + kk] = 0.f;
        d_PCTT2[baseT + li] = 0.f;
    }
    double powv = 1.0;
    for (int i = 0; i < m; i++) powv *= -st;
    double p2 = 0.28209479177387814347 * s_sect * powv;
    {
        int li = (m >> 1);
        d_PCTW2[baseW + (size_t)li * 128 + kk] = (float)(p2 * w);
        d_PCTT2[baseT + li] = (float)p2;
    }
    if (m + 1 < LMAX) {
        double p1 = sqrt(2.0 * m + 3.0) * ct * p2;
        {
            int li = 64 + ((m + 1) >> 1);
            d_PCTW2[baseW + (size_t)li * 128 + kk] = (float)(p1 * w);
            d_PCTT2[baseT + li] = (float)p1;
        }
        for (int l = m + 2; l < LMAX; l++) {
            double p = s_a[l] * (ct * p1 - s_b[l] * p2);
            int li = (((l + m) & 1) << 6) | (l >> 1);
            d_PCTW2[baseW + (size_t)li * 128 + kk] = (float)(p * w);
            d_PCTT2[baseT + li] = (float)p;
            p2 = p1; p1 = p;
        }
    }
}

__global__ __launch_bounds__(256) void k_fold(const float* __restrict__ x) {
    __shared__ float s[32][257];
    int t = threadIdx.x;
    int col0 = blockIdx.x * 32;
    int klat = col0 >> 8;
    int bc0  = col0 & 255;
    #pragma unroll 4
    for (int r = 0; r < 32; r++)
        s[r][t] = x[(size_t)(bc0 + r) * 65536 + klat * 256 + t];
    __syncthreads();
    #pragma unroll 4
    for (int it = 0; it < 16; it++) {
        int idx = it * 256 + t;
        int j = idx >> 5, c = idx & 31;
        float a = s[c][j];
        float b = s[c][(256 - j) & 255];
        float xe = (j == 0) ? a : a + b;
        float xo = (j == 0) ? 0.f : a - b;
        d_xe[(size_t)j * NROW + col0 + c] = xe;
        d_xo[(size_t)j * NROW + col0 + c] = xo;
    }
    if (t < 32) d_xe[(size_t)128 * NROW + col0 + t] = s[t][128];
}

#define A_TSTORE(buf, v) \
    do { (buf)[(ak4+0)*132+am] = (v).x; (buf)[(ak4+1)*132+am] = (v).y; \
         (buf)[(ak4+2)*132+am] = (v).z; (buf)[(ak4+3)*132+am] = (v).w; } while(0)

// ---------------------------------------------------------------------------
// G1 quarter-folded (proven)
// ---------------------------------------------------------------------------
template<int IM>
__global__ __launch_bounds__(256, 2) void k_g1p() {
    __shared__ float Ast[2][8 * 132];
    __shared__ float BpS[2][8 * 132];
    __shared__ float BmS[2][8 * 132];
    int t = threadIdx.x;
    int col0 = blockIdx.x * 128;
    const float* A = IM ? d_Ts2 : d_Tc2;
    const float* B = IM ? d_xo : d_xe;
    int am = t >> 1, ak4 = (t & 1) * 4;
    int bk = t >> 5, bn4 = (t & 31) * 4;
    int tc = t & 15, tn = t >> 4;
    float4 av = *reinterpret_cast<const float4*>(&A[am * KQ + ak4]);
    float4 bt = *reinterpret_cast<const float4*>(&B[(size_t)bk * NROW + col0 + bn4]);
    float4 bb = *reinterpret_cast<const float4*>(&B[(size_t)(128 - bk) * NROW + col0 + bn4]);
    A_TSTORE(Ast[0], av);
    *reinterpret_cast<float4*>(&BpS[0][bk * 132 + bn4]) =
        make_float4(bt.x + bb.x, bt.y + bb.y, bt.z + bb.z, bt.w + bb.w);
    *reinterpret_cast<float4*>(&BmS[0][bk * 132 + bn4]) =
        make_float4(bt.x - bb.x, bt.y - bb.y, bt.z - bb.z, bt.w - bb.w);
    __syncthreads();
    u64 acc2[8][4] = {};
    for (int kt = 0; kt < 9; kt++) {
        int cur = kt & 1;
        bool more = (kt + 1 < 9);
        float4 an, btn, bbn;
        if (more) {
            int k0 = (kt + 1) * 8;
            an  = *reinterpret_cast<const float4*>(&A[am * KQ + k0 + ak4]);
            btn = *reinterpret_cast<const float4*>(&B[(size_t)(k0 + bk) * NROW + col0 + bn4]);
            bbn = *reinterpret_cast<const float4*>(&B[(size_t)(128 - k0 - bk) * NROW + col0 + bn4]);
        }
        const float* Ap = Ast[cur];
        const float* Bev = IM ? BmS[cur] : BpS[cur];
        const float* Bod = IM ? BpS[cur] : BmS[cur];
        #pragma unroll
        for (int j = 0; j < 8; j++) {
            {
                float4 a0 = *reinterpret_cast<const float4*>(&Ap[j*132 + tn*4]);
                float4 b0 = *reinterpret_cast<const float4*>(&Bev[j*132 + tc*4]);
                float4 b1 = *reinterpret_cast<const float4*>(&Bev[j*132 + tc*4 + 64]);
                u64 bbv[4] = {pk2(b0.x,b0.y), pk2(b0.z,b0.w), pk2(b1.x,b1.y), pk2(b1.z,b1.w)};
                float ar[4] = {a0.x,a0.y,a0.z,a0.w};
                #pragma unroll
                for (int p = 0; p < 4; p++) {
                    u64 aa = dup2(ar[p]);
                    #pragma unroll
                    for (int q = 0; q < 4; q++) fma2(acc2[p][q], aa, bbv[q]);
                }
            }
            {
                float4 a1 = *reinterpret_cast<const float4*>(&Ap[j*132 + tn*4 + 64]);
                float4 b0 = *reinterpret_cast<const float4*>(&Bod[j*132 + tc*4]);
                float4 b1 = *reinterpret_cast<const float4*>(&Bod[j*132 + tc*4 + 64]);
                u64 bbv[4] = {pk2(b0.x,b0.y), pk2(b0.z,b0.w), pk2(b1.x,b1.y), pk2(b1.z,b1.w)};
                float ar[4] = {a1.x,a1.y,a1.z,a1.w};
                #pragma unroll
                for (int p = 0; p < 4; p++) {
                    u64 aa = dup2(ar[p]);
                    #pragma unroll
                    for (int q = 0; q < 4; q++) fma2(acc2[4 + p][q], aa, bbv[q]);
                }
            }
        }
        if (more) {
            A_TSTORE(Ast[cur ^ 1], an);
            *reinterpret_cast<float4*>(&BpS[cur ^ 1][bk * 132 + bn4]) =
                make_float4(btn.x + bbn.x, btn.y + bbn.y, btn.z + bbn.z, btn.w + bbn.w);
            *reinterpret_cast<float4*>(&BmS[cur ^ 1][bk * 132 + bn4]) =
                make_float4(btn.x - bbn.x, btn.y - bbn.y, btn.z - bbn.z, btn.w - bbn.w);
            __syncthreads();
        }
    }
    #pragma unroll
    for (int ph = 0; ph < 2; ph++)
        #pragma unroll
        for (int e = 0; e < 4; e++) {
            int le = tn * 4 + e;
            int xr = (ph == 0) ? (4 * le + IM) : (4 * le + 2 + IM);
            int p = ph * 4 + e;
            float2 c0 = un2(acc2[p][0]), c1 = un2(acc2[p][1]);
            float2 c2 = un2(acc2[p][2]), c3 = un2(acc2[p][3]);
            float* dst = &d_xh[(size_t)xr * NROW + col0];
            *reinterpret_cast<float4*>(dst + tc * 4)      = make_float4(c0.x, c0.y, c1.x, c1.y);
            *reinterpret_cast<float4*>(dst + tc * 4 + 64) = make_float4(c2.x, c2.y, c3.x, c3.y);
        }
}

// ---------------------------------------------------------------------------
// G2 latitude-folded + triangle M-split: blockIdx.z = leh selects le half
// [32*leh, 32*leh+32). leh=0 blocks are all-zero for m>=64 -> skip.
// M-tile = 64 li rows (32 le x 2 parities), 4 rows/thread (single parity each).
// ---------------------------------------------------------------------------
__global__ __launch_bounds__(256, 2) void k_g2h() {
    __shared__ float Ast[2][8 * 68];     // [k][r], r<32 E rows, r>=32 O rows
    __shared__ float BeS[2][8 * 132];
    __shared__ float BoS[2][8 * 132];
    int t = threadIdx.x;
    int bc0 = blockIdx.x * 128;
    int mri = blockIdx.y;
    int leh = blockIdx.z;
    int m = mri >> 1, ri = mri & 1, par0 = m & 1;
    if (leh == 0 && m >= 64) return;     // whole le-half is l<m: zero
    const float* A = d_PCTW2 + (size_t)m * 128 * 128;
    const float* B = d_xh + (size_t)mri * NROW;
    int arow = t >> 1, ach = (t & 1) * 4;            // t<128: A loader
    int bk = t >> 5, bn4 = (t & 31) * 4;
    int tc = t & 15, tn = t >> 4;
    int ali = (arow < 32) ? (leh * 32 + arow) : (64 + leh * 32 + (arow - 32));
    if (t < 128) {
        float4 av = *reinterpret_cast<const float4*>(&A[ali * 128 + ach]);
        Ast[0][(ach + 0) * 68 + arow] = av.x;
        Ast[0][(ach + 1) * 68 + arow] = av.y;
        Ast[0][(ach + 2) * 68 + arow] = av.z;
        Ast[0][(ach + 3) * 68 + arow] = av.w;
    }
    float4 bt = *reinterpret_cast<const float4*>(&B[(size_t)bk * 256 + bc0 + bn4]);
    float4 bb = *reinterpret_cast<const float4*>(&B[(size_t)(255 - bk) * 256 + bc0 + bn4]);
    *reinterpret_cast<float4*>(&BeS[0][bk * 132 + bn4]) =
        make_float4(bt.x + bb.x, bt.y + bb.y, bt.z + bb.z, bt.w + bb.w);
    *reinterpret_cast<float4*>(&BoS[0][bk * 132 + bn4]) =
        make_float4(bt.x - bb.x, bt.y - bb.y, bt.z - bb.z, bt.w - bb.w);
    __syncthreads();
    u64 acc2[4][4] = {};
    for (int kt = 0; kt < 16; kt++) {
        int cur = kt & 1;
        bool more = (kt + 1 < 16);
        float4 an, btn, bbn;
        if (more) {
            int k0 = (kt + 1) * 8;
            if (t < 128)
                an = *reinterpret_cast<const float4*>(&A[ali * 128 + k0 + ach]);
            btn = *reinterpret_cast<const float4*>(&B[(size_t)(k0 + bk) * 256 + bc0 + bn4]);
            bbn = *reinterpret_cast<const float4*>(&B[(size_t)(255 - k0 - bk) * 256 + bc0 + bn4]);
        }
        const float* Ap = Ast[cur];
        const float* Bsel = (tn >= 8) ? BoS[cur] : BeS[cur];
        #pragma unroll
        for (int j = 0; j < 8; j++) {
            float4 a0 = *reinterpret_cast<const float4*>(&Ap[j*68 + tn*4]);
            float4 b0 = *reinterpret_cast<const float4*>(&Bsel[j*132 + tc*4]);
            float4 b1 = *reinterpret_cast<const float4*>(&Bsel[j*132 + tc*4 + 64]);
            u64 bbv[4] = {pk2(b0.x,b0.y), pk2(b0.z,b0.w), pk2(b1.x,b1.y), pk2(b1.z,b1.w)};
            float ar[4] = {a0.x,a0.y,a0.z,a0.w};
            #pragma unroll
            for (int p = 0; p < 4; p++) {
                u64 aa = dup2(ar[p]);
                #pragma unroll
                for (int q = 0; q < 4; q++) fma2(acc2[p][q], aa, bbv[q]);
            }
        }
        if (more) {
            if (t < 128) {
                Ast[cur ^ 1][(ach + 0) * 68 + arow] = an.x;
                Ast[cur ^ 1][(ach + 1) * 68 + arow] = an.y;
                Ast[cur ^ 1][(ach + 2) * 68 + arow] = an.z;
                Ast[cur ^ 1][(ach + 3) * 68 + arow] = an.w;
            }
            *reinterpret_cast<float4*>(&BeS[cur ^ 1][bk * 132 + bn4]) =
                make_float4(btn.x + bbn.x, btn.y + bbn.y, btn.z + bbn.z, btn.w + bbn.w);
            *reinterpret_cast<float4*>(&BoS[cur ^ 1][bk * 132 + bn4]) =
                make_float4(btn.x - bbn.x, btn.y - bbn.y, btn.z - bbn.z, btn.w - bbn.w);
            __syncthreads();
        }
    }
    #pragma unroll
    for (int e = 0; e < 4; e++) {
        int r = tn * 4 + e;
        bool isO = (r >= 32);
        int le = leh * 32 + (isO ? (r - 32) : r);
        int l = 2 * le + (isO ? (1 - par0) : par0);
        size_t xrow = ((size_t)l * 129 + m) * 2 + ri;
        float2 c0 = un2(acc2[e][0]), c1 = un2(acc2[e][1]);
        float2 c2 = un2(acc2[e][2]), c3 = un2(acc2[e][3]);
        float* dst = &d_spec[xrow * 256 + bc0];
        *reinterpret_cast<float4*>(dst + tc * 4)      = make_float4(c0.x, c0.y, c1.x, c1.y);
        *reinterpret_cast<float4*>(dst + tc * 4 + 64) = make_float4(c2.x, c2.y, c3.x, c3.y);
    }
}

// ---------------------------------------------------------------------------
// G3 channel mix with all-zero block skip (proven)
// ---------------------------------------------------------------------------
__global__ __launch_bounds__(256) void k_mix(const float* __restrict__ W) {
    __shared__ float Ws[8 * 1028];
    __shared__ float Ss[8 * 256];
    int t = threadIdx.x;
    int x0 = blockIdx.x * 8;
    bool allz = true;
    #pragma unroll
    for (int i = 0; i < 8; i++) {
        int lm = (x0 + i) >> 1;
        int l = lm / 129, m = lm - l * 129;
        if (l >= m) allz = false;
    }
    if (allz) return;
    #pragma unroll
    for (int rep = 0; rep < 32; rep++) {
        int idx = rep * 256 + t;
        int xl = idx & 7, io = idx >> 3;
        Ws[xl * 1028 + io] = W[(size_t)io * NX + x0 + xl];
    }
    #pragma unroll
    for (int rep = 0; rep < 8; rep++) {
        int idx = rep * 256 + t;
        int xl = idx >> 8, bc = idx & 255;
        Ss[xl * 256 + bc] = d_spec[(size_t)(x0 + xl) * 256 + bc];
    }
    __syncthreads();
    int b = t >> 5, o = t & 31;
    float acc[8] = {};
    #pragma unroll
    for (int xl = 0; xl < 8; xl++)
        #pragma unroll
        for (int i = 0; i < 32; i++)
            acc[xl] += Ss[xl * 256 + b * 32 + i] * Ws[xl * 1028 + i * 32 + o];
    #pragma unroll
    for (int xl = 0; xl < 8; xl++)
        d_out2[(size_t)(x0 + xl) * 256 + t] = acc[xl];
}

// ---------------------------------------------------------------------------
// G4 latitude-folded + triangle K-skip (proven)
// ---------------------------------------------------------------------------
__global__ __launch_bounds__(256, 2) void k_g4f() {
    __shared__ float AeS[2][8 * 132];
    __shared__ float AoS[2][8 * 132];
    __shared__ float BeS[2][8 * 68];
    __shared__ float BoS[2][8 * 68];
    int t = threadIdx.x;
    int bo0 = blockIdx.x * 64;
    int mri = blockIdx.y;
    int m = mri >> 1, ri = mri & 1, par0 = m & 1;
    int lt0 = m >> 4;
    const float* A = d_PCTT2 + (size_t)m * 128 * 128;
    int am = t >> 1, ak4 = (t & 1) * 4;
    int blr = (t & 127) >> 4, bn4 = (t & 15) * 4;
    int isBo = t >> 7;
    int tc = t & 15, tn = t >> 4;
    int l0i = lt0 * 8;
    float4 ave = *reinterpret_cast<const float4*>(&A[am * 128 + l0i + ak4]);
    float4 avo = *reinterpret_cast<const float4*>(&A[am * 128 + 64 + l0i + ak4]);
    float4 bv;
    {
        int l = 2 * (l0i + blr) + (isBo ? (1 - par0) : par0);
        size_t xrow = ((size_t)l * 129 + m) * 2 + ri;
        bv = *reinterpret_cast<const float4*>(&d_out2[xrow * 256 + bo0 + bn4]);
    }
    A_TSTORE(AeS[0], ave);
    { float* buf = AoS[0];
      buf[(ak4+0)*132+am] = avo.x; buf[(ak4+1)*132+am] = avo.y;
      buf[(ak4+2)*132+am] = avo.z; buf[(ak4+3)*132+am] = avo.w; }
    if (isBo) *reinterpret_cast<float4*>(&BoS[0][blr * 68 + bn4]) = bv;
    else      *reinterpret_cast<float4*>(&BeS[0][blr * 68 + bn4]) = bv;
    __syncthreads();
    u64 acc2E[8][2] = {};
    u64 acc2O[8][2] = {};
    for (int lt = lt0; lt < 8; lt++) {
        int cur = (lt - lt0) & 1;
        bool more = (lt + 1 < 8);
        float4 ane, ano, bn_;
        if (more) {
            int l0 = (lt + 1) * 8;
            ane = *reinterpret_cast<const float4*>(&A[am * 128 + l0 + ak4]);
            ano = *reinterpret_cast<const float4*>(&A[am * 128 + 64 + l0 + ak4]);
            int l = 2 * (l0 + blr) + (isBo ? (1 - par0) : par0);
            size_t xrow = ((size_t)l * 129 + m) * 2 + ri;
            bn_ = *reinterpret_cast<const float4*>(&d_out2[xrow * 256 + bo0 + bn4]);
        }
        const float* Ae = AeS[cur]; const float* Ao = AoS[cur];
        const float* Be = BeS[cur]; const float* Bo = BoS[cur];
        #pragma unroll
        for (int j = 0; j < 8; j++) {
            float4 e0 = *reinterpret_cast<const float4*>(&Ae[j*132 + tn*4]);
            float4 e1 = *reinterpret_cast<const float4*>(&Ae[j*132 + tn*4 + 64]);
            float4 o0 = *reinterpret_cast<const float4*>(&Ao[j*132 + tn*4]);
            float4 o1 = *reinterpret_cast<const float4*>(&Ao[j*132 + tn*4 + 64]);
            float4 be = *reinterpret_cast<const float4*>(&Be[j*68 + tc*4]);
            float4 bo = *reinterpret_cast<const float4*>(&Bo[j*68 + tc*4]);
            u64 bbe[2] = {pk2(be.x,be.y), pk2(be.z,be.w)};
            u64 bbo[2] = {pk2(bo.x,bo.y), pk2(bo.z,bo.w)};
            float ae[8] = {e0.x,e0.y,e0.z,e0.w,e1.x,e1.y,e1.z,e1.w};
            float ao[8] = {o0.x,o0.y,o0.z,o0.w,o1.x,o1.y,o1.z,o1.w};
            #pragma unroll
            for (int p = 0; p < 8; p++) {
                u64 aaE = dup2(ae[p]);
                fma2(acc2E[p][0], aaE, bbe[0]);
                fma2(acc2E[p][1], aaE, bbe[1]);
                u64 aaO = dup2(ao[p]);
                fma2(acc2O[p][0], aaO, bbo[0]);
                fma2(acc2O[p][1], aaO, bbo[1]);
            }
        }
        if (more) {
            A_TSTORE(AeS[cur ^ 1], ane);
            { float* buf = AoS[cur ^ 1];
              buf[(ak4+0)*132+am] = ano.x; buf[(ak4+1)*132+am] = ano.y;
              buf[(ak4+2)*132+am] = ano.z; buf[(ak4+3)*132+am] = ano.w; }
            if (isBo) *reinterpret_cast<float4*>(&BoS[cur ^ 1][blr * 68 + bn4]) = bn_;
            else      *reinterpret_cast<float4*>(&BeS[cur ^ 1][blr * 68 + bn4]) = bn_;
            __syncthreads();
        }
    }
    #pragma unroll
    for (int ph = 0; ph < 2; ph++)
        #pragma unroll
        for (int e = 0; e < 4; e++) {
            int p = ph * 4 + e;
            int k = ph * 64 + tn * 4 + e;
            float2 E0 = un2(acc2E[p][0]), E1 = un2(acc2E[p][1]);
            float2 O0 = un2(acc2O[p][0]), O1 = un2(acc2O[p][1]);
            float* base = &d_rr[(size_t)mri * NROW];
            *reinterpret_cast<float4*>(base + (size_t)k * 256 + bo0 + tc * 4) =
                make_float4(E0.x + O0.x, E0.y + O0.y, E1.x + O1.x, E1.y + O1.y);
            *reinterpret_cast<float4*>(base + (size_t)(255 - k) * 256 + bo0 + tc * 4) =
                make_float4(E0.x - O0.x, E0.y - O0.y, E1.x - O1.x, E1.y - O1.y);
        }
}

// ---------------------------------------------------------------------------
// G5 quarter-folded (proven)
// ---------------------------------------------------------------------------
__global__ __launch_bounds__(256, 2) void k_g5q(float* __restrict__ out) {
    __shared__ float As[2][4][8 * 68];
    __shared__ float Bs[2][4][8 * 68];
    int t = threadIdx.x;
    int col0 = blockIdx.x * 64;
    int tc = t & 15, tn = t >> 4;
    #pragma unroll
    for (int it = 0; it < 2; it++) {
        int idx = it * 256 + t;
        int row = idx >> 4, c4 = (idx & 15) * 4;
        int g = row & 3, ql = row >> 2;
        float4 av = *reinterpret_cast<const float4*>(&d_rr[(size_t)(4 * ql + g) * NROW + col0 + c4]);
        *reinterpret_cast<float4*>(&As[0][g][ql * 68 + c4]) = av;
        float4 bv = *reinterpret_cast<const float4*>(&d_G5t[g * 4096 + ql * 64 + c4]);
        *reinterpret_cast<float4*>(&Bs[0][g][ql * 68 + c4]) = bv;
    }
    __syncthreads();
    u64 acc[4][4][2] = {};
    for (int kt = 0; kt < 8; kt++) {
        int cur = kt & 1;
        bool more = (kt + 1 < 8);
        float4 pa[2], pb[2];
        if (more) {
            int q0 = (kt + 1) * 8;
            #pragma unroll
            for (int it = 0; it < 2; it++) {
                int idx = it * 256 + t;
                int row = idx >> 4, c4 = (idx & 15) * 4;
                int g = row & 3, ql = row >> 2;
                pa[it] = *reinterpret_cast<const float4*>(&d_rr[(size_t)(4 * (q0 + ql) + g) * NROW + col0 + c4]);
                pb[it] = *reinterpret_cast<const float4*>(&d_G5t[g * 4096 + (q0 + ql) * 64 + c4]);
            }
        }
        #pragma unroll
        for (int q = 0; q < 8; q++) {
            #pragma unroll
            for (int g = 0; g < 4; g++) {
                float4 a = *reinterpret_cast<const float4*>(&As[cur][g][q * 68 + tn * 4]);
                float4 b = *reinterpret_cast<const float4*>(&Bs[cur][g][q * 68 + tc * 4]);
                u64 bb[2] = {pk2(b.x, b.y), pk2(b.z, b.w)};
                float ar[4] = {a.x, a.y, a.z, a.w};
                #pragma unroll
                for (int p = 0; p < 4; p++) {
                    u64 aa = dup2(ar[p]);
                    fma2(acc[g][p][0], aa, bb[0]);
                    fma2(acc[g][p][1], aa, bb[1]);
                }
            }
        }
        if (more) {
            #pragma unroll
            for (int it = 0; it < 2; it++) {
                int idx = it * 256 + t;
                int row = idx >> 4, c4 = (idx & 15) * 4;
                int g = row & 3, ql = row >> 2;
                *reinterpret_cast<float4*>(&As[cur ^ 1][g][ql * 68 + c4]) = pa[it];
                *reinterpret_cast<float4*>(&Bs[cur ^ 1][g][ql * 68 + c4]) = pb[it];
            }
            __syncthreads();
        }
    }
    int jb = tc * 4;
    #pragma unroll
    for (int p = 0; p < 4; p++) {
        int col = col0 + tn * 4 + p;
        int bo = col & 255, k = col >> 8;
        float* base = &out[(size_t)bo * 65536 + (size_t)k * 256];
        float2 Ce0 = un2(acc[0][p][0]), Ce1 = un2(acc[0][p][1]);
        float2 Se0 = un2(acc[1][p][0]), Se1 = un2(acc[1][p][1]);
        float2 Co0 = un2(acc[2][p][0]), Co1 = un2(acc[2][p][1]);
        float2 So0 = un2(acc[3][p][0]), So1 = un2(acc[3][p][1]);
        float Ce[4] = {Ce0.x, Ce0.y, Ce1.x, Ce1.y};
        float Se[4] = {Se0.x, Se0.y, Se1.x, Se1.y};
        float Co[4] = {Co0.x, Co0.y, Co1.x, Co1.y};
        float So[4] = {So0.x, So0.y, So1.x, So1.y};
        float yA[4], yB[4], yC[4], yD[4];
        #pragma unroll
        for (int q = 0; q < 4; q++) {
            float Cp = Ce[q] + Co[q], Cm = Ce[q] - Co[q];
            float Sp = Se[q] + So[q], Sm = Se[q] - So[q];
            yA[q] = Cp - Sp;
            yB[q] = Cp + Sp;
            yC[q] = Cm + Sm;
            yD[q] = Cm - Sm;
        }
        *reinterpret_cast<float4*>(base + jb) = make_float4(yA[0], yA[1], yA[2], yA[3]);
        *reinterpret_cast<float4*>(base + 128 + jb) = make_float4(yD[0], yD[1], yD[2], yD[3]);
        #pragma unroll
        for (int q = 0; q < 4; q++) {
            int j = jb + q;
            base[128 - j] = yC[q];
            if (j > 0) base[256 - j] = yB[q];
        }
    }
}

__global__ __launch_bounds__(256) void k_y64(float* __restrict__ out) {
    int col = blockIdx.x * 256 + threadIdx.x;
    float C = 0.f, S = 0.f;
    #pragma unroll
    for (int q = 0; q < 64; q++) {
        float sg = (q & 1) ? -1.f : 1.f;
        float w = (q == 0) ? 1.f : 2.f;
        C += w * sg * d_rr[(size_t)(4 * q) * NROW + col];
        S += 2.f * sg * d_rr[(size_t)(4 * q + 3) * NROW + col];
    }
    int bo = col & 255, k = col >> 8;
    float* base = &out[(size_t)bo * 65536 + (size_t)k * 256];
    base[64]  = C - S;
    base[192] = C + S;
}

// ---------------------------------------------------------------------------
extern "C" void kernel_launch(void* const* d_in, const int* in_sizes, int n_in,
                              void* d_out, int out_size) {
    const float* x = (const float*)d_in[0];
    const float* w = (const float*)d_in[1];
    float* out = (float*)d_out;

    k_quad<<<256, 128>>>();
    k_tab<<<128, 128>>>();
    k_legendre<<<128, 128>>>();

    k_fold<<<2048, 256>>>(x);
    k_g1p<0><<<512, 256>>>();
    k_g1p<1><<<512, 256>>>();
    dim3 g2(2, 256, 2); k_g2h<<<g2, 256>>>();
    k_mix<<<NX / 8, 256>>>(w);
    dim3 g4(4, 256);   k_g4f<<<g4, 256>>>();
    k_g5q<<<1024, 256>>>(out);
    k_y64<<<256, 256>>>(out);
}